// round 2
// baseline (speedup 1.0000x reference)
#include <cuda_runtime.h>
#include <math.h>

// ---------------------------------------------------------------------------
// MLA attention, fp32 SIMT baseline.
// Pipeline:
//   1) c_kv = h @ Wdkv^T + b          (8192x512,  K=2048)
//   2) c_q  = h @ Wdq^T  + b          (8192x512,  K=2048)
//   3) krl  = h @ Wkr^T  + b          (8192x64,   K=2048)
//   4) k_c  = c_kv @ Wuk^T + b        (8192x1024, K=512)
//   5) v_c  = c_kv @ Wuv^T + b        (8192x1024, K=512)
//   6) q_c  = c_q  @ Wuq^T + b        (8192x1024, K=512)
//   7) qrl  = c_q  @ Wqr^T + b        (8192x1024, K=512)
//   8) rope(qrl, 16 heads), rope(krl, 1 head)   [source's swapped sin/cos]
//   9) attention per (b,h): softmax(QK^T/sqrt(192)) V  -> ao (tok, h, 64)
//  10) out = ao @ Wfc^T + b           (8192x2048, K=1024)
// ---------------------------------------------------------------------------

#define TOK    8192
#define SEQLEN 512
#define DMODEL 2048
#define DOWND  512
#define UPDIM  1024
#define NHEADS 16
#define RDIM   64
#define BATCH  16

// scratch (allocation-free rule: device globals)
__device__ float g_ckv[TOK * DOWND];
__device__ float g_cq [TOK * DOWND];
__device__ float g_kc [TOK * UPDIM];
__device__ float g_vc [TOK * UPDIM];
__device__ float g_qc [TOK * UPDIM];
__device__ float g_qr [TOK * UPDIM];
__device__ float g_kr [TOK * RDIM];
__device__ float g_ao [TOK * UPDIM];

// ---------------------------------------------------------------------------
// Generic C = A(MxK) @ W^T(NxK) + bias.  128x128 tile, BK=16, 8x8 per thread.
// ---------------------------------------------------------------------------
__global__ __launch_bounds__(256)
void gemm_bias_kernel(const float* __restrict__ A,
                      const float* __restrict__ W,
                      const float* __restrict__ bias,
                      float* __restrict__ C,
                      int M, int N, int K)
{
    __shared__ float As[16][132];   // [k][m], padded: float4-aligned, low conflicts
    __shared__ float Bs[16][132];   // [k][n]

    const int tid = threadIdx.x;
    const int m0  = blockIdx.y * 128;
    const int n0  = blockIdx.x * 128;
    const int tm  = tid >> 4;        // 0..15
    const int tn  = tid & 15;        // 0..15
    const int lr  = tid >> 2;        // 0..63   loader row
    const int lc  = (tid & 3) << 2;  // 0,4,8,12 loader col group

    float acc[8][8];
#pragma unroll
    for (int i = 0; i < 8; i++)
#pragma unroll
        for (int j = 0; j < 8; j++) acc[i][j] = 0.0f;

    for (int k0 = 0; k0 < K; k0 += 16) {
        float4 a0 = *(const float4*)(A + (m0 + lr)      * K + k0 + lc);
        float4 a1 = *(const float4*)(A + (m0 + lr + 64) * K + k0 + lc);
        float4 b0 = make_float4(0.f, 0.f, 0.f, 0.f);
        float4 b1 = make_float4(0.f, 0.f, 0.f, 0.f);
        if (n0 + lr < N)      b0 = *(const float4*)(W + (n0 + lr)      * K + k0 + lc);
        if (n0 + lr + 64 < N) b1 = *(const float4*)(W + (n0 + lr + 64) * K + k0 + lc);

        __syncthreads();
        As[lc + 0][lr] = a0.x; As[lc + 1][lr] = a0.y;
        As[lc + 2][lr] = a0.z; As[lc + 3][lr] = a0.w;
        As[lc + 0][lr + 64] = a1.x; As[lc + 1][lr + 64] = a1.y;
        As[lc + 2][lr + 64] = a1.z; As[lc + 3][lr + 64] = a1.w;
        Bs[lc + 0][lr] = b0.x; Bs[lc + 1][lr] = b0.y;
        Bs[lc + 2][lr] = b0.z; Bs[lc + 3][lr] = b0.w;
        Bs[lc + 0][lr + 64] = b1.x; Bs[lc + 1][lr + 64] = b1.y;
        Bs[lc + 2][lr + 64] = b1.z; Bs[lc + 3][lr + 64] = b1.w;
        __syncthreads();

#pragma unroll
        for (int kk = 0; kk < 16; kk++) {
            float4 av0 = *(const float4*)&As[kk][tm * 8];
            float4 av1 = *(const float4*)&As[kk][tm * 8 + 4];
            float4 bv0 = *(const float4*)&Bs[kk][tn * 8];
            float4 bv1 = *(const float4*)&Bs[kk][tn * 8 + 4];
            float a[8] = {av0.x, av0.y, av0.z, av0.w, av1.x, av1.y, av1.z, av1.w};
            float b[8] = {bv0.x, bv0.y, bv0.z, bv0.w, bv1.x, bv1.y, bv1.z, bv1.w};
#pragma unroll
            for (int i = 0; i < 8; i++)
#pragma unroll
                for (int j = 0; j < 8; j++)
                    acc[i][j] = fmaf(a[i], b[j], acc[i][j]);
        }
    }

#pragma unroll
    for (int i = 0; i < 8; i++) {
        int m = m0 + tm * 8 + i;
#pragma unroll
        for (int j = 0; j < 8; j++) {
            int n = n0 + tn * 8 + j;
            if (n < N) C[m * N + n] = acc[i][j] + bias[n];
        }
    }
}

// ---------------------------------------------------------------------------
// RoPE (faithful to source quirk: cos_pos = sin(ang), sin_pos = cos(ang)).
// x layout: (TOK, nheads, 64). One thread per even/odd pair.
// out[2i]   = x[2i]*sin(a) - x[2i+1]*cos(a)
// out[2i+1] = x[2i+1]*sin(a) + x[2i]*cos(a),  a = l * 10000^(-i/32)
// ---------------------------------------------------------------------------
__global__ void rope_kernel(float* __restrict__ x, int nheads, int total)
{
    int idx = blockIdx.x * blockDim.x + threadIdx.x;
    if (idx >= total) return;
    int pair = idx & 31;
    int rest = idx >> 5;                 // tok*nheads + head
    int tok  = rest / nheads;
    int l    = tok & (SEQLEN - 1);
    float theta = powf(10000.0f, -(float)pair * (1.0f / 32.0f));
    float ang = (float)l * theta;
    float s, c;
    sincosf(ang, &s, &c);
    float* p = x + rest * 64 + pair * 2;
    float x0 = p[0], x1 = p[1];
    p[0] = x0 * s - x1 * c;
    p[1] = x1 * s + x0 * c;
}

// ---------------------------------------------------------------------------
// Attention: block = (qtile of 64, head, batch). Two-pass, scores in SMEM.
//   Qs[128][68] (transposed), Ks[128][68] (transposed, reused as Vs[64][68]),
//   Ss[64][516].  256 threads, 4x4 micro-tiles.
// ---------------------------------------------------------------------------
#define QSW 68
#define SSW 516
#define ATTN_SMEM ((2 * 128 * QSW + 64 * SSW) * 4)

__global__ __launch_bounds__(256)
void attn_kernel(const float* __restrict__ qc, const float* __restrict__ qr,
                 const float* __restrict__ kc, const float* __restrict__ kr,
                 const float* __restrict__ vc, float* __restrict__ ao)
{
    extern __shared__ float sm[];
    float* Qs = sm;                     // [128][QSW]  Qs[d][m]
    float* Ks = sm + 128 * QSW;         // [128][QSW]  Ks[d][n] / Vs[key][d]
    float* Ss = sm + 2 * 128 * QSW;     // [64][SSW]

    const int b  = blockIdx.z;
    const int hh = blockIdx.y;
    const int q0 = blockIdx.x * 64;
    const int tid = threadIdx.x;
    const int tm = tid >> 4;            // 0..15
    const int tn = tid & 15;            // 0..15
    const float scale = 0.07216878364870322f;   // 1/sqrt(192)

    // load Q tile (64 queries x 128 dims), transposed
    for (int idx = tid; idx < 64 * 128; idx += 256) {
        int m = idx >> 7, d = idx & 127;
        int tok = b * SEQLEN + q0 + m;
        float v = (d < 64) ? qc[tok * UPDIM + hh * 64 + d]
                           : qr[tok * UPDIM + hh * 64 + (d - 64)];
        Qs[d * QSW + m] = v;
    }

    // phase 1: S = Q K^T * scale, key tiles of 64
    for (int kt = 0; kt < 8; kt++) {
        __syncthreads();
        for (int idx = tid; idx < 64 * 128; idx += 256) {
            int key = idx >> 7, d = idx & 127;
            int tok = b * SEQLEN + kt * 64 + key;
            float v = (d < 64) ? kc[tok * UPDIM + hh * 64 + d]
                               : kr[tok * RDIM + (d - 64)];
            Ks[d * QSW + key] = v;
        }
        __syncthreads();

        float acc[4][4] = {};
#pragma unroll 8
        for (int kk = 0; kk < 128; kk++) {
            float4 av = *(const float4*)&Qs[kk * QSW + tm * 4];
            float4 bv = *(const float4*)&Ks[kk * QSW + tn * 4];
            float a[4] = {av.x, av.y, av.z, av.w};
            float bb[4] = {bv.x, bv.y, bv.z, bv.w};
#pragma unroll
            for (int i = 0; i < 4; i++)
#pragma unroll
                for (int j = 0; j < 4; j++)
                    acc[i][j] = fmaf(a[i], bb[j], acc[i][j]);
        }
#pragma unroll
        for (int i = 0; i < 4; i++)
#pragma unroll
            for (int j = 0; j < 4; j++)
                Ss[(tm * 4 + i) * SSW + kt * 64 + tn * 4 + j] = acc[i][j] * scale;
    }
    __syncthreads();

    // softmax per row (4 threads/row, strided cols -> conflict-free banks)
    {
        int row  = tid >> 2;
        int part = tid & 3;
        float* srow = Ss + row * SSW;
        float mx = -1e30f;
        for (int k2 = 0; k2 < 128; k2++)
            mx = fmaxf(mx, srow[part + k2 * 4]);
        mx = fmaxf(mx, __shfl_xor_sync(0xffffffffu, mx, 1));
        mx = fmaxf(mx, __shfl_xor_sync(0xffffffffu, mx, 2));
        float sum = 0.0f;
        for (int k2 = 0; k2 < 128; k2++) {
            float e = expf(srow[part + k2 * 4] - mx);
            srow[part + k2 * 4] = e;
            sum += e;
        }
        sum += __shfl_xor_sync(0xffffffffu, sum, 1);
        sum += __shfl_xor_sync(0xffffffffu, sum, 2);
        float inv = 1.0f / sum;
        for (int k2 = 0; k2 < 128; k2++)
            srow[part + k2 * 4] *= inv;
    }

    // phase 3: O = P V, key tiles of 64 (V reuses Ks buffer)
    float oacc[4][4] = {};
    for (int kt = 0; kt < 8; kt++) {
        __syncthreads();
        for (int idx = tid; idx < 64 * 64; idx += 256) {
            int key = idx >> 6, d = idx & 63;
            int tok = b * SEQLEN + kt * 64 + key;
            Ks[key * QSW + d] = vc[tok * UPDIM + hh * 64 + d];
        }
        __syncthreads();
#pragma unroll 4
        for (int kk = 0; kk < 64; kk++) {
            float a0 = Ss[(tm * 4 + 0) * SSW + kt * 64 + kk];
            float a1 = Ss[(tm * 4 + 1) * SSW + kt * 64 + kk];
            float a2 = Ss[(tm * 4 + 2) * SSW + kt * 64 + kk];
            float a3 = Ss[(tm * 4 + 3) * SSW + kt * 64 + kk];
            float4 bv = *(const float4*)&Ks[kk * QSW + tn * 4];
            float bb[4] = {bv.x, bv.y, bv.z, bv.w};
            float a[4] = {a0, a1, a2, a3};
#pragma unroll
            for (int i = 0; i < 4; i++)
#pragma unroll
                for (int j = 0; j < 4; j++)
                    oacc[i][j] = fmaf(a[i], bb[j], oacc[i][j]);
        }
    }

#pragma unroll
    for (int i = 0; i < 4; i++) {
        int tok = b * SEQLEN + q0 + tm * 4 + i;
#pragma unroll
        for (int j = 0; j < 4; j++)
            ao[tok * UPDIM + hh * 64 + tn * 4 + j] = oacc[i][j];
    }
}

// ---------------------------------------------------------------------------
extern "C" void kernel_launch(void* const* d_in, const int* in_sizes, int n_in,
                              void* d_out, int out_size)
{
    const float* h    = (const float*)d_in[0];
    const float* Wdkv = (const float*)d_in[1];
    const float* bdkv = (const float*)d_in[2];
    const float* Wuk  = (const float*)d_in[3];
    const float* buk  = (const float*)d_in[4];
    const float* Wuv  = (const float*)d_in[5];
    const float* buv  = (const float*)d_in[6];
    const float* Wdq  = (const float*)d_in[7];
    const float* bdq  = (const float*)d_in[8];
    const float* Wuq  = (const float*)d_in[9];
    const float* buq  = (const float*)d_in[10];
    const float* Wqr  = (const float*)d_in[11];
    const float* bqr  = (const float*)d_in[12];
    const float* Wkr  = (const float*)d_in[13];
    const float* bkr  = (const float*)d_in[14];
    const float* Wfc  = (const float*)d_in[15];
    const float* bfc  = (const float*)d_in[16];
    float* out = (float*)d_out;

    float *ckv, *cq, *kc, *vc, *qc, *qr, *kr, *ao;
    cudaGetSymbolAddress((void**)&ckv, g_ckv);
    cudaGetSymbolAddress((void**)&cq,  g_cq);
    cudaGetSymbolAddress((void**)&kc,  g_kc);
    cudaGetSymbolAddress((void**)&vc,  g_vc);
    cudaGetSymbolAddress((void**)&qc,  g_qc);
    cudaGetSymbolAddress((void**)&qr,  g_qr);
    cudaGetSymbolAddress((void**)&kr,  g_kr);
    cudaGetSymbolAddress((void**)&ao,  g_ao);

    cudaFuncSetAttribute(attn_kernel,
                         cudaFuncAttributeMaxDynamicSharedMemorySize, ATTN_SMEM);

    dim3 blk(256);

    // down projections + decoupled k rope projection
    gemm_bias_kernel<<<dim3(DOWND / 128, TOK / 128), blk>>>(h, Wdkv, bdkv, ckv, TOK, DOWND, DMODEL);
    gemm_bias_kernel<<<dim3(DOWND / 128, TOK / 128), blk>>>(h, Wdq,  bdq,  cq,  TOK, DOWND, DMODEL);
    gemm_bias_kernel<<<dim3(1,           TOK / 128), blk>>>(h, Wkr,  bkr,  kr,  TOK, RDIM,  DMODEL);

    // up projections
    gemm_bias_kernel<<<dim3(UPDIM / 128, TOK / 128), blk>>>(ckv, Wuk, buk, kc, TOK, UPDIM, DOWND);
    gemm_bias_kernel<<<dim3(UPDIM / 128, TOK / 128), blk>>>(ckv, Wuv, buv, vc, TOK, UPDIM, DOWND);
    gemm_bias_kernel<<<dim3(UPDIM / 128, TOK / 128), blk>>>(cq,  Wuq, buq, qc, TOK, UPDIM, DOWND);
    gemm_bias_kernel<<<dim3(UPDIM / 128, TOK / 128), blk>>>(cq,  Wqr, bqr, qr, TOK, UPDIM, DOWND);

    // rope
    rope_kernel<<<(TOK * NHEADS * 32) / 256, 256>>>(qr, NHEADS, TOK * NHEADS * 32);
    rope_kernel<<<(TOK * 1 * 32) / 256, 256>>>(kr, 1, TOK * 32);

    // attention
    attn_kernel<<<dim3(SEQLEN / 64, NHEADS, BATCH), blk, ATTN_SMEM>>>(qc, qr, kc, kr, vc, ao);

    // output projection
    gemm_bias_kernel<<<dim3(DMODEL / 128, TOK / 128), blk>>>(ao, Wfc, bfc, out, TOK, DMODEL, UPDIM);
}

// round 5
// speedup vs baseline: 1.3976x; 1.3976x over previous
#include <cuda_runtime.h>
#include <cuda_bf16.h>
#include <math.h>
#include <cstdint>

// ===========================================================================
// MLA attention. GEMMs via mma.sync bf16 split (hi+lo -> 3 MMAs, fp32 accum).
// (tcgen05 is rejected by this toolchain: harness emits compute_103 PTX.)
// Attention + rope remain fp32 SIMT this round.
// ===========================================================================

#define TOK    8192
#define SEQLEN 512
#define DMODEL 2048
#define DOWND  512
#define UPDIM  1024
#define NHEADS 16
#define RDIM   64
#define BATCH  16

// ------------------------------ scratch ------------------------------------
__device__ float g_ckv[TOK * DOWND];
__device__ float g_cq [TOK * DOWND];
__device__ float g_kc [TOK * UPDIM];
__device__ float g_vc [TOK * UPDIM];
__device__ float g_qc [TOK * UPDIM];
__device__ float g_qr [TOK * UPDIM];
__device__ float g_kr [TOK * RDIM];
__device__ float g_ao [TOK * UPDIM];

__device__ __nv_bfloat16 g_hH [TOK * DMODEL];
__device__ __nv_bfloat16 g_hL [TOK * DMODEL];
__device__ __nv_bfloat16 g_ckvH[TOK * DOWND];
__device__ __nv_bfloat16 g_ckvL[TOK * DOWND];
__device__ __nv_bfloat16 g_cqH [TOK * DOWND];
__device__ __nv_bfloat16 g_cqL [TOK * DOWND];
__device__ __nv_bfloat16 g_aoH [TOK * UPDIM];
__device__ __nv_bfloat16 g_aoL [TOK * UPDIM];

__device__ __nv_bfloat16 g_WdkvH[DOWND * DMODEL];
__device__ __nv_bfloat16 g_WdkvL[DOWND * DMODEL];
__device__ __nv_bfloat16 g_WdqH [DOWND * DMODEL];
__device__ __nv_bfloat16 g_WdqL [DOWND * DMODEL];
__device__ __nv_bfloat16 g_WkrH [RDIM * DMODEL];
__device__ __nv_bfloat16 g_WkrL [RDIM * DMODEL];
__device__ __nv_bfloat16 g_WukH [UPDIM * DOWND];
__device__ __nv_bfloat16 g_WukL [UPDIM * DOWND];
__device__ __nv_bfloat16 g_WuvH [UPDIM * DOWND];
__device__ __nv_bfloat16 g_WuvL [UPDIM * DOWND];
__device__ __nv_bfloat16 g_WuqH [UPDIM * DOWND];
__device__ __nv_bfloat16 g_WuqL [UPDIM * DOWND];
__device__ __nv_bfloat16 g_WqrH [UPDIM * DOWND];
__device__ __nv_bfloat16 g_WqrL [UPDIM * DOWND];
__device__ __nv_bfloat16 g_WfcH [DMODEL * UPDIM];
__device__ __nv_bfloat16 g_WfcL [DMODEL * UPDIM];

// ------------------------------ helpers ------------------------------------
__device__ __forceinline__ uint32_t smem_u32(const void* p) {
    uint32_t a;
    asm("{ .reg .u64 t; cvta.to.shared.u64 t, %1; cvt.u32.u64 %0, t; }"
        : "=r"(a) : "l"(p));
    return a;
}

__device__ __forceinline__ void ldsm_x4(uint32_t& r0, uint32_t& r1,
                                        uint32_t& r2, uint32_t& r3,
                                        uint32_t addr) {
    asm volatile("ldmatrix.sync.aligned.m8n8.x4.shared.b16 {%0,%1,%2,%3}, [%4];"
                 : "=r"(r0), "=r"(r1), "=r"(r2), "=r"(r3) : "r"(addr));
}
__device__ __forceinline__ void ldsm_x2(uint32_t& r0, uint32_t& r1,
                                        uint32_t addr) {
    asm volatile("ldmatrix.sync.aligned.m8n8.x2.shared.b16 {%0,%1}, [%2];"
                 : "=r"(r0), "=r"(r1) : "r"(addr));
}
__device__ __forceinline__ void mma16816(float* c, const uint32_t* a,
                                         const uint32_t* b) {
    asm volatile(
        "mma.sync.aligned.m16n8k16.row.col.f32.bf16.bf16.f32 "
        "{%0,%1,%2,%3}, {%4,%5,%6,%7}, {%8,%9}, {%0,%1,%2,%3};"
        : "+f"(c[0]), "+f"(c[1]), "+f"(c[2]), "+f"(c[3])
        : "r"(a[0]), "r"(a[1]), "r"(a[2]), "r"(a[3]), "r"(b[0]), "r"(b[1]));
}

// ------------------------------ split kernel -------------------------------
__global__ void split_kernel(const float* __restrict__ x,
                             __nv_bfloat16* __restrict__ hi,
                             __nv_bfloat16* __restrict__ lo, int n)
{
    int i = blockIdx.x * blockDim.x + threadIdx.x;
    if (i >= n) return;
    float v = x[i];
    __nv_bfloat16 h = __float2bfloat16(v);
    hi[i] = h;
    lo[i] = __float2bfloat16(v - __bfloat162float(h));
}

// ------------------------------ tensor GEMM (mma.sync) ---------------------
// C(M,N) = A(M,K) @ W^T(N,K) + bias.  CTA 128x128, K-chunk 32, 8 warps,
// warp tile 64x32.  smem rows padded to 40 bf16 (80 B, conflict-free ldmatrix).
#define ROWB 80
#define TILEB (128 * ROWB)

__global__ __launch_bounds__(256)
void tgemm_kernel(const __nv_bfloat16* __restrict__ Ah,
                  const __nv_bfloat16* __restrict__ Al,
                  const __nv_bfloat16* __restrict__ Bh,
                  const __nv_bfloat16* __restrict__ Bl,
                  const float* __restrict__ bias,
                  float* __restrict__ C,
                  int N, int K)
{
    __shared__ __align__(16) char smem[4 * TILEB];

    const int tid  = threadIdx.x;
    const int wid  = tid >> 5;
    const int lane = tid & 31;
    const int wm   = wid >> 2;          // 0..1
    const int wn   = wid & 3;           // 0..3
    const int m0   = blockIdx.y * 128;
    const int n0   = blockIdx.x * 128;
    const uint32_t sb = smem_u32(smem);

    const __nv_bfloat16* srcs[4] = {Ah, Al, Bh, Bl};

    float acc[4][4][4];
#pragma unroll
    for (int i = 0; i < 4; i++)
#pragma unroll
        for (int j = 0; j < 4; j++)
#pragma unroll
            for (int v = 0; v < 4; v++) acc[i][j][v] = 0.0f;

    // ldmatrix source addresses (within a tile)
    const int r16   = lane & 15;
    const int khalfA = (lane >> 4) * 16;          // bytes: 8 bf16
    const int r8    = lane & 7;
    const int khalfB = ((lane >> 3) & 1) * 16;

    for (int k0 = 0; k0 < K; k0 += 32) {
        __syncthreads();
        // ---- stage 4 tiles: 128 rows x 32 bf16 each ----
#pragma unroll
        for (int t = 0; t < 4; t++) {
            const bool isB = (t >= 2);
            const __nv_bfloat16* src = srcs[t];
#pragma unroll
            for (int j = 0; j < 2; j++) {
                int idx = tid + j * 256;          // 0..511
                int row = idx >> 2;
                int q   = idx & 3;
                uint4 v = make_uint4(0u, 0u, 0u, 0u);
                int grow = isB ? (n0 + row) : (m0 + row);
                if (!isB || grow < N)
                    v = *(const uint4*)(src + (size_t)grow * K + k0 + q * 8);
                *(uint4*)(smem + t * TILEB + row * ROWB + q * 16) = v;
            }
        }
        __syncthreads();

#pragma unroll
        for (int ks = 0; ks < 2; ks++) {
            const int kb = ks * 32;               // byte offset of k16 step
            uint32_t ah[4][4], al[4][4], bh[4][2], bl[4][2];
#pragma unroll
            for (int mi = 0; mi < 4; mi++)
                ldsm_x4(ah[mi][0], ah[mi][1], ah[mi][2], ah[mi][3],
                        sb + 0 * TILEB + (wm * 64 + mi * 16 + r16) * ROWB + kb + khalfA);
#pragma unroll
            for (int ni = 0; ni < 4; ni++)
                ldsm_x2(bh[ni][0], bh[ni][1],
                        sb + 2 * TILEB + (wn * 32 + ni * 8 + r8) * ROWB + kb + khalfB);
#pragma unroll
            for (int mi = 0; mi < 4; mi++)
#pragma unroll
                for (int ni = 0; ni < 4; ni++)
                    mma16816(acc[mi][ni], ah[mi], bh[ni]);

#pragma unroll
            for (int ni = 0; ni < 4; ni++)
                ldsm_x2(bl[ni][0], bl[ni][1],
                        sb + 3 * TILEB + (wn * 32 + ni * 8 + r8) * ROWB + kb + khalfB);
#pragma unroll
            for (int mi = 0; mi < 4; mi++)
#pragma unroll
                for (int ni = 0; ni < 4; ni++)
                    mma16816(acc[mi][ni], ah[mi], bl[ni]);

#pragma unroll
            for (int mi = 0; mi < 4; mi++)
                ldsm_x4(al[mi][0], al[mi][1], al[mi][2], al[mi][3],
                        sb + 1 * TILEB + (wm * 64 + mi * 16 + r16) * ROWB + kb + khalfA);
#pragma unroll
            for (int mi = 0; mi < 4; mi++)
#pragma unroll
                for (int ni = 0; ni < 4; ni++)
                    mma16816(acc[mi][ni], al[mi], bh[ni]);
        }
    }

    // ---- epilogue ----
#pragma unroll
    for (int mi = 0; mi < 4; mi++) {
        int row0 = m0 + wm * 64 + mi * 16 + (lane >> 2);
#pragma unroll
        for (int ni = 0; ni < 4; ni++) {
            int col = n0 + wn * 32 + ni * 8 + 2 * (lane & 3);
            if (col < N) {
                float2 b2 = *(const float2*)(bias + col);
                float2 o0 = make_float2(acc[mi][ni][0] + b2.x, acc[mi][ni][1] + b2.y);
                float2 o1 = make_float2(acc[mi][ni][2] + b2.x, acc[mi][ni][3] + b2.y);
                *(float2*)(C + (size_t)row0 * N + col) = o0;
                *(float2*)(C + (size_t)(row0 + 8) * N + col) = o1;
            }
        }
    }
}

// ------------------------------ rope ---------------------------------------
__global__ void rope_kernel(float* __restrict__ x, int nheads, int total)
{
    int idx = blockIdx.x * blockDim.x + threadIdx.x;
    if (idx >= total) return;
    int pair = idx & 31;
    int rest = idx >> 5;
    int tok  = rest / nheads;
    int l    = tok & (SEQLEN - 1);
    float theta = powf(10000.0f, -(float)pair * (1.0f / 32.0f));
    float ang = (float)l * theta;
    float s, c;
    sincosf(ang, &s, &c);
    float* p = x + rest * 64 + pair * 2;
    float x0 = p[0], x1 = p[1];
    p[0] = x0 * s - x1 * c;
    p[1] = x1 * s + x0 * c;
}

// ------------------------------ attention ----------------------------------
#define QSW 68
#define SSW 516
#define ATTN_SMEM ((2 * 128 * QSW + 64 * SSW) * 4)

__global__ __launch_bounds__(256)
void attn_kernel(const float* __restrict__ qc, const float* __restrict__ qr,
                 const float* __restrict__ kc, const float* __restrict__ kr,
                 const float* __restrict__ vc, float* __restrict__ ao)
{
    extern __shared__ float sm[];
    float* Qs = sm;
    float* Ks = sm + 128 * QSW;
    float* Ss = sm + 2 * 128 * QSW;

    const int b  = blockIdx.z;
    const int hh = blockIdx.y;
    const int q0 = blockIdx.x * 64;
    const int tid = threadIdx.x;
    const int tm = tid >> 4;
    const int tn = tid & 15;
    const float scale = 0.07216878364870322f;

    for (int idx = tid; idx < 64 * 128; idx += 256) {
        int m = idx >> 7, d = idx & 127;
        int tok = b * SEQLEN + q0 + m;
        float v = (d < 64) ? qc[tok * UPDIM + hh * 64 + d]
                           : qr[tok * UPDIM + hh * 64 + (d - 64)];
        Qs[d * QSW + m] = v;
    }

    for (int kt = 0; kt < 8; kt++) {
        __syncthreads();
        for (int idx = tid; idx < 64 * 128; idx += 256) {
            int key = idx >> 7, d = idx & 127;
            int tok = b * SEQLEN + kt * 64 + key;
            float v = (d < 64) ? kc[tok * UPDIM + hh * 64 + d]
                               : kr[tok * RDIM + (d - 64)];
            Ks[d * QSW + key] = v;
        }
        __syncthreads();

        float acc[4][4] = {};
#pragma unroll 8
        for (int kk = 0; kk < 128; kk++) {
            float4 av = *(const float4*)&Qs[kk * QSW + tm * 4];
            float4 bv = *(const float4*)&Ks[kk * QSW + tn * 4];
            float a[4] = {av.x, av.y, av.z, av.w};
            float bb[4] = {bv.x, bv.y, bv.z, bv.w};
#pragma unroll
            for (int i = 0; i < 4; i++)
#pragma unroll
                for (int j = 0; j < 4; j++)
                    acc[i][j] = fmaf(a[i], bb[j], acc[i][j]);
        }
#pragma unroll
        for (int i = 0; i < 4; i++)
#pragma unroll
            for (int j = 0; j < 4; j++)
                Ss[(tm * 4 + i) * SSW + kt * 64 + tn * 4 + j] = acc[i][j] * scale;
    }
    __syncthreads();

    {
        int row  = tid >> 2;
        int part = tid & 3;
        float* srow = Ss + row * SSW;
        float mx = -1e30f;
        for (int k2 = 0; k2 < 128; k2++)
            mx = fmaxf(mx, srow[part + k2 * 4]);
        mx = fmaxf(mx, __shfl_xor_sync(0xffffffffu, mx, 1));
        mx = fmaxf(mx, __shfl_xor_sync(0xffffffffu, mx, 2));
        float sum = 0.0f;
        for (int k2 = 0; k2 < 128; k2++) {
            float e = expf(srow[part + k2 * 4] - mx);
            srow[part + k2 * 4] = e;
            sum += e;
        }
        sum += __shfl_xor_sync(0xffffffffu, sum, 1);
        sum += __shfl_xor_sync(0xffffffffu, sum, 2);
        float inv = 1.0f / sum;
        for (int k2 = 0; k2 < 128; k2++)
            srow[part + k2 * 4] *= inv;
    }

    float oacc[4][4] = {};
    for (int kt = 0; kt < 8; kt++) {
        __syncthreads();
        for (int idx = tid; idx < 64 * 64; idx += 256) {
            int key = idx >> 6, d = idx & 63;
            int tok = b * SEQLEN + kt * 64 + key;
            Ks[key * QSW + d] = vc[tok * UPDIM + hh * 64 + d];
        }
        __syncthreads();
#pragma unroll 4
        for (int kk = 0; kk < 64; kk++) {
            float a0 = Ss[(tm * 4 + 0) * SSW + kt * 64 + kk];
            float a1 = Ss[(tm * 4 + 1) * SSW + kt * 64 + kk];
            float a2 = Ss[(tm * 4 + 2) * SSW + kt * 64 + kk];
            float a3 = Ss[(tm * 4 + 3) * SSW + kt * 64 + kk];
            float4 bv = *(const float4*)&Ks[kk * QSW + tn * 4];
            float bb[4] = {bv.x, bv.y, bv.z, bv.w};
            float a[4] = {a0, a1, a2, a3};
#pragma unroll
            for (int i = 0; i < 4; i++)
#pragma unroll
                for (int j = 0; j < 4; j++)
                    oacc[i][j] = fmaf(a[i], bb[j], oacc[i][j]);
        }
    }

#pragma unroll
    for (int i = 0; i < 4; i++) {
        int tok = b * SEQLEN + q0 + tm * 4 + i;
#pragma unroll
        for (int j = 0; j < 4; j++)
            ao[tok * UPDIM + hh * 64 + tn * 4 + j] = oacc[i][j];
    }
}

// ---------------------------------------------------------------------------
static void split(const float* x, __nv_bfloat16* hi, __nv_bfloat16* lo, int n)
{
    split_kernel<<<(n + 255) / 256, 256>>>(x, hi, lo, n);
}

extern "C" void kernel_launch(void* const* d_in, const int* in_sizes, int n_in,
                              void* d_out, int out_size)
{
    const float* h    = (const float*)d_in[0];
    const float* Wdkv = (const float*)d_in[1];
    const float* bdkv = (const float*)d_in[2];
    const float* Wuk  = (const float*)d_in[3];
    const float* buk  = (const float*)d_in[4];
    const float* Wuv  = (const float*)d_in[5];
    const float* buv  = (const float*)d_in[6];
    const float* Wdq  = (const float*)d_in[7];
    const float* bdq  = (const float*)d_in[8];
    const float* Wuq  = (const float*)d_in[9];
    const float* buq  = (const float*)d_in[10];
    const float* Wqr  = (const float*)d_in[11];
    const float* bqr  = (const float*)d_in[12];
    const float* Wkr  = (const float*)d_in[13];
    const float* bkr  = (const float*)d_in[14];
    const float* Wfc  = (const float*)d_in[15];
    const float* bfc  = (const float*)d_in[16];
    float* out = (float*)d_out;

    float *ckv, *cq, *kc, *vc, *qc, *qr, *kr, *ao;
    cudaGetSymbolAddress((void**)&ckv, g_ckv);
    cudaGetSymbolAddress((void**)&cq,  g_cq);
    cudaGetSymbolAddress((void**)&kc,  g_kc);
    cudaGetSymbolAddress((void**)&vc,  g_vc);
    cudaGetSymbolAddress((void**)&qc,  g_qc);
    cudaGetSymbolAddress((void**)&qr,  g_qr);
    cudaGetSymbolAddress((void**)&kr,  g_kr);
    cudaGetSymbolAddress((void**)&ao,  g_ao);

    __nv_bfloat16 *hH, *hL, *ckvH, *ckvL, *cqH, *cqL, *aoH, *aoL;
    __nv_bfloat16 *WdkvH, *WdkvL, *WdqH, *WdqL, *WkrH, *WkrL;
    __nv_bfloat16 *WukH, *WukL, *WuvH, *WuvL, *WuqH, *WuqL, *WqrH, *WqrL;
    __nv_bfloat16 *WfcH, *WfcL;
    cudaGetSymbolAddress((void**)&hH,    g_hH);
    cudaGetSymbolAddress((void**)&hL,    g_hL);
    cudaGetSymbolAddress((void**)&ckvH,  g_ckvH);
    cudaGetSymbolAddress((void**)&ckvL,  g_ckvL);
    cudaGetSymbolAddress((void**)&cqH,   g_cqH);
    cudaGetSymbolAddress((void**)&cqL,   g_cqL);
    cudaGetSymbolAddress((void**)&aoH,   g_aoH);
    cudaGetSymbolAddress((void**)&aoL,   g_aoL);
    cudaGetSymbolAddress((void**)&WdkvH, g_WdkvH);
    cudaGetSymbolAddress((void**)&WdkvL, g_WdkvL);
    cudaGetSymbolAddress((void**)&WdqH,  g_WdqH);
    cudaGetSymbolAddress((void**)&WdqL,  g_WdqL);
    cudaGetSymbolAddress((void**)&WkrH,  g_WkrH);
    cudaGetSymbolAddress((void**)&WkrL,  g_WkrL);
    cudaGetSymbolAddress((void**)&WukH,  g_WukH);
    cudaGetSymbolAddress((void**)&WukL,  g_WukL);
    cudaGetSymbolAddress((void**)&WuvH,  g_WuvH);
    cudaGetSymbolAddress((void**)&WuvL,  g_WuvL);
    cudaGetSymbolAddress((void**)&WuqH,  g_WuqH);
    cudaGetSymbolAddress((void**)&WuqL,  g_WuqL);
    cudaGetSymbolAddress((void**)&WqrH,  g_WqrH);
    cudaGetSymbolAddress((void**)&WqrL,  g_WqrL);
    cudaGetSymbolAddress((void**)&WfcH,  g_WfcH);
    cudaGetSymbolAddress((void**)&WfcL,  g_WfcL);

    cudaFuncSetAttribute(attn_kernel,
                         cudaFuncAttributeMaxDynamicSharedMemorySize, ATTN_SMEM);

    // splits: activations + weights
    split(h,    hH,    hL,    TOK * DMODEL);
    split(Wdkv, WdkvH, WdkvL, DOWND * DMODEL);
    split(Wdq,  WdqH,  WdqL,  DOWND * DMODEL);
    split(Wkr,  WkrH,  WkrL,  RDIM * DMODEL);
    split(Wuk,  WukH,  WukL,  UPDIM * DOWND);
    split(Wuv,  WuvH,  WuvL,  UPDIM * DOWND);
    split(Wuq,  WuqH,  WuqL,  UPDIM * DOWND);
    split(Wqr,  WqrH,  WqrL,  UPDIM * DOWND);
    split(Wfc,  WfcH,  WfcL,  DMODEL * UPDIM);

    dim3 blk(256);
    // down projections + decoupled k rope projection
    tgemm_kernel<<<dim3(DOWND / 128, TOK / 128), blk>>>(hH, hL, WdkvH, WdkvL, bdkv, ckv, DOWND, DMODEL);
    tgemm_kernel<<<dim3(DOWND / 128, TOK / 128), blk>>>(hH, hL, WdqH,  WdqL,  bdq,  cq,  DOWND, DMODEL);
    tgemm_kernel<<<dim3(1,           TOK / 128), blk>>>(hH, hL, WkrH,  WkrL,  bkr,  kr,  RDIM,  DMODEL);

    split(ckv, ckvH, ckvL, TOK * DOWND);
    split(cq,  cqH,  cqL,  TOK * DOWND);

    // up projections
    tgemm_kernel<<<dim3(UPDIM / 128, TOK / 128), blk>>>(ckvH, ckvL, WukH, WukL, buk, kc, UPDIM, DOWND);
    tgemm_kernel<<<dim3(UPDIM / 128, TOK / 128), blk>>>(ckvH, ckvL, WuvH, WuvL, buv, vc, UPDIM, DOWND);
    tgemm_kernel<<<dim3(UPDIM / 128, TOK / 128), blk>>>(cqH,  cqL,  WuqH, WuqL, buq, qc, UPDIM, DOWND);
    tgemm_kernel<<<dim3(UPDIM / 128, TOK / 128), blk>>>(cqH,  cqL,  WqrH, WqrL, bqr, qr, UPDIM, DOWND);

    // rope
    rope_kernel<<<(TOK * NHEADS * 32) / 256, 256>>>(qr, NHEADS, TOK * NHEADS * 32);
    rope_kernel<<<(TOK * 1 * 32) / 256, 256>>>(kr, 1, TOK * 32);

    // attention
    attn_kernel<<<dim3(SEQLEN / 64, NHEADS, BATCH), blk, ATTN_SMEM>>>(qc, qr, kc, kr, vc, ao);

    // output projection
    split(ao, aoH, aoL, TOK * UPDIM);
    tgemm_kernel<<<dim3(DMODEL / 128, TOK / 128), blk>>>(aoH, aoL, WfcH, WfcL, bfc, out, DMODEL, UPDIM);
}

// round 6
// speedup vs baseline: 2.0732x; 1.4834x over previous
#include <cuda_runtime.h>
#include <cuda_bf16.h>
#include <math.h>
#include <cstdint>

// ===========================================================================
// MLA attention. All GEMMs + attention via mma.sync bf16 split (3 MMAs, fp32
// accum). RoPE fused into Q/K pack kernels. Softmax fp32 SIMT.
// ===========================================================================

#define TOK    8192
#define SEQLEN 512
#define DMODEL 2048
#define DOWND  512
#define UPDIM  1024
#define NHEADS 16
#define RDIM   64
#define BATCH  16
#define NBH    (BATCH * NHEADS)

// ------------------------------ scratch ------------------------------------
__device__ float g_ckv[TOK * DOWND];
__device__ float g_cq [TOK * DOWND];
__device__ float g_kc [TOK * UPDIM];
__device__ float g_vc [TOK * UPDIM];
__device__ float g_qc [TOK * UPDIM];
__device__ float g_qr [TOK * UPDIM];
__device__ float g_kr [TOK * RDIM];
__device__ float g_ao [TOK * UPDIM];

__device__ __nv_bfloat16 g_hH [TOK * DMODEL];
__device__ __nv_bfloat16 g_hL [TOK * DMODEL];
__device__ __nv_bfloat16 g_ckvH[TOK * DOWND];
__device__ __nv_bfloat16 g_ckvL[TOK * DOWND];
__device__ __nv_bfloat16 g_cqH [TOK * DOWND];
__device__ __nv_bfloat16 g_cqL [TOK * DOWND];
__device__ __nv_bfloat16 g_aoH [TOK * UPDIM];
__device__ __nv_bfloat16 g_aoL [TOK * UPDIM];

__device__ __nv_bfloat16 g_WdkvH[DOWND * DMODEL];
__device__ __nv_bfloat16 g_WdkvL[DOWND * DMODEL];
__device__ __nv_bfloat16 g_WdqH [DOWND * DMODEL];
__device__ __nv_bfloat16 g_WdqL [DOWND * DMODEL];
__device__ __nv_bfloat16 g_WkrH [RDIM * DMODEL];
__device__ __nv_bfloat16 g_WkrL [RDIM * DMODEL];
__device__ __nv_bfloat16 g_WukH [UPDIM * DOWND];
__device__ __nv_bfloat16 g_WukL [UPDIM * DOWND];
__device__ __nv_bfloat16 g_WuvH [UPDIM * DOWND];
__device__ __nv_bfloat16 g_WuvL [UPDIM * DOWND];
__device__ __nv_bfloat16 g_WuqH [UPDIM * DOWND];
__device__ __nv_bfloat16 g_WuqL [UPDIM * DOWND];
__device__ __nv_bfloat16 g_WqrH [UPDIM * DOWND];
__device__ __nv_bfloat16 g_WqrL [UPDIM * DOWND];
__device__ __nv_bfloat16 g_WfcH [DMODEL * UPDIM];
__device__ __nv_bfloat16 g_WfcL [DMODEL * UPDIM];

// packed attention operands: [bh][seq][dim] hi/lo
__device__ __nv_bfloat16 g_QPH[NBH * SEQLEN * 128];
__device__ __nv_bfloat16 g_QPL[NBH * SEQLEN * 128];
__device__ __nv_bfloat16 g_KPH[NBH * SEQLEN * 128];
__device__ __nv_bfloat16 g_KPL[NBH * SEQLEN * 128];
__device__ __nv_bfloat16 g_VPH[NBH * SEQLEN * 64];
__device__ __nv_bfloat16 g_VPL[NBH * SEQLEN * 64];

// ------------------------------ helpers ------------------------------------
__device__ __forceinline__ uint32_t smem_u32(const void* p) {
    uint32_t a;
    asm("{ .reg .u64 t; cvta.to.shared.u64 t, %1; cvt.u32.u64 %0, t; }"
        : "=r"(a) : "l"(p));
    return a;
}
__device__ __forceinline__ void ldsm_x4(uint32_t& r0, uint32_t& r1,
                                        uint32_t& r2, uint32_t& r3,
                                        uint32_t addr) {
    asm volatile("ldmatrix.sync.aligned.m8n8.x4.shared.b16 {%0,%1,%2,%3}, [%4];"
                 : "=r"(r0), "=r"(r1), "=r"(r2), "=r"(r3) : "r"(addr));
}
__device__ __forceinline__ void ldsm_x2(uint32_t& r0, uint32_t& r1,
                                        uint32_t addr) {
    asm volatile("ldmatrix.sync.aligned.m8n8.x2.shared.b16 {%0,%1}, [%2];"
                 : "=r"(r0), "=r"(r1) : "r"(addr));
}
__device__ __forceinline__ void mma16816(float* c, const uint32_t* a,
                                         const uint32_t* b) {
    asm volatile(
        "mma.sync.aligned.m16n8k16.row.col.f32.bf16.bf16.f32 "
        "{%0,%1,%2,%3}, {%4,%5,%6,%7}, {%8,%9}, {%0,%1,%2,%3};"
        : "+f"(c[0]), "+f"(c[1]), "+f"(c[2]), "+f"(c[3])
        : "r"(a[0]), "r"(a[1]), "r"(a[2]), "r"(a[3]), "r"(b[0]), "r"(b[1]));
}
__device__ __forceinline__ void splt(float v, __nv_bfloat16& h, __nv_bfloat16& l) {
    h = __float2bfloat16(v);
    l = __float2bfloat16(v - __bfloat162float(h));
}
__device__ __forceinline__ void f2_hilo(float2 f, uint32_t& h, uint32_t& l) {
    __nv_bfloat162 hb = __floats2bfloat162_rn(f.x, f.y);
    float rx = f.x - __bfloat162float(hb.x);
    float ry = f.y - __bfloat162float(hb.y);
    __nv_bfloat162 lb = __floats2bfloat162_rn(rx, ry);
    h = *(uint32_t*)&hb;
    l = *(uint32_t*)&lb;
}

// ------------------------------ split kernel -------------------------------
__global__ void split_kernel(const float* __restrict__ x,
                             __nv_bfloat16* __restrict__ hi,
                             __nv_bfloat16* __restrict__ lo, int n)
{
    int i = blockIdx.x * blockDim.x + threadIdx.x;
    if (i >= n) return;
    float v = x[i];
    __nv_bfloat16 h = __float2bfloat16(v);
    hi[i] = h;
    lo[i] = __float2bfloat16(v - __bfloat162float(h));
}

// ------------------------------ tensor GEMM (mma.sync) ---------------------
#define ROWB 80
#define TILEB (128 * ROWB)

__global__ __launch_bounds__(256)
void tgemm_kernel(const __nv_bfloat16* __restrict__ Ah,
                  const __nv_bfloat16* __restrict__ Al,
                  const __nv_bfloat16* __restrict__ Bh,
                  const __nv_bfloat16* __restrict__ Bl,
                  const float* __restrict__ bias,
                  float* __restrict__ C,
                  int N, int K)
{
    __shared__ __align__(16) char smem[4 * TILEB];

    const int tid  = threadIdx.x;
    const int wid  = tid >> 5;
    const int lane = tid & 31;
    const int wm   = wid >> 2;
    const int wn   = wid & 3;
    const int m0   = blockIdx.y * 128;
    const int n0   = blockIdx.x * 128;
    const uint32_t sb = smem_u32(smem);

    const __nv_bfloat16* srcs[4] = {Ah, Al, Bh, Bl};

    float acc[4][4][4];
#pragma unroll
    for (int i = 0; i < 4; i++)
#pragma unroll
        for (int j = 0; j < 4; j++)
#pragma unroll
            for (int v = 0; v < 4; v++) acc[i][j][v] = 0.0f;

    const int r16   = lane & 15;
    const int khalfA = (lane >> 4) * 16;
    const int r8    = lane & 7;
    const int khalfB = ((lane >> 3) & 1) * 16;

    for (int k0 = 0; k0 < K; k0 += 32) {
        __syncthreads();
#pragma unroll
        for (int t = 0; t < 4; t++) {
            const bool isB = (t >= 2);
            const __nv_bfloat16* src = srcs[t];
#pragma unroll
            for (int j = 0; j < 2; j++) {
                int idx = tid + j * 256;
                int row = idx >> 2;
                int q   = idx & 3;
                uint4 v = make_uint4(0u, 0u, 0u, 0u);
                int grow = isB ? (n0 + row) : (m0 + row);
                if (!isB || grow < N)
                    v = *(const uint4*)(src + (size_t)grow * K + k0 + q * 8);
                *(uint4*)(smem + t * TILEB + row * ROWB + q * 16) = v;
            }
        }
        __syncthreads();

#pragma unroll
        for (int ks = 0; ks < 2; ks++) {
            const int kb = ks * 32;
            uint32_t ah[4][4], al[4][4], bh[4][2], bl[4][2];
#pragma unroll
            for (int mi = 0; mi < 4; mi++)
                ldsm_x4(ah[mi][0], ah[mi][1], ah[mi][2], ah[mi][3],
                        sb + 0 * TILEB + (wm * 64 + mi * 16 + r16) * ROWB + kb + khalfA);
#pragma unroll
            for (int ni = 0; ni < 4; ni++)
                ldsm_x2(bh[ni][0], bh[ni][1],
                        sb + 2 * TILEB + (wn * 32 + ni * 8 + r8) * ROWB + kb + khalfB);
#pragma unroll
            for (int mi = 0; mi < 4; mi++)
#pragma unroll
                for (int ni = 0; ni < 4; ni++)
                    mma16816(acc[mi][ni], ah[mi], bh[ni]);

#pragma unroll
            for (int ni = 0; ni < 4; ni++)
                ldsm_x2(bl[ni][0], bl[ni][1],
                        sb + 3 * TILEB + (wn * 32 + ni * 8 + r8) * ROWB + kb + khalfB);
#pragma unroll
            for (int mi = 0; mi < 4; mi++)
#pragma unroll
                for (int ni = 0; ni < 4; ni++)
                    mma16816(acc[mi][ni], ah[mi], bl[ni]);

#pragma unroll
            for (int mi = 0; mi < 4; mi++)
                ldsm_x4(al[mi][0], al[mi][1], al[mi][2], al[mi][3],
                        sb + 1 * TILEB + (wm * 64 + mi * 16 + r16) * ROWB + kb + khalfA);
#pragma unroll
            for (int mi = 0; mi < 4; mi++)
#pragma unroll
                for (int ni = 0; ni < 4; ni++)
                    mma16816(acc[mi][ni], al[mi], bh[ni]);
        }
    }

#pragma unroll
    for (int mi = 0; mi < 4; mi++) {
        int row0 = m0 + wm * 64 + mi * 16 + (lane >> 2);
#pragma unroll
        for (int ni = 0; ni < 4; ni++) {
            int col = n0 + wn * 32 + ni * 8 + 2 * (lane & 3);
            if (col < N) {
                float2 b2 = *(const float2*)(bias + col);
                float2 o0 = make_float2(acc[mi][ni][0] + b2.x, acc[mi][ni][1] + b2.y);
                float2 o1 = make_float2(acc[mi][ni][2] + b2.x, acc[mi][ni][3] + b2.y);
                *(float2*)(C + (size_t)row0 * N + col) = o0;
                *(float2*)(C + (size_t)(row0 + 8) * N + col) = o1;
            }
        }
    }
}

// ------------------------------ pack kernels (rope fused) ------------------
// QP/KP: [bh][s][128]; first 64 dims = content path, last 64 = rope path.
__global__ void qpack_kernel(const float* __restrict__ qc,
                             const float* __restrict__ qr,
                             __nv_bfloat16* __restrict__ PH,
                             __nv_bfloat16* __restrict__ PL)
{
    int idx = blockIdx.x * 256 + threadIdx.x;     // NBH*512*64
    int d2 = idx & 63;
    int s  = (idx >> 6) & (SEQLEN - 1);
    int bh = idx >> 15;
    int h = bh & (NHEADS - 1), b = bh >> 4;
    int tok = b * SEQLEN + s;
    float f0, f1;
    int dd;
    if (d2 < 32) {
        dd = d2 * 2;
        f0 = qc[(size_t)tok * UPDIM + h * 64 + dd];
        f1 = qc[(size_t)tok * UPDIM + h * 64 + dd + 1];
    } else {
        int pair = d2 - 32;
        int rp = pair * 2;
        float x0 = qr[(size_t)tok * UPDIM + h * 64 + rp];
        float x1 = qr[(size_t)tok * UPDIM + h * 64 + rp + 1];
        float theta = powf(10000.0f, -(float)pair * (1.0f / 32.0f));
        float sn, cs;
        sincosf((float)s * theta, &sn, &cs);
        f0 = x0 * sn - x1 * cs;
        f1 = x1 * sn + x0 * cs;
        dd = 64 + rp;
    }
    size_t base = ((size_t)bh * SEQLEN + s) * 128 + dd;
    splt(f0, PH[base], PL[base]);
    splt(f1, PH[base + 1], PL[base + 1]);
}

__global__ void kpack_kernel(const float* __restrict__ kc,
                             const float* __restrict__ kr,
                             __nv_bfloat16* __restrict__ PH,
                             __nv_bfloat16* __restrict__ PL)
{
    int idx = blockIdx.x * 256 + threadIdx.x;
    int d2 = idx & 63;
    int s  = (idx >> 6) & (SEQLEN - 1);
    int bh = idx >> 15;
    int h = bh & (NHEADS - 1), b = bh >> 4;
    int tok = b * SEQLEN + s;
    float f0, f1;
    int dd;
    if (d2 < 32) {
        dd = d2 * 2;
        f0 = kc[(size_t)tok * UPDIM + h * 64 + dd];
        f1 = kc[(size_t)tok * UPDIM + h * 64 + dd + 1];
    } else {
        int pair = d2 - 32;
        int rp = pair * 2;
        float x0 = kr[(size_t)tok * RDIM + rp];
        float x1 = kr[(size_t)tok * RDIM + rp + 1];
        float theta = powf(10000.0f, -(float)pair * (1.0f / 32.0f));
        float sn, cs;
        sincosf((float)s * theta, &sn, &cs);
        f0 = x0 * sn - x1 * cs;
        f1 = x1 * sn + x0 * cs;
        dd = 64 + rp;
    }
    size_t base = ((size_t)bh * SEQLEN + s) * 128 + dd;
    splt(f0, PH[base], PL[base]);
    splt(f1, PH[base + 1], PL[base + 1]);
}

__global__ void vpack_kernel(const float* __restrict__ vc,
                             __nv_bfloat16* __restrict__ PH,
                             __nv_bfloat16* __restrict__ PL)
{
    int idx = blockIdx.x * 256 + threadIdx.x;     // NBH*512*32
    int d2 = idx & 31;
    int s  = (idx >> 5) & (SEQLEN - 1);
    int bh = idx >> 14;
    int h = bh & (NHEADS - 1), b = bh >> 4;
    int tok = b * SEQLEN + s;
    int dd = d2 * 2;
    float f0 = vc[(size_t)tok * UPDIM + h * 64 + dd];
    float f1 = vc[(size_t)tok * UPDIM + h * 64 + dd + 1];
    size_t base = ((size_t)bh * SEQLEN + s) * 64 + dd;
    splt(f0, PH[base], PL[base]);
    splt(f1, PH[base + 1], PL[base + 1]);
}

// ------------------------------ attention (mma.sync) -----------------------
// CTA: 64 queries x 512 keys for one (b,h). Two-pass with fp32 scores in smem.
#define QPITCH 272
#define VPITCH 144
#define SPITCH 516
#define OFF_QH 0
#define OFF_QL 17408
#define OFF_KH 34816
#define OFF_KL 52224
#define OFF_VH 34816
#define OFF_VL 44032
#define OFF_S  69632
#define ATTN2_SMEM (OFF_S + 64 * SPITCH * 4)

__global__ __launch_bounds__(256)
void attn2_kernel(const __nv_bfloat16* __restrict__ QPH,
                  const __nv_bfloat16* __restrict__ QPL,
                  const __nv_bfloat16* __restrict__ KPH,
                  const __nv_bfloat16* __restrict__ KPL,
                  const __nv_bfloat16* __restrict__ VPH,
                  const __nv_bfloat16* __restrict__ VPL,
                  float* __restrict__ ao)
{
    extern __shared__ char sm2[];
    const uint32_t sb = smem_u32(sm2);
    float* Ssf = (float*)(sm2 + OFF_S);

    const int tid  = threadIdx.x;
    const int wid  = tid >> 5;
    const int lane = tid & 31;
    const int wm = wid >> 2;              // 0..1
    const int wn = wid & 3;               // 0..3
    const int q0 = blockIdx.x * 64;
    const int hh = blockIdx.y;
    const int b  = blockIdx.z;
    const int bh = b * NHEADS + hh;
    const size_t pbase = (size_t)bh * SEQLEN * 128;
    const float scale = 0.07216878364870322f;   // 1/sqrt(192)

    const int r16 = lane & 15;
    const int khalfA = (lane >> 4) * 16;
    const int r8 = lane & 7;
    const int khalfB = ((lane >> 3) & 1) * 16;

    // ---- load Q tile (64 x 128), hi+lo ----
#pragma unroll
    for (int j = 0; j < 4; j++) {
        int idx = tid + j * 256;          // 1024
        int row = idx >> 4, c = idx & 15;
        size_t g = pbase + (size_t)(q0 + row) * 128 + c * 8;
        *(uint4*)(sm2 + OFF_QH + row * QPITCH + c * 16) = *(const uint4*)(QPH + g);
        *(uint4*)(sm2 + OFF_QL + row * QPITCH + c * 16) = *(const uint4*)(QPL + g);
    }

    // ---- phase 1: S = Q K^T * scale ----
    for (int kt = 0; kt < 8; kt++) {
        __syncthreads();
#pragma unroll
        for (int j = 0; j < 4; j++) {
            int idx = tid + j * 256;
            int row = idx >> 4, c = idx & 15;
            size_t g = pbase + (size_t)(kt * 64 + row) * 128 + c * 8;
            *(uint4*)(sm2 + OFF_KH + row * QPITCH + c * 16) = *(const uint4*)(KPH + g);
            *(uint4*)(sm2 + OFF_KL + row * QPITCH + c * 16) = *(const uint4*)(KPL + g);
        }
        __syncthreads();

        float acc[2][2][4];
#pragma unroll
        for (int mi = 0; mi < 2; mi++)
#pragma unroll
            for (int ni = 0; ni < 2; ni++)
#pragma unroll
                for (int v = 0; v < 4; v++) acc[mi][ni][v] = 0.0f;

#pragma unroll
        for (int ks = 0; ks < 8; ks++) {
            const int kb = ks * 32;
            uint32_t ah[2][4], al[2][4], bhf[2][2], blf[2][2];
#pragma unroll
            for (int mi = 0; mi < 2; mi++)
                ldsm_x4(ah[mi][0], ah[mi][1], ah[mi][2], ah[mi][3],
                        sb + OFF_QH + (wm * 32 + mi * 16 + r16) * QPITCH + kb + khalfA);
#pragma unroll
            for (int ni = 0; ni < 2; ni++)
                ldsm_x2(bhf[ni][0], bhf[ni][1],
                        sb + OFF_KH + (wn * 16 + ni * 8 + r8) * QPITCH + kb + khalfB);
#pragma unroll
            for (int mi = 0; mi < 2; mi++)
#pragma unroll
                for (int ni = 0; ni < 2; ni++)
                    mma16816(acc[mi][ni], ah[mi], bhf[ni]);
#pragma unroll
            for (int ni = 0; ni < 2; ni++)
                ldsm_x2(blf[ni][0], blf[ni][1],
                        sb + OFF_KL + (wn * 16 + ni * 8 + r8) * QPITCH + kb + khalfB);
#pragma unroll
            for (int mi = 0; mi < 2; mi++)
#pragma unroll
                for (int ni = 0; ni < 2; ni++)
                    mma16816(acc[mi][ni], ah[mi], blf[ni]);
#pragma unroll
            for (int mi = 0; mi < 2; mi++)
                ldsm_x4(al[mi][0], al[mi][1], al[mi][2], al[mi][3],
                        sb + OFF_QL + (wm * 32 + mi * 16 + r16) * QPITCH + kb + khalfA);
#pragma unroll
            for (int mi = 0; mi < 2; mi++)
#pragma unroll
                for (int ni = 0; ni < 2; ni++)
                    mma16816(acc[mi][ni], al[mi], bhf[ni]);
        }

#pragma unroll
        for (int mi = 0; mi < 2; mi++) {
            int row = wm * 32 + mi * 16 + (lane >> 2);
#pragma unroll
            for (int ni = 0; ni < 2; ni++) {
                int col = kt * 64 + wn * 16 + ni * 8 + 2 * (lane & 3);
                Ssf[row * SPITCH + col]           = acc[mi][ni][0] * scale;
                Ssf[row * SPITCH + col + 1]       = acc[mi][ni][1] * scale;
                Ssf[(row + 8) * SPITCH + col]     = acc[mi][ni][2] * scale;
                Ssf[(row + 8) * SPITCH + col + 1] = acc[mi][ni][3] * scale;
            }
        }
    }
    __syncthreads();

    // ---- softmax (4 threads per row) ----
    {
        int row  = tid >> 2;
        int part = tid & 3;
        float* srow = Ssf + row * SPITCH;
        float mx = -1e30f;
#pragma unroll 4
        for (int k2 = 0; k2 < 128; k2++)
            mx = fmaxf(mx, srow[part + k2 * 4]);
        mx = fmaxf(mx, __shfl_xor_sync(0xffffffffu, mx, 1));
        mx = fmaxf(mx, __shfl_xor_sync(0xffffffffu, mx, 2));
        float sum = 0.0f;
#pragma unroll 4
        for (int k2 = 0; k2 < 128; k2++) {
            float e = __expf(srow[part + k2 * 4] - mx);
            srow[part + k2 * 4] = e;
            sum += e;
        }
        sum += __shfl_xor_sync(0xffffffffu, sum, 1);
        sum += __shfl_xor_sync(0xffffffffu, sum, 2);
        float inv = 1.0f / sum;
#pragma unroll 4
        for (int k2 = 0; k2 < 128; k2++)
            srow[part + k2 * 4] *= inv;
    }

    // ---- phase 3: O = P V ----
    float accO[2][2][4];
#pragma unroll
    for (int mi = 0; mi < 2; mi++)
#pragma unroll
        for (int ni = 0; ni < 2; ni++)
#pragma unroll
            for (int v = 0; v < 4; v++) accO[mi][ni][v] = 0.0f;

    const size_t vbase = (size_t)bh * SEQLEN * 64;
    for (int kt = 0; kt < 8; kt++) {
        __syncthreads();
        // load V tile transposed: VS[d][key]
#pragma unroll
        for (int j = 0; j < 2; j++) {
            int idx = tid + j * 256;      // 512
            int key = idx >> 3, dg = idx & 7;
            size_t g = vbase + (size_t)(kt * 64 + key) * 64 + dg * 8;
            uint4 vh = *(const uint4*)(VPH + g);
            uint4 vl = *(const uint4*)(VPL + g);
            const uint16_t* ph = (const uint16_t*)&vh;
            const uint16_t* pl = (const uint16_t*)&vl;
#pragma unroll
            for (int jj = 0; jj < 8; jj++) {
                *(uint16_t*)(sm2 + OFF_VH + (dg * 8 + jj) * VPITCH + key * 2) = ph[jj];
                *(uint16_t*)(sm2 + OFF_VL + (dg * 8 + jj) * VPITCH + key * 2) = pl[jj];
            }
        }
        __syncthreads();

#pragma unroll
        for (int ks = 0; ks < 4; ks++) {
            uint32_t ph_[2][4], pl_[2][4];
#pragma unroll
            for (int mi = 0; mi < 2; mi++) {
                int r  = wm * 32 + mi * 16 + (lane >> 2);
                int kc = kt * 64 + ks * 16 + 2 * (lane & 3);
                f2_hilo(*(float2*)&Ssf[r * SPITCH + kc],           ph_[mi][0], pl_[mi][0]);
                f2_hilo(*(float2*)&Ssf[(r + 8) * SPITCH + kc],     ph_[mi][1], pl_[mi][1]);
                f2_hilo(*(float2*)&Ssf[r * SPITCH + kc + 8],       ph_[mi][2], pl_[mi][2]);
                f2_hilo(*(float2*)&Ssf[(r + 8) * SPITCH + kc + 8], ph_[mi][3], pl_[mi][3]);
            }
            uint32_t vh_[2][2], vl_[2][2];
#pragma unroll
            for (int ni = 0; ni < 2; ni++) {
                uint32_t a = sb + (wn * 16 + ni * 8 + r8) * VPITCH + ks * 32 + khalfB;
                ldsm_x2(vh_[ni][0], vh_[ni][1], a + OFF_VH);
                ldsm_x2(vl_[ni][0], vl_[ni][1], a + OFF_VL);
            }
#pragma unroll
            for (int mi = 0; mi < 2; mi++)
#pragma unroll
                for (int ni = 0; ni < 2; ni++) {
                    mma16816(accO[mi][ni], ph_[mi], vh_[ni]);
                    mma16816(accO[mi][ni], pl_[mi], vh_[ni]);
                    mma16816(accO[mi][ni], ph_[mi], vl_[ni]);
                }
        }
    }

    // ---- epilogue: ao[tok][h*64 + d] ----
#pragma unroll
    for (int mi = 0; mi < 2; mi++) {
        int rloc = wm * 32 + mi * 16 + (lane >> 2);
        int tok  = b * SEQLEN + q0 + rloc;
#pragma unroll
        for (int ni = 0; ni < 2; ni++) {
            int col = wn * 16 + ni * 8 + 2 * (lane & 3);
            *(float2*)(ao + (size_t)tok * UPDIM + hh * 64 + col) =
                make_float2(accO[mi][ni][0], accO[mi][ni][1]);
            *(float2*)(ao + (size_t)(tok + 8) * UPDIM + hh * 64 + col) =
                make_float2(accO[mi][ni][2], accO[mi][ni][3]);
        }
    }
}

// ---------------------------------------------------------------------------
static void split(const float* x, __nv_bfloat16* hi, __nv_bfloat16* lo, int n)
{
    split_kernel<<<(n + 255) / 256, 256>>>(x, hi, lo, n);
}

extern "C" void kernel_launch(void* const* d_in, const int* in_sizes, int n_in,
                              void* d_out, int out_size)
{
    const float* h    = (const float*)d_in[0];
    const float* Wdkv = (const float*)d_in[1];
    const float* bdkv = (const float*)d_in[2];
    const float* Wuk  = (const float*)d_in[3];
    const float* buk  = (const float*)d_in[4];
    const float* Wuv  = (const float*)d_in[5];
    const float* buv  = (const float*)d_in[6];
    const float* Wdq  = (const float*)d_in[7];
    const float* bdq  = (const float*)d_in[8];
    const float* Wuq  = (const float*)d_in[9];
    const float* buq  = (const float*)d_in[10];
    const float* Wqr  = (const float*)d_in[11];
    const float* bqr  = (const float*)d_in[12];
    const float* Wkr  = (const float*)d_in[13];
    const float* bkr  = (const float*)d_in[14];
    const float* Wfc  = (const float*)d_in[15];
    const float* bfc  = (const float*)d_in[16];
    float* out = (float*)d_out;

    float *ckv, *cq, *kc, *vc, *qc, *qr, *kr, *ao;
    cudaGetSymbolAddress((void**)&ckv, g_ckv);
    cudaGetSymbolAddress((void**)&cq,  g_cq);
    cudaGetSymbolAddress((void**)&kc,  g_kc);
    cudaGetSymbolAddress((void**)&vc,  g_vc);
    cudaGetSymbolAddress((void**)&qc,  g_qc);
    cudaGetSymbolAddress((void**)&qr,  g_qr);
    cudaGetSymbolAddress((void**)&kr,  g_kr);
    cudaGetSymbolAddress((void**)&ao,  g_ao);

    __nv_bfloat16 *hH, *hL, *ckvH, *ckvL, *cqH, *cqL, *aoH, *aoL;
    __nv_bfloat16 *WdkvH, *WdkvL, *WdqH, *WdqL, *WkrH, *WkrL;
    __nv_bfloat16 *WukH, *WukL, *WuvH, *WuvL, *WuqH, *WuqL, *WqrH, *WqrL;
    __nv_bfloat16 *WfcH, *WfcL;
    __nv_bfloat16 *QPH, *QPL, *KPH, *KPL, *VPH, *VPL;
    cudaGetSymbolAddress((void**)&hH,    g_hH);
    cudaGetSymbolAddress((void**)&hL,    g_hL);
    cudaGetSymbolAddress((void**)&ckvH,  g_ckvH);
    cudaGetSymbolAddress((void**)&ckvL,  g_ckvL);
    cudaGetSymbolAddress((void**)&cqH,   g_cqH);
    cudaGetSymbolAddress((void**)&cqL,   g_cqL);
    cudaGetSymbolAddress((void**)&aoH,   g_aoH);
    cudaGetSymbolAddress((void**)&aoL,   g_aoL);
    cudaGetSymbolAddress((void**)&WdkvH, g_WdkvH);
    cudaGetSymbolAddress((void**)&WdkvL, g_WdkvL);
    cudaGetSymbolAddress((void**)&WdqH,  g_WdqH);
    cudaGetSymbolAddress((void**)&WdqL,  g_WdqL);
    cudaGetSymbolAddress((void**)&WkrH,  g_WkrH);
    cudaGetSymbolAddress((void**)&WkrL,  g_WkrL);
    cudaGetSymbolAddress((void**)&WukH,  g_WukH);
    cudaGetSymbolAddress((void**)&WukL,  g_WukL);
    cudaGetSymbolAddress((void**)&WuvH,  g_WuvH);
    cudaGetSymbolAddress((void**)&WuvL,  g_WuvL);
    cudaGetSymbolAddress((void**)&WuqH,  g_WuqH);
    cudaGetSymbolAddress((void**)&WuqL,  g_WuqL);
    cudaGetSymbolAddress((void**)&WqrH,  g_WqrH);
    cudaGetSymbolAddress((void**)&WqrL,  g_WqrL);
    cudaGetSymbolAddress((void**)&WfcH,  g_WfcH);
    cudaGetSymbolAddress((void**)&WfcL,  g_WfcL);
    cudaGetSymbolAddress((void**)&QPH,   g_QPH);
    cudaGetSymbolAddress((void**)&QPL,   g_QPL);
    cudaGetSymbolAddress((void**)&KPH,   g_KPH);
    cudaGetSymbolAddress((void**)&KPL,   g_KPL);
    cudaGetSymbolAddress((void**)&VPH,   g_VPH);
    cudaGetSymbolAddress((void**)&VPL,   g_VPL);

    cudaFuncSetAttribute(attn2_kernel,
                         cudaFuncAttributeMaxDynamicSharedMemorySize, ATTN2_SMEM);

    // splits: activations + weights
    split(h,    hH,    hL,    TOK * DMODEL);
    split(Wdkv, WdkvH, WdkvL, DOWND * DMODEL);
    split(Wdq,  WdqH,  WdqL,  DOWND * DMODEL);
    split(Wkr,  WkrH,  WkrL,  RDIM * DMODEL);
    split(Wuk,  WukH,  WukL,  UPDIM * DOWND);
    split(Wuv,  WuvH,  WuvL,  UPDIM * DOWND);
    split(Wuq,  WuqH,  WuqL,  UPDIM * DOWND);
    split(Wqr,  WqrH,  WqrL,  UPDIM * DOWND);
    split(Wfc,  WfcH,  WfcL,  DMODEL * UPDIM);

    dim3 blk(256);
    // down projections + decoupled k rope projection
    tgemm_kernel<<<dim3(DOWND / 128, TOK / 128), blk>>>(hH, hL, WdkvH, WdkvL, bdkv, ckv, DOWND, DMODEL);
    tgemm_kernel<<<dim3(DOWND / 128, TOK / 128), blk>>>(hH, hL, WdqH,  WdqL,  bdq,  cq,  DOWND, DMODEL);
    tgemm_kernel<<<dim3(1,           TOK / 128), blk>>>(hH, hL, WkrH,  WkrL,  bkr,  kr,  RDIM,  DMODEL);

    split(ckv, ckvH, ckvL, TOK * DOWND);
    split(cq,  cqH,  cqL,  TOK * DOWND);

    // up projections
    tgemm_kernel<<<dim3(UPDIM / 128, TOK / 128), blk>>>(ckvH, ckvL, WukH, WukL, buk, kc, UPDIM, DOWND);
    tgemm_kernel<<<dim3(UPDIM / 128, TOK / 128), blk>>>(ckvH, ckvL, WuvH, WuvL, buv, vc, UPDIM, DOWND);
    tgemm_kernel<<<dim3(UPDIM / 128, TOK / 128), blk>>>(cqH,  cqL,  WuqH, WuqL, buq, qc, UPDIM, DOWND);
    tgemm_kernel<<<dim3(UPDIM / 128, TOK / 128), blk>>>(cqH,  cqL,  WqrH, WqrL, bqr, qr, UPDIM, DOWND);

    // pack (rope fused) + attention
    qpack_kernel<<<NBH * SEQLEN * 64 / 256, 256>>>(qc, qr, QPH, QPL);
    kpack_kernel<<<NBH * SEQLEN * 64 / 256, 256>>>(kc, kr, KPH, KPL);
    vpack_kernel<<<NBH * SEQLEN * 32 / 256, 256>>>(vc, VPH, VPL);
    attn2_kernel<<<dim3(SEQLEN / 64, NHEADS, BATCH), blk, ATTN2_SMEM>>>(
        QPH, QPL, KPH, KPL, VPH, VPL, ao);

    // output projection
    split(ao, aoH, aoL, TOK * UPDIM);
    tgemm_kernel<<<dim3(DMODEL / 128, TOK / 128), blk>>>(aoH, aoL, WfcH, WfcL, bfc, out, DMODEL, UPDIM);
}

// round 7
// speedup vs baseline: 2.5032x; 1.2074x over previous
#include <cuda_runtime.h>
#include <cuda_bf16.h>
#include <math.h>
#include <cstdint>

// ===========================================================================
// MLA attention. All GEMMs + attention via mma.sync bf16 split (3 MMAs, fp32
// accum). GEMMs double-buffered with cp.async. RoPE fused into pack kernels.
// ===========================================================================

#define TOK    8192
#define SEQLEN 512
#define DMODEL 2048
#define DOWND  512
#define UPDIM  1024
#define NHEADS 16
#define RDIM   64
#define BATCH  16
#define NBH    (BATCH * NHEADS)

// ------------------------------ scratch ------------------------------------
__device__ float g_ckv[TOK * DOWND];
__device__ float g_cq [TOK * DOWND];
__device__ float g_kc [TOK * UPDIM];
__device__ float g_vc [TOK * UPDIM];
__device__ float g_qc [TOK * UPDIM];
__device__ float g_qr [TOK * UPDIM];
__device__ float g_kr [TOK * RDIM];
__device__ float g_ao [TOK * UPDIM];

__device__ __nv_bfloat16 g_hH [TOK * DMODEL];
__device__ __nv_bfloat16 g_hL [TOK * DMODEL];
__device__ __nv_bfloat16 g_ckvH[TOK * DOWND];
__device__ __nv_bfloat16 g_ckvL[TOK * DOWND];
__device__ __nv_bfloat16 g_cqH [TOK * DOWND];
__device__ __nv_bfloat16 g_cqL [TOK * DOWND];
__device__ __nv_bfloat16 g_aoH [TOK * UPDIM];
__device__ __nv_bfloat16 g_aoL [TOK * UPDIM];

__device__ __nv_bfloat16 g_WdkvH[DOWND * DMODEL];
__device__ __nv_bfloat16 g_WdkvL[DOWND * DMODEL];
__device__ __nv_bfloat16 g_WdqH [DOWND * DMODEL];
__device__ __nv_bfloat16 g_WdqL [DOWND * DMODEL];
__device__ __nv_bfloat16 g_WkrH [RDIM * DMODEL];
__device__ __nv_bfloat16 g_WkrL [RDIM * DMODEL];
__device__ __nv_bfloat16 g_WukH [UPDIM * DOWND];
__device__ __nv_bfloat16 g_WukL [UPDIM * DOWND];
__device__ __nv_bfloat16 g_WuvH [UPDIM * DOWND];
__device__ __nv_bfloat16 g_WuvL [UPDIM * DOWND];
__device__ __nv_bfloat16 g_WuqH [UPDIM * DOWND];
__device__ __nv_bfloat16 g_WuqL [UPDIM * DOWND];
__device__ __nv_bfloat16 g_WqrH [UPDIM * DOWND];
__device__ __nv_bfloat16 g_WqrL [UPDIM * DOWND];
__device__ __nv_bfloat16 g_WfcH [DMODEL * UPDIM];
__device__ __nv_bfloat16 g_WfcL [DMODEL * UPDIM];

// packed attention operands: [bh][seq][dim] hi/lo
__device__ __nv_bfloat16 g_QPH[NBH * SEQLEN * 128];
__device__ __nv_bfloat16 g_QPL[NBH * SEQLEN * 128];
__device__ __nv_bfloat16 g_KPH[NBH * SEQLEN * 128];
__device__ __nv_bfloat16 g_KPL[NBH * SEQLEN * 128];
__device__ __nv_bfloat16 g_VPH[NBH * SEQLEN * 64];
__device__ __nv_bfloat16 g_VPL[NBH * SEQLEN * 64];

// ------------------------------ helpers ------------------------------------
__device__ __forceinline__ uint32_t smem_u32(const void* p) {
    uint32_t a;
    asm("{ .reg .u64 t; cvta.to.shared.u64 t, %1; cvt.u32.u64 %0, t; }"
        : "=r"(a) : "l"(p));
    return a;
}
__device__ __forceinline__ void ldsm_x4(uint32_t& r0, uint32_t& r1,
                                        uint32_t& r2, uint32_t& r3,
                                        uint32_t addr) {
    asm volatile("ldmatrix.sync.aligned.m8n8.x4.shared.b16 {%0,%1,%2,%3}, [%4];"
                 : "=r"(r0), "=r"(r1), "=r"(r2), "=r"(r3) : "r"(addr));
}
__device__ __forceinline__ void ldsm_x2(uint32_t& r0, uint32_t& r1,
                                        uint32_t addr) {
    asm volatile("ldmatrix.sync.aligned.m8n8.x2.shared.b16 {%0,%1}, [%2];"
                 : "=r"(r0), "=r"(r1) : "r"(addr));
}
__device__ __forceinline__ void mma16816(float* c, const uint32_t* a,
                                         const uint32_t* b) {
    asm volatile(
        "mma.sync.aligned.m16n8k16.row.col.f32.bf16.bf16.f32 "
        "{%0,%1,%2,%3}, {%4,%5,%6,%7}, {%8,%9}, {%0,%1,%2,%3};"
        : "+f"(c[0]), "+f"(c[1]), "+f"(c[2]), "+f"(c[3])
        : "r"(a[0]), "r"(a[1]), "r"(a[2]), "r"(a[3]), "r"(b[0]), "r"(b[1]));
}
__device__ __forceinline__ void cp16(uint32_t dst, const void* src, int nbytes) {
    asm volatile("cp.async.cg.shared.global [%0], [%1], 16, %2;"
                 :: "r"(dst), "l"(src), "r"(nbytes));
}
__device__ __forceinline__ void cp_commit() {
    asm volatile("cp.async.commit_group;");
}
template <int N> __device__ __forceinline__ void cp_wait() {
    asm volatile("cp.async.wait_group %0;" :: "n"(N));
}
__device__ __forceinline__ void splt(float v, __nv_bfloat16& h, __nv_bfloat16& l) {
    h = __float2bfloat16(v);
    l = __float2bfloat16(v - __bfloat162float(h));
}
__device__ __forceinline__ void f2_hilo(float2 f, uint32_t& h, uint32_t& l) {
    __nv_bfloat162 hb = __floats2bfloat162_rn(f.x, f.y);
    float rx = f.x - __bfloat162float(hb.x);
    float ry = f.y - __bfloat162float(hb.y);
    __nv_bfloat162 lb = __floats2bfloat162_rn(rx, ry);
    h = *(uint32_t*)&hb;
    l = *(uint32_t*)&lb;
}

// ------------------------------ split kernel (x2 vectorized) ---------------
__global__ void split_kernel(const float* __restrict__ x,
                             __nv_bfloat16* __restrict__ hi,
                             __nv_bfloat16* __restrict__ lo, int n2)
{
    int i = blockIdx.x * blockDim.x + threadIdx.x;
    if (i >= n2) return;
    float2 v = *(const float2*)(x + i * 2);
    __nv_bfloat162 hb = __floats2bfloat162_rn(v.x, v.y);
    float rx = v.x - __bfloat162float(hb.x);
    float ry = v.y - __bfloat162float(hb.y);
    __nv_bfloat162 lb = __floats2bfloat162_rn(rx, ry);
    *(__nv_bfloat162*)(hi + i * 2) = hb;
    *(__nv_bfloat162*)(lo + i * 2) = lb;
}

// ------------------------------ tensor GEMM (cp.async pipelined) -----------
// C(M,N) = A(M,K) @ W^T(N,K) + bias.  CTA 128x128, K-chunk 32, 8 warps,
// warp tile 64x32.  2-stage cp.async double buffer.
#define ROWB 80
#define TILEB (128 * ROWB)
#define STAGEB (4 * TILEB)
#define GT_SMEM (2 * STAGEB)

__global__ __launch_bounds__(256)
void tgemm_kernel(const __nv_bfloat16* __restrict__ Ah,
                  const __nv_bfloat16* __restrict__ Al,
                  const __nv_bfloat16* __restrict__ Bh,
                  const __nv_bfloat16* __restrict__ Bl,
                  const float* __restrict__ bias,
                  float* __restrict__ C,
                  int N, int K)
{
    extern __shared__ __align__(16) char smem[];

    const int tid  = threadIdx.x;
    const int wid  = tid >> 5;
    const int lane = tid & 31;
    const int wm   = wid >> 2;
    const int wn   = wid & 3;
    const int m0   = blockIdx.y * 128;
    const int n0   = blockIdx.x * 128;
    const uint32_t sb = smem_u32(smem);

    const __nv_bfloat16* srcs[4] = {Ah, Al, Bh, Bl};

    // per-thread load mapping: 2 iters x (row, q)
    const int lrow0 = tid >> 2;            // via idx=tid
    const int lq0   = tid & 3;
    const int lrow1 = (tid + 256) >> 2;
    const int lq1   = (tid + 256) & 3;

    float acc[4][4][4];
#pragma unroll
    for (int i = 0; i < 4; i++)
#pragma unroll
        for (int j = 0; j < 4; j++)
#pragma unroll
            for (int v = 0; v < 4; v++) acc[i][j][v] = 0.0f;

    const int r16   = lane & 15;
    const int khalfA = (lane >> 4) * 16;
    const int r8    = lane & 7;
    const int khalfB = ((lane >> 3) & 1) * 16;

    const int nchunks = K >> 5;

    // ---- issue chunk 0 into stage 0 ----
    {
        const int k0 = 0;
#pragma unroll
        for (int t = 0; t < 4; t++) {
            const bool isB = (t >= 2);
            const __nv_bfloat16* src = srcs[t];
            {
                int grow = isB ? (n0 + lrow0) : (m0 + lrow0);
                int ok = (!isB || grow < N) ? 16 : 0;
                if (!ok) grow = isB ? n0 : m0;
                cp16(sb + t * TILEB + lrow0 * ROWB + lq0 * 16,
                     src + (size_t)grow * K + k0 + lq0 * 8, ok);
            }
            {
                int grow = isB ? (n0 + lrow1) : (m0 + lrow1);
                int ok = (!isB || grow < N) ? 16 : 0;
                if (!ok) grow = isB ? n0 : m0;
                cp16(sb + t * TILEB + lrow1 * ROWB + lq1 * 16,
                     src + (size_t)grow * K + k0 + lq1 * 8, ok);
            }
        }
        cp_commit();
    }

    for (int ci = 0; ci < nchunks; ci++) {
        const uint32_t cur = sb + (uint32_t)(ci & 1) * STAGEB;

        // issue next chunk into other stage
        if (ci + 1 < nchunks) {
            const int k0 = (ci + 1) << 5;
            const uint32_t nxt = sb + (uint32_t)((ci + 1) & 1) * STAGEB;
#pragma unroll
            for (int t = 0; t < 4; t++) {
                const bool isB = (t >= 2);
                const __nv_bfloat16* src = srcs[t];
                {
                    int grow = isB ? (n0 + lrow0) : (m0 + lrow0);
                    int ok = (!isB || grow < N) ? 16 : 0;
                    if (!ok) grow = isB ? n0 : m0;
                    cp16(nxt + t * TILEB + lrow0 * ROWB + lq0 * 16,
                         src + (size_t)grow * K + k0 + lq0 * 8, ok);
                }
                {
                    int grow = isB ? (n0 + lrow1) : (m0 + lrow1);
                    int ok = (!isB || grow < N) ? 16 : 0;
                    if (!ok) grow = isB ? n0 : m0;
                    cp16(nxt + t * TILEB + lrow1 * ROWB + lq1 * 16,
                         src + (size_t)grow * K + k0 + lq1 * 8, ok);
                }
            }
            cp_commit();
            cp_wait<1>();
        } else {
            cp_wait<0>();
        }
        __syncthreads();

#pragma unroll
        for (int ks = 0; ks < 2; ks++) {
            const int kb = ks * 32;
            uint32_t ah[4][4], al[4][4], bh[4][2], bl[4][2];
#pragma unroll
            for (int mi = 0; mi < 4; mi++)
                ldsm_x4(ah[mi][0], ah[mi][1], ah[mi][2], ah[mi][3],
                        cur + 0 * TILEB + (wm * 64 + mi * 16 + r16) * ROWB + kb + khalfA);
#pragma unroll
            for (int ni = 0; ni < 4; ni++)
                ldsm_x2(bh[ni][0], bh[ni][1],
                        cur + 2 * TILEB + (wn * 32 + ni * 8 + r8) * ROWB + kb + khalfB);
#pragma unroll
            for (int mi = 0; mi < 4; mi++)
#pragma unroll
                for (int ni = 0; ni < 4; ni++)
                    mma16816(acc[mi][ni], ah[mi], bh[ni]);

#pragma unroll
            for (int ni = 0; ni < 4; ni++)
                ldsm_x2(bl[ni][0], bl[ni][1],
                        cur + 3 * TILEB + (wn * 32 + ni * 8 + r8) * ROWB + kb + khalfB);
#pragma unroll
            for (int mi = 0; mi < 4; mi++)
#pragma unroll
                for (int ni = 0; ni < 4; ni++)
                    mma16816(acc[mi][ni], ah[mi], bl[ni]);

#pragma unroll
            for (int mi = 0; mi < 4; mi++)
                ldsm_x4(al[mi][0], al[mi][1], al[mi][2], al[mi][3],
                        cur + 1 * TILEB + (wm * 64 + mi * 16 + r16) * ROWB + kb + khalfA);
#pragma unroll
            for (int mi = 0; mi < 4; mi++)
#pragma unroll
                for (int ni = 0; ni < 4; ni++)
                    mma16816(acc[mi][ni], al[mi], bh[ni]);
        }
        __syncthreads();
    }

#pragma unroll
    for (int mi = 0; mi < 4; mi++) {
        int row0 = m0 + wm * 64 + mi * 16 + (lane >> 2);
#pragma unroll
        for (int ni = 0; ni < 4; ni++) {
            int col = n0 + wn * 32 + ni * 8 + 2 * (lane & 3);
            if (col < N) {
                float2 b2 = *(const float2*)(bias + col);
                float2 o0 = make_float2(acc[mi][ni][0] + b2.x, acc[mi][ni][1] + b2.y);
                float2 o1 = make_float2(acc[mi][ni][2] + b2.x, acc[mi][ni][3] + b2.y);
                *(float2*)(C + (size_t)row0 * N + col) = o0;
                *(float2*)(C + (size_t)(row0 + 8) * N + col) = o1;
            }
        }
    }
}

// ------------------------------ pack kernels (rope fused) ------------------
__global__ void qpack_kernel(const float* __restrict__ qc,
                             const float* __restrict__ qr,
                             __nv_bfloat16* __restrict__ PH,
                             __nv_bfloat16* __restrict__ PL)
{
    int idx = blockIdx.x * 256 + threadIdx.x;
    int d2 = idx & 63;
    int s  = (idx >> 6) & (SEQLEN - 1);
    int bh = idx >> 15;
    int h = bh & (NHEADS - 1), b = bh >> 4;
    int tok = b * SEQLEN + s;
    float f0, f1;
    int dd;
    if (d2 < 32) {
        dd = d2 * 2;
        float2 v = *(const float2*)(qc + (size_t)tok * UPDIM + h * 64 + dd);
        f0 = v.x; f1 = v.y;
    } else {
        int pair = d2 - 32;
        int rp = pair * 2;
        float2 v = *(const float2*)(qr + (size_t)tok * UPDIM + h * 64 + rp);
        float theta = powf(10000.0f, -(float)pair * (1.0f / 32.0f));
        float sn, cs;
        sincosf((float)s * theta, &sn, &cs);
        f0 = v.x * sn - v.y * cs;
        f1 = v.y * sn + v.x * cs;
        dd = 64 + rp;
    }
    size_t base = ((size_t)bh * SEQLEN + s) * 128 + dd;
    splt(f0, PH[base], PL[base]);
    splt(f1, PH[base + 1], PL[base + 1]);
}

__global__ void kpack_kernel(const float* __restrict__ kc,
                             const float* __restrict__ kr,
                             __nv_bfloat16* __restrict__ PH,
                             __nv_bfloat16* __restrict__ PL)
{
    int idx = blockIdx.x * 256 + threadIdx.x;
    int d2 = idx & 63;
    int s  = (idx >> 6) & (SEQLEN - 1);
    int bh = idx >> 15;
    int h = bh & (NHEADS - 1), b = bh >> 4;
    int tok = b * SEQLEN + s;
    float f0, f1;
    int dd;
    if (d2 < 32) {
        dd = d2 * 2;
        float2 v = *(const float2*)(kc + (size_t)tok * UPDIM + h * 64 + dd);
        f0 = v.x; f1 = v.y;
    } else {
        int pair = d2 - 32;
        int rp = pair * 2;
        float2 v = *(const float2*)(kr + (size_t)tok * RDIM + rp);
        float theta = powf(10000.0f, -(float)pair * (1.0f / 32.0f));
        float sn, cs;
        sincosf((float)s * theta, &sn, &cs);
        f0 = v.x * sn - v.y * cs;
        f1 = v.y * sn + v.x * cs;
        dd = 64 + rp;
    }
    size_t base = ((size_t)bh * SEQLEN + s) * 128 + dd;
    splt(f0, PH[base], PL[base]);
    splt(f1, PH[base + 1], PL[base + 1]);
}

__global__ void vpack_kernel(const float* __restrict__ vc,
                             __nv_bfloat16* __restrict__ PH,
                             __nv_bfloat16* __restrict__ PL)
{
    int idx = blockIdx.x * 256 + threadIdx.x;
    int d2 = idx & 31;
    int s  = (idx >> 5) & (SEQLEN - 1);
    int bh = idx >> 14;
    int h = bh & (NHEADS - 1), b = bh >> 4;
    int tok = b * SEQLEN + s;
    int dd = d2 * 2;
    float2 v = *(const float2*)(vc + (size_t)tok * UPDIM + h * 64 + dd);
    size_t base = ((size_t)bh * SEQLEN + s) * 64 + dd;
    splt(v.x, PH[base], PL[base]);
    splt(v.y, PH[base + 1], PL[base + 1]);
}

// ------------------------------ attention (mma.sync) -----------------------
#define QPITCH 272
#define VPITCH 144
#define SPITCH 516
#define OFF_QH 0
#define OFF_QL 17408
#define OFF_KH 34816
#define OFF_KL 52224
#define OFF_VH 34816
#define OFF_VL 44032
#define OFF_S  69632
#define ATTN2_SMEM (OFF_S + 64 * SPITCH * 4)

__global__ __launch_bounds__(256)
void attn2_kernel(const __nv_bfloat16* __restrict__ QPH,
                  const __nv_bfloat16* __restrict__ QPL,
                  const __nv_bfloat16* __restrict__ KPH,
                  const __nv_bfloat16* __restrict__ KPL,
                  const __nv_bfloat16* __restrict__ VPH,
                  const __nv_bfloat16* __restrict__ VPL,
                  float* __restrict__ ao)
{
    extern __shared__ char sm2[];
    const uint32_t sb = smem_u32(sm2);
    float* Ssf = (float*)(sm2 + OFF_S);

    const int tid  = threadIdx.x;
    const int wid  = tid >> 5;
    const int lane = tid & 31;
    const int wm = wid >> 2;
    const int wn = wid & 3;
    const int q0 = blockIdx.x * 64;
    const int hh = blockIdx.y;
    const int b  = blockIdx.z;
    const int bh = b * NHEADS + hh;
    const size_t pbase = (size_t)bh * SEQLEN * 128;
    const float scale = 0.07216878364870322f;

    const int r16 = lane & 15;
    const int khalfA = (lane >> 4) * 16;
    const int r8 = lane & 7;
    const int khalfB = ((lane >> 3) & 1) * 16;

#pragma unroll
    for (int j = 0; j < 4; j++) {
        int idx = tid + j * 256;
        int row = idx >> 4, c = idx & 15;
        size_t g = pbase + (size_t)(q0 + row) * 128 + c * 8;
        *(uint4*)(sm2 + OFF_QH + row * QPITCH + c * 16) = *(const uint4*)(QPH + g);
        *(uint4*)(sm2 + OFF_QL + row * QPITCH + c * 16) = *(const uint4*)(QPL + g);
    }

    for (int kt = 0; kt < 8; kt++) {
        __syncthreads();
#pragma unroll
        for (int j = 0; j < 4; j++) {
            int idx = tid + j * 256;
            int row = idx >> 4, c = idx & 15;
            size_t g = pbase + (size_t)(kt * 64 + row) * 128 + c * 8;
            *(uint4*)(sm2 + OFF_KH + row * QPITCH + c * 16) = *(const uint4*)(KPH + g);
            *(uint4*)(sm2 + OFF_KL + row * QPITCH + c * 16) = *(const uint4*)(KPL + g);
        }
        __syncthreads();

        float acc[2][2][4];
#pragma unroll
        for (int mi = 0; mi < 2; mi++)
#pragma unroll
            for (int ni = 0; ni < 2; ni++)
#pragma unroll
                for (int v = 0; v < 4; v++) acc[mi][ni][v] = 0.0f;

#pragma unroll
        for (int ks = 0; ks < 8; ks++) {
            const int kb = ks * 32;
            uint32_t ah[2][4], al[2][4], bhf[2][2], blf[2][2];
#pragma unroll
            for (int mi = 0; mi < 2; mi++)
                ldsm_x4(ah[mi][0], ah[mi][1], ah[mi][2], ah[mi][3],
                        sb + OFF_QH + (wm * 32 + mi * 16 + r16) * QPITCH + kb + khalfA);
#pragma unroll
            for (int ni = 0; ni < 2; ni++)
                ldsm_x2(bhf[ni][0], bhf[ni][1],
                        sb + OFF_KH + (wn * 16 + ni * 8 + r8) * QPITCH + kb + khalfB);
#pragma unroll
            for (int mi = 0; mi < 2; mi++)
#pragma unroll
                for (int ni = 0; ni < 2; ni++)
                    mma16816(acc[mi][ni], ah[mi], bhf[ni]);
#pragma unroll
            for (int ni = 0; ni < 2; ni++)
                ldsm_x2(blf[ni][0], blf[ni][1],
                        sb + OFF_KL + (wn * 16 + ni * 8 + r8) * QPITCH + kb + khalfB);
#pragma unroll
            for (int mi = 0; mi < 2; mi++)
#pragma unroll
                for (int ni = 0; ni < 2; ni++)
                    mma16816(acc[mi][ni], ah[mi], blf[ni]);
#pragma unroll
            for (int mi = 0; mi < 2; mi++)
                ldsm_x4(al[mi][0], al[mi][1], al[mi][2], al[mi][3],
                        sb + OFF_QL + (wm * 32 + mi * 16 + r16) * QPITCH + kb + khalfA);
#pragma unroll
            for (int mi = 0; mi < 2; mi++)
#pragma unroll
                for (int ni = 0; ni < 2; ni++)
                    mma16816(acc[mi][ni], al[mi], bhf[ni]);
        }

#pragma unroll
        for (int mi = 0; mi < 2; mi++) {
            int row = wm * 32 + mi * 16 + (lane >> 2);
#pragma unroll
            for (int ni = 0; ni < 2; ni++) {
                int col = kt * 64 + wn * 16 + ni * 8 + 2 * (lane & 3);
                Ssf[row * SPITCH + col]           = acc[mi][ni][0] * scale;
                Ssf[row * SPITCH + col + 1]       = acc[mi][ni][1] * scale;
                Ssf[(row + 8) * SPITCH + col]     = acc[mi][ni][2] * scale;
                Ssf[(row + 8) * SPITCH + col + 1] = acc[mi][ni][3] * scale;
            }
        }
    }
    __syncthreads();

    {
        int row  = tid >> 2;
        int part = tid & 3;
        float* srow = Ssf + row * SPITCH;
        float mx = -1e30f;
#pragma unroll 4
        for (int k2 = 0; k2 < 128; k2++)
            mx = fmaxf(mx, srow[part + k2 * 4]);
        mx = fmaxf(mx, __shfl_xor_sync(0xffffffffu, mx, 1));
        mx = fmaxf(mx, __shfl_xor_sync(0xffffffffu, mx, 2));
        float sum = 0.0f;
#pragma unroll 4
        for (int k2 = 0; k2 < 128; k2++) {
            float e = __expf(srow[part + k2 * 4] - mx);
            srow[part + k2 * 4] = e;
            sum += e;
        }
        sum += __shfl_xor_sync(0xffffffffu, sum, 1);
        sum += __shfl_xor_sync(0xffffffffu, sum, 2);
        float inv = 1.0f / sum;
#pragma unroll 4
        for (int k2 = 0; k2 < 128; k2++)
            srow[part + k2 * 4] *= inv;
    }

    float accO[2][2][4];
#pragma unroll
    for (int mi = 0; mi < 2; mi++)
#pragma unroll
        for (int ni = 0; ni < 2; ni++)
#pragma unroll
            for (int v = 0; v < 4; v++) accO[mi][ni][v] = 0.0f;

    const size_t vbase = (size_t)bh * SEQLEN * 64;
    for (int kt = 0; kt < 8; kt++) {
        __syncthreads();
#pragma unroll
        for (int j = 0; j < 2; j++) {
            int idx = tid + j * 256;
            int key = idx >> 3, dg = idx & 7;
            size_t g = vbase + (size_t)(kt * 64 + key) * 64 + dg * 8;
            uint4 vh = *(const uint4*)(VPH + g);
            uint4 vl = *(const uint4*)(VPL + g);
            const uint16_t* ph = (const uint16_t*)&vh;
            const uint16_t* pl = (const uint16_t*)&vl;
#pragma unroll
            for (int jj = 0; jj < 8; jj++) {
                *(uint16_t*)(sm2 + OFF_VH + (dg * 8 + jj) * VPITCH + key * 2) = ph[jj];
                *(uint16_t*)(sm2 + OFF_VL + (dg * 8 + jj) * VPITCH + key * 2) = pl[jj];
            }
        }
        __syncthreads();

#pragma unroll
        for (int ks = 0; ks < 4; ks++) {
            uint32_t ph_[2][4], pl_[2][4];
#pragma unroll
            for (int mi = 0; mi < 2; mi++) {
                int r  = wm * 32 + mi * 16 + (lane >> 2);
                int kc = kt * 64 + ks * 16 + 2 * (lane & 3);
                f2_hilo(*(float2*)&Ssf[r * SPITCH + kc],           ph_[mi][0], pl_[mi][0]);
                f2_hilo(*(float2*)&Ssf[(r + 8) * SPITCH + kc],     ph_[mi][1], pl_[mi][1]);
                f2_hilo(*(float2*)&Ssf[r * SPITCH + kc + 8],       ph_[mi][2], pl_[mi][2]);
                f2_hilo(*(float2*)&Ssf[(r + 8) * SPITCH + kc + 8], ph_[mi][3], pl_[mi][3]);
            }
            uint32_t vh_[2][2], vl_[2][2];
#pragma unroll
            for (int ni = 0; ni < 2; ni++) {
                uint32_t a = sb + (wn * 16 + ni * 8 + r8) * VPITCH + ks * 32 + khalfB;
                ldsm_x2(vh_[ni][0], vh_[ni][1], a + OFF_VH);
                ldsm_x2(vl_[ni][0], vl_[ni][1], a + OFF_VL);
            }
#pragma unroll
            for (int mi = 0; mi < 2; mi++)
#pragma unroll
                for (int ni = 0; ni < 2; ni++) {
                    mma16816(accO[mi][ni], ph_[mi], vh_[ni]);
                    mma16816(accO[mi][ni], pl_[mi], vh_[ni]);
                    mma16816(accO[mi][ni], ph_[mi], vl_[ni]);
                }
        }
    }

#pragma unroll
    for (int mi = 0; mi < 2; mi++) {
        int rloc = wm * 32 + mi * 16 + (lane >> 2);
        int tok  = b * SEQLEN + q0 + rloc;
#pragma unroll
        for (int ni = 0; ni < 2; ni++) {
            int col = wn * 16 + ni * 8 + 2 * (lane & 3);
            *(float2*)(ao + (size_t)tok * UPDIM + hh * 64 + col) =
                make_float2(accO[mi][ni][0], accO[mi][ni][1]);
            *(float2*)(ao + (size_t)(tok + 8) * UPDIM + hh * 64 + col) =
                make_float2(accO[mi][ni][2], accO[mi][ni][3]);
        }
    }
}

// ---------------------------------------------------------------------------
static void split(const float* x, __nv_bfloat16* hi, __nv_bfloat16* lo, int n)
{
    int n2 = n / 2;
    split_kernel<<<(n2 + 255) / 256, 256>>>(x, hi, lo, n2);
}

extern "C" void kernel_launch(void* const* d_in, const int* in_sizes, int n_in,
                              void* d_out, int out_size)
{
    const float* h    = (const float*)d_in[0];
    const float* Wdkv = (const float*)d_in[1];
    const float* bdkv = (const float*)d_in[2];
    const float* Wuk  = (const float*)d_in[3];
    const float* buk  = (const float*)d_in[4];
    const float* Wuv  = (const float*)d_in[5];
    const float* buv  = (const float*)d_in[6];
    const float* Wdq  = (const float*)d_in[7];
    const float* bdq  = (const float*)d_in[8];
    const float* Wuq  = (const float*)d_in[9];
    const float* buq  = (const float*)d_in[10];
    const float* Wqr  = (const float*)d_in[11];
    const float* bqr  = (const float*)d_in[12];
    const float* Wkr  = (const float*)d_in[13];
    const float* bkr  = (const float*)d_in[14];
    const float* Wfc  = (const float*)d_in[15];
    const float* bfc  = (const float*)d_in[16];
    float* out = (float*)d_out;

    float *ckv, *cq, *kc, *vc, *qc, *qr, *kr, *ao;
    cudaGetSymbolAddress((void**)&ckv, g_ckv);
    cudaGetSymbolAddress((void**)&cq,  g_cq);
    cudaGetSymbolAddress((void**)&kc,  g_kc);
    cudaGetSymbolAddress((void**)&vc,  g_vc);
    cudaGetSymbolAddress((void**)&qc,  g_qc);
    cudaGetSymbolAddress((void**)&qr,  g_qr);
    cudaGetSymbolAddress((void**)&kr,  g_kr);
    cudaGetSymbolAddress((void**)&ao,  g_ao);

    __nv_bfloat16 *hH, *hL, *ckvH, *ckvL, *cqH, *cqL, *aoH, *aoL;
    __nv_bfloat16 *WdkvH, *WdkvL, *WdqH, *WdqL, *WkrH, *WkrL;
    __nv_bfloat16 *WukH, *WukL, *WuvH, *WuvL, *WuqH, *WuqL, *WqrH, *WqrL;
    __nv_bfloat16 *WfcH, *WfcL;
    __nv_bfloat16 *QPH, *QPL, *KPH, *KPL, *VPH, *VPL;
    cudaGetSymbolAddress((void**)&hH,    g_hH);
    cudaGetSymbolAddress((void**)&hL,    g_hL);
    cudaGetSymbolAddress((void**)&ckvH,  g_ckvH);
    cudaGetSymbolAddress((void**)&ckvL,  g_ckvL);
    cudaGetSymbolAddress((void**)&cqH,   g_cqH);
    cudaGetSymbolAddress((void**)&cqL,   g_cqL);
    cudaGetSymbolAddress((void**)&aoH,   g_aoH);
    cudaGetSymbolAddress((void**)&aoL,   g_aoL);
    cudaGetSymbolAddress((void**)&WdkvH, g_WdkvH);
    cudaGetSymbolAddress((void**)&WdkvL, g_WdkvL);
    cudaGetSymbolAddress((void**)&WdqH,  g_WdqH);
    cudaGetSymbolAddress((void**)&WdqL,  g_WdqL);
    cudaGetSymbolAddress((void**)&WkrH,  g_WkrH);
    cudaGetSymbolAddress((void**)&WkrL,  g_WkrL);
    cudaGetSymbolAddress((void**)&WukH,  g_WukH);
    cudaGetSymbolAddress((void**)&WukL,  g_WukL);
    cudaGetSymbolAddress((void**)&WuvH,  g_WuvH);
    cudaGetSymbolAddress((void**)&WuvL,  g_WuvL);
    cudaGetSymbolAddress((void**)&WuqH,  g_WuqH);
    cudaGetSymbolAddress((void**)&WuqL,  g_WuqL);
    cudaGetSymbolAddress((void**)&WqrH,  g_WqrH);
    cudaGetSymbolAddress((void**)&WqrL,  g_WqrL);
    cudaGetSymbolAddress((void**)&WfcH,  g_WfcH);
    cudaGetSymbolAddress((void**)&WfcL,  g_WfcL);
    cudaGetSymbolAddress((void**)&QPH,   g_QPH);
    cudaGetSymbolAddress((void**)&QPL,   g_QPL);
    cudaGetSymbolAddress((void**)&KPH,   g_KPH);
    cudaGetSymbolAddress((void**)&KPL,   g_KPL);
    cudaGetSymbolAddress((void**)&VPH,   g_VPH);
    cudaGetSymbolAddress((void**)&VPL,   g_VPL);

    cudaFuncSetAttribute(attn2_kernel,
                         cudaFuncAttributeMaxDynamicSharedMemorySize, ATTN2_SMEM);
    cudaFuncSetAttribute(tgemm_kernel,
                         cudaFuncAttributeMaxDynamicSharedMemorySize, GT_SMEM);

    // splits: activations + weights
    split(h,    hH,    hL,    TOK * DMODEL);
    split(Wdkv, WdkvH, WdkvL, DOWND * DMODEL);
    split(Wdq,  WdqH,  WdqL,  DOWND * DMODEL);
    split(Wkr,  WkrH,  WkrL,  RDIM * DMODEL);
    split(Wuk,  WukH,  WukL,  UPDIM * DOWND);
    split(Wuv,  WuvH,  WuvL,  UPDIM * DOWND);
    split(Wuq,  WuqH,  WuqL,  UPDIM * DOWND);
    split(Wqr,  WqrH,  WqrL,  UPDIM * DOWND);
    split(Wfc,  WfcH,  WfcL,  DMODEL * UPDIM);

    dim3 blk(256);
    // down projections + decoupled k rope projection
    tgemm_kernel<<<dim3(DOWND / 128, TOK / 128), blk, GT_SMEM>>>(hH, hL, WdkvH, WdkvL, bdkv, ckv, DOWND, DMODEL);
    tgemm_kernel<<<dim3(DOWND / 128, TOK / 128), blk, GT_SMEM>>>(hH, hL, WdqH,  WdqL,  bdq,  cq,  DOWND, DMODEL);
    tgemm_kernel<<<dim3(1,           TOK / 128), blk, GT_SMEM>>>(hH, hL, WkrH,  WkrL,  bkr,  kr,  RDIM,  DMODEL);

    split(ckv, ckvH, ckvL, TOK * DOWND);
    split(cq,  cqH,  cqL,  TOK * DOWND);

    // up projections
    tgemm_kernel<<<dim3(UPDIM / 128, TOK / 128), blk, GT_SMEM>>>(ckvH, ckvL, WukH, WukL, buk, kc, UPDIM, DOWND);
    tgemm_kernel<<<dim3(UPDIM / 128, TOK / 128), blk, GT_SMEM>>>(ckvH, ckvL, WuvH, WuvL, buv, vc, UPDIM, DOWND);
    tgemm_kernel<<<dim3(UPDIM / 128, TOK / 128), blk, GT_SMEM>>>(cqH,  cqL,  WuqH, WuqL, buq, qc, UPDIM, DOWND);
    tgemm_kernel<<<dim3(UPDIM / 128, TOK / 128), blk, GT_SMEM>>>(cqH,  cqL,  WqrH, WqrL, bqr, qr, UPDIM, DOWND);

    // pack (rope fused) + attention
    qpack_kernel<<<NBH * SEQLEN * 64 / 256, 256>>>(qc, qr, QPH, QPL);
    kpack_kernel<<<NBH * SEQLEN * 64 / 256, 256>>>(kc, kr, KPH, KPL);
    vpack_kernel<<<NBH * SEQLEN * 32 / 256, 256>>>(vc, VPH, VPL);
    attn2_kernel<<<dim3(SEQLEN / 64, NHEADS, BATCH), blk, ATTN2_SMEM>>>(
        QPH, QPL, KPH, KPL, VPH, VPL, ao);

    // output projection
    split(ao, aoH, aoL, TOK * UPDIM);
    tgemm_kernel<<<dim3(DMODEL / 128, TOK / 128), blk, GT_SMEM>>>(aoH, aoL, WfcH, WfcL, bfc, out, DMODEL, UPDIM);
}

// round 8
// speedup vs baseline: 3.6253x; 1.4483x over previous
#include <cuda_runtime.h>
#include <cuda_fp16.h>
#include <math.h>
#include <cstdint>

// ===========================================================================
// MLA attention. All GEMMs + attention via mma.sync fp16 2-pass split
// (A = Ah+Al fp16 pair, B single fp16; fp32 accum). RoPE fused into packs.
// GEMMs double-buffered with cp.async. Splits fused into epilogues.
// ===========================================================================

#define TOK    8192
#define SEQLEN 512
#define DMODEL 2048
#define DOWND  512
#define UPDIM  1024
#define NHEADS 16
#define RDIM   64
#define BATCH  16
#define NBH    (BATCH * NHEADS)

// ------------------------------ scratch ------------------------------------
__device__ float g_kc [TOK * UPDIM];
__device__ float g_vc [TOK * UPDIM];
__device__ float g_qc [TOK * UPDIM];
__device__ float g_qr [TOK * UPDIM];
__device__ float g_kr [TOK * RDIM];

__device__ __half g_hH [TOK * DMODEL];
__device__ __half g_hL [TOK * DMODEL];
__device__ __half g_ckvH[TOK * DOWND];
__device__ __half g_ckvL[TOK * DOWND];
__device__ __half g_cqH [TOK * DOWND];
__device__ __half g_cqL [TOK * DOWND];
__device__ __half g_aoH [TOK * UPDIM];
__device__ __half g_aoL [TOK * UPDIM];

__device__ __half g_Wdkv16[DOWND * DMODEL];
__device__ __half g_Wdq16 [DOWND * DMODEL];
__device__ __half g_Wkr16 [RDIM * DMODEL];
__device__ __half g_Wuk16 [UPDIM * DOWND];
__device__ __half g_Wuv16 [UPDIM * DOWND];
__device__ __half g_Wuq16 [UPDIM * DOWND];
__device__ __half g_Wqr16 [UPDIM * DOWND];
__device__ __half g_Wfc16 [DMODEL * UPDIM];

// packed attention operands
__device__ __half g_QPH[NBH * SEQLEN * 128];
__device__ __half g_QPL[NBH * SEQLEN * 128];
__device__ __half g_KPH[NBH * SEQLEN * 128];
__device__ __half g_VPH[NBH * SEQLEN * 64];

// ------------------------------ helpers ------------------------------------
__device__ __forceinline__ uint32_t smem_u32(const void* p) {
    uint32_t a;
    asm("{ .reg .u64 t; cvta.to.shared.u64 t, %1; cvt.u32.u64 %0, t; }"
        : "=r"(a) : "l"(p));
    return a;
}
__device__ __forceinline__ void ldsm_x4(uint32_t& r0, uint32_t& r1,
                                        uint32_t& r2, uint32_t& r3,
                                        uint32_t addr) {
    asm volatile("ldmatrix.sync.aligned.m8n8.x4.shared.b16 {%0,%1,%2,%3}, [%4];"
                 : "=r"(r0), "=r"(r1), "=r"(r2), "=r"(r3) : "r"(addr));
}
__device__ __forceinline__ void ldsm_x2(uint32_t& r0, uint32_t& r1,
                                        uint32_t addr) {
    asm volatile("ldmatrix.sync.aligned.m8n8.x2.shared.b16 {%0,%1}, [%2];"
                 : "=r"(r0), "=r"(r1) : "r"(addr));
}
__device__ __forceinline__ void mma16816(float* c, const uint32_t* a,
                                         const uint32_t* b) {
    asm volatile(
        "mma.sync.aligned.m16n8k16.row.col.f32.f16.f16.f32 "
        "{%0,%1,%2,%3}, {%4,%5,%6,%7}, {%8,%9}, {%0,%1,%2,%3};"
        : "+f"(c[0]), "+f"(c[1]), "+f"(c[2]), "+f"(c[3])
        : "r"(a[0]), "r"(a[1]), "r"(a[2]), "r"(a[3]), "r"(b[0]), "r"(b[1]));
}
__device__ __forceinline__ void cp16(uint32_t dst, const void* src, int nbytes) {
    asm volatile("cp.async.cg.shared.global [%0], [%1], 16, %2;"
                 :: "r"(dst), "l"(src), "r"(nbytes));
}
__device__ __forceinline__ void cp_commit() {
    asm volatile("cp.async.commit_group;");
}
template <int N> __device__ __forceinline__ void cp_wait() {
    asm volatile("cp.async.wait_group %0;" :: "n"(N));
}
__device__ __forceinline__ void splt_h(float v, __half& h, __half& l) {
    h = __float2half_rn(v);
    l = __float2half_rn(v - __half2float(h));
}
__device__ __forceinline__ void f2_hilo_h(float2 f, uint32_t& h, uint32_t& l) {
    __half2 hb = __floats2half2_rn(f.x, f.y);
    float rx = f.x - __low2float(hb);
    float ry = f.y - __high2float(hb);
    __half2 lb = __floats2half2_rn(rx, ry);
    h = *(uint32_t*)&hb;
    l = *(uint32_t*)&lb;
}

// ------------------------------ prep kernels -------------------------------
__global__ void split_kernel(const float* __restrict__ x,
                             __half* __restrict__ hi,
                             __half* __restrict__ lo, int n2)
{
    int i = blockIdx.x * blockDim.x + threadIdx.x;
    if (i >= n2) return;
    float2 v = *(const float2*)(x + i * 2);
    __half2 hb = __floats2half2_rn(v.x, v.y);
    float rx = v.x - __low2float(hb);
    float ry = v.y - __high2float(hb);
    __half2 lb = __floats2half2_rn(rx, ry);
    *(__half2*)(hi + i * 2) = hb;
    *(__half2*)(lo + i * 2) = lb;
}

__global__ void wconv_kernel(const float* __restrict__ x,
                             __half* __restrict__ w16, int n2)
{
    int i = blockIdx.x * blockDim.x + threadIdx.x;
    if (i >= n2) return;
    float2 v = *(const float2*)(x + i * 2);
    *(__half2*)(w16 + i * 2) = __floats2half2_rn(v.x, v.y);
}

// ------------------------------ tensor GEMM --------------------------------
// C(M,N) = (Ah+Al)(M,K) @ Bh^T(N,K) + bias.  CTA 128x128, K-chunk 32,
// 8 warps, warp tile 64x32, 2-stage cp.async double buffer, 2 MMA passes.
// Outputs: fp32 C (if non-null) and/or fp16 hi/lo CH/CL (if non-null).
#define ROWB 80
#define TILEB (128 * ROWB)
#define STAGEB (3 * TILEB)
#define GT_SMEM (2 * STAGEB)

__global__ __launch_bounds__(256)
void tgemm_kernel(const __half* __restrict__ Ah,
                  const __half* __restrict__ Al,
                  const __half* __restrict__ Bh,
                  const float* __restrict__ bias,
                  float* __restrict__ C,
                  __half* __restrict__ CH,
                  __half* __restrict__ CL,
                  int N, int K)
{
    extern __shared__ __align__(16) char smem[];

    const int tid  = threadIdx.x;
    const int wid  = tid >> 5;
    const int lane = tid & 31;
    const int wm   = wid >> 2;
    const int wn   = wid & 3;
    const int m0   = blockIdx.y * 128;
    const int n0   = blockIdx.x * 128;
    const uint32_t sb = smem_u32(smem);

    const __half* srcs[3] = {Ah, Al, Bh};

    const int lrow0 = tid >> 2;
    const int lq0   = tid & 3;
    const int lrow1 = (tid + 256) >> 2;
    const int lq1   = (tid + 256) & 3;

    float acc[4][4][4];
#pragma unroll
    for (int i = 0; i < 4; i++)
#pragma unroll
        for (int j = 0; j < 4; j++)
#pragma unroll
            for (int v = 0; v < 4; v++) acc[i][j][v] = 0.0f;

    const int r16   = lane & 15;
    const int khalfA = (lane >> 4) * 16;
    const int r8    = lane & 7;
    const int khalfB = ((lane >> 3) & 1) * 16;

    const int nchunks = K >> 5;

    // issue chunk 0 into stage 0
    {
#pragma unroll
        for (int t = 0; t < 3; t++) {
            const bool isB = (t == 2);
            const __half* src = srcs[t];
            {
                int grow = isB ? (n0 + lrow0) : (m0 + lrow0);
                int ok = (!isB || grow < N) ? 16 : 0;
                if (!ok) grow = n0;
                cp16(sb + t * TILEB + lrow0 * ROWB + lq0 * 16,
                     src + (size_t)grow * K + lq0 * 8, ok);
            }
            {
                int grow = isB ? (n0 + lrow1) : (m0 + lrow1);
                int ok = (!isB || grow < N) ? 16 : 0;
                if (!ok) grow = n0;
                cp16(sb + t * TILEB + lrow1 * ROWB + lq1 * 16,
                     src + (size_t)grow * K + lq1 * 8, ok);
            }
        }
        cp_commit();
    }

    for (int ci = 0; ci < nchunks; ci++) {
        const uint32_t cur = sb + (uint32_t)(ci & 1) * STAGEB;

        if (ci + 1 < nchunks) {
            const int k0 = (ci + 1) << 5;
            const uint32_t nxt = sb + (uint32_t)((ci + 1) & 1) * STAGEB;
#pragma unroll
            for (int t = 0; t < 3; t++) {
                const bool isB = (t == 2);
                const __half* src = srcs[t];
                {
                    int grow = isB ? (n0 + lrow0) : (m0 + lrow0);
                    int ok = (!isB || grow < N) ? 16 : 0;
                    if (!ok) grow = n0;
                    cp16(nxt + t * TILEB + lrow0 * ROWB + lq0 * 16,
                         src + (size_t)grow * K + k0 + lq0 * 8, ok);
                }
                {
                    int grow = isB ? (n0 + lrow1) : (m0 + lrow1);
                    int ok = (!isB || grow < N) ? 16 : 0;
                    if (!ok) grow = n0;
                    cp16(nxt + t * TILEB + lrow1 * ROWB + lq1 * 16,
                         src + (size_t)grow * K + k0 + lq1 * 8, ok);
                }
            }
            cp_commit();
            cp_wait<1>();
        } else {
            cp_wait<0>();
        }
        __syncthreads();

#pragma unroll
        for (int ks = 0; ks < 2; ks++) {
            const int kb = ks * 32;
            uint32_t ah[4][4], al[4][4], bh[4][2];
#pragma unroll
            for (int mi = 0; mi < 4; mi++)
                ldsm_x4(ah[mi][0], ah[mi][1], ah[mi][2], ah[mi][3],
                        cur + 0 * TILEB + (wm * 64 + mi * 16 + r16) * ROWB + kb + khalfA);
#pragma unroll
            for (int ni = 0; ni < 4; ni++)
                ldsm_x2(bh[ni][0], bh[ni][1],
                        cur + 2 * TILEB + (wn * 32 + ni * 8 + r8) * ROWB + kb + khalfB);
#pragma unroll
            for (int mi = 0; mi < 4; mi++)
#pragma unroll
                for (int ni = 0; ni < 4; ni++)
                    mma16816(acc[mi][ni], ah[mi], bh[ni]);

#pragma unroll
            for (int mi = 0; mi < 4; mi++)
                ldsm_x4(al[mi][0], al[mi][1], al[mi][2], al[mi][3],
                        cur + 1 * TILEB + (wm * 64 + mi * 16 + r16) * ROWB + kb + khalfA);
#pragma unroll
            for (int mi = 0; mi < 4; mi++)
#pragma unroll
                for (int ni = 0; ni < 4; ni++)
                    mma16816(acc[mi][ni], al[mi], bh[ni]);
        }
        __syncthreads();
    }

#pragma unroll
    for (int mi = 0; mi < 4; mi++) {
        int row0 = m0 + wm * 64 + mi * 16 + (lane >> 2);
#pragma unroll
        for (int ni = 0; ni < 4; ni++) {
            int col = n0 + wn * 32 + ni * 8 + 2 * (lane & 3);
            if (col < N) {
                float2 b2 = *(const float2*)(bias + col);
                float v00 = acc[mi][ni][0] + b2.x, v01 = acc[mi][ni][1] + b2.y;
                float v10 = acc[mi][ni][2] + b2.x, v11 = acc[mi][ni][3] + b2.y;
                if (C) {
                    *(float2*)(C + (size_t)row0 * N + col) = make_float2(v00, v01);
                    *(float2*)(C + (size_t)(row0 + 8) * N + col) = make_float2(v10, v11);
                }
                if (CH) {
                    __half2 h0 = __floats2half2_rn(v00, v01);
                    __half2 l0 = __floats2half2_rn(v00 - __low2float(h0),
                                                   v01 - __high2float(h0));
                    __half2 h1 = __floats2half2_rn(v10, v11);
                    __half2 l1 = __floats2half2_rn(v10 - __low2float(h1),
                                                   v11 - __high2float(h1));
                    *(__half2*)(CH + (size_t)row0 * N + col) = h0;
                    *(__half2*)(CL + (size_t)row0 * N + col) = l0;
                    *(__half2*)(CH + (size_t)(row0 + 8) * N + col) = h1;
                    *(__half2*)(CL + (size_t)(row0 + 8) * N + col) = l1;
                }
            }
        }
    }
}

// ------------------------------ pack kernels (rope fused) ------------------
__global__ void qpack_kernel(const float* __restrict__ qc,
                             const float* __restrict__ qr,
                             __half* __restrict__ PH,
                             __half* __restrict__ PL)
{
    int idx = blockIdx.x * 256 + threadIdx.x;
    int d2 = idx & 63;
    int s  = (idx >> 6) & (SEQLEN - 1);
    int bh = idx >> 15;
    int h = bh & (NHEADS - 1), b = bh >> 4;
    int tok = b * SEQLEN + s;
    float f0, f1;
    int dd;
    if (d2 < 32) {
        dd = d2 * 2;
        float2 v = *(const float2*)(qc + (size_t)tok * UPDIM + h * 64 + dd);
        f0 = v.x; f1 = v.y;
    } else {
        int pair = d2 - 32;
        int rp = pair * 2;
        float2 v = *(const float2*)(qr + (size_t)tok * UPDIM + h * 64 + rp);
        float theta = powf(10000.0f, -(float)pair * (1.0f / 32.0f));
        float sn, cs;
        sincosf((float)s * theta, &sn, &cs);
        f0 = v.x * sn - v.y * cs;
        f1 = v.y * sn + v.x * cs;
        dd = 64 + rp;
    }
    size_t base = ((size_t)bh * SEQLEN + s) * 128 + dd;
    splt_h(f0, PH[base], PL[base]);
    splt_h(f1, PH[base + 1], PL[base + 1]);
}

__global__ void kpack_kernel(const float* __restrict__ kc,
                             const float* __restrict__ kr,
                             __half* __restrict__ PH)
{
    int idx = blockIdx.x * 256 + threadIdx.x;
    int d2 = idx & 63;
    int s  = (idx >> 6) & (SEQLEN - 1);
    int bh = idx >> 15;
    int h = bh & (NHEADS - 1), b = bh >> 4;
    int tok = b * SEQLEN + s;
    float f0, f1;
    int dd;
    if (d2 < 32) {
        dd = d2 * 2;
        float2 v = *(const float2*)(kc + (size_t)tok * UPDIM + h * 64 + dd);
        f0 = v.x; f1 = v.y;
    } else {
        int pair = d2 - 32;
        int rp = pair * 2;
        float2 v = *(const float2*)(kr + (size_t)tok * RDIM + rp);
        float theta = powf(10000.0f, -(float)pair * (1.0f / 32.0f));
        float sn, cs;
        sincosf((float)s * theta, &sn, &cs);
        f0 = v.x * sn - v.y * cs;
        f1 = v.y * sn + v.x * cs;
        dd = 64 + rp;
    }
    size_t base = ((size_t)bh * SEQLEN + s) * 128 + dd;
    *(__half2*)(PH + base) = __floats2half2_rn(f0, f1);
}

__global__ void vpack_kernel(const float* __restrict__ vc,
                             __half* __restrict__ PH)
{
    int idx = blockIdx.x * 256 + threadIdx.x;
    int d2 = idx & 31;
    int s  = (idx >> 5) & (SEQLEN - 1);
    int bh = idx >> 14;
    int h = bh & (NHEADS - 1), b = bh >> 4;
    int tok = b * SEQLEN + s;
    int dd = d2 * 2;
    float2 v = *(const float2*)(vc + (size_t)tok * UPDIM + h * 64 + dd);
    size_t base = ((size_t)bh * SEQLEN + s) * 64 + dd;
    *(__half2*)(PH + base) = __floats2half2_rn(v.x, v.y);
}

// ------------------------------ attention ----------------------------------
#define QPITCH 272
#define VPITCH 144
#define SPITCH 516
#define OFF_QH 0
#define OFF_QL 17408
#define OFF_KH 34816
#define OFF_VH 34816
#define OFF_S  52224
#define ATTN2_SMEM (OFF_S + 64 * SPITCH * 4)

__global__ __launch_bounds__(256)
void attn2_kernel(const __half* __restrict__ QPH,
                  const __half* __restrict__ QPL,
                  const __half* __restrict__ KPH,
                  const __half* __restrict__ VPH,
                  __half* __restrict__ aoH,
                  __half* __restrict__ aoL)
{
    extern __shared__ char sm2[];
    const uint32_t sb = smem_u32(sm2);
    float* Ssf = (float*)(sm2 + OFF_S);

    const int tid  = threadIdx.x;
    const int wid  = tid >> 5;
    const int lane = tid & 31;
    const int wm = wid >> 2;
    const int wn = wid & 3;
    const int q0 = blockIdx.x * 64;
    const int hh = blockIdx.y;
    const int b  = blockIdx.z;
    const int bh = b * NHEADS + hh;
    const size_t pbase = (size_t)bh * SEQLEN * 128;
    const float scale = 0.07216878364870322f;

    const int r16 = lane & 15;
    const int khalfA = (lane >> 4) * 16;
    const int r8 = lane & 7;
    const int khalfB = ((lane >> 3) & 1) * 16;

#pragma unroll
    for (int j = 0; j < 4; j++) {
        int idx = tid + j * 256;
        int row = idx >> 4, c = idx & 15;
        size_t g = pbase + (size_t)(q0 + row) * 128 + c * 8;
        *(uint4*)(sm2 + OFF_QH + row * QPITCH + c * 16) = *(const uint4*)(QPH + g);
        *(uint4*)(sm2 + OFF_QL + row * QPITCH + c * 16) = *(const uint4*)(QPL + g);
    }

    for (int kt = 0; kt < 8; kt++) {
        __syncthreads();
#pragma unroll
        for (int j = 0; j < 4; j++) {
            int idx = tid + j * 256;
            int row = idx >> 4, c = idx & 15;
            size_t g = pbase + (size_t)(kt * 64 + row) * 128 + c * 8;
            *(uint4*)(sm2 + OFF_KH + row * QPITCH + c * 16) = *(const uint4*)(KPH + g);
        }
        __syncthreads();

        float acc[2][2][4];
#pragma unroll
        for (int mi = 0; mi < 2; mi++)
#pragma unroll
            for (int ni = 0; ni < 2; ni++)
#pragma unroll
                for (int v = 0; v < 4; v++) acc[mi][ni][v] = 0.0f;

#pragma unroll
        for (int ks = 0; ks < 8; ks++) {
            const int kb = ks * 32;
            uint32_t ah[2][4], al[2][4], bhf[2][2];
#pragma unroll
            for (int mi = 0; mi < 2; mi++)
                ldsm_x4(ah[mi][0], ah[mi][1], ah[mi][2], ah[mi][3],
                        sb + OFF_QH + (wm * 32 + mi * 16 + r16) * QPITCH + kb + khalfA);
#pragma unroll
            for (int ni = 0; ni < 2; ni++)
                ldsm_x2(bhf[ni][0], bhf[ni][1],
                        sb + OFF_KH + (wn * 16 + ni * 8 + r8) * QPITCH + kb + khalfB);
#pragma unroll
            for (int mi = 0; mi < 2; mi++)
#pragma unroll
                for (int ni = 0; ni < 2; ni++)
                    mma16816(acc[mi][ni], ah[mi], bhf[ni]);
#pragma unroll
            for (int mi = 0; mi < 2; mi++)
                ldsm_x4(al[mi][0], al[mi][1], al[mi][2], al[mi][3],
                        sb + OFF_QL + (wm * 32 + mi * 16 + r16) * QPITCH + kb + khalfA);
#pragma unroll
            for (int mi = 0; mi < 2; mi++)
#pragma unroll
                for (int ni = 0; ni < 2; ni++)
                    mma16816(acc[mi][ni], al[mi], bhf[ni]);
        }

#pragma unroll
        for (int mi = 0; mi < 2; mi++) {
            int row = wm * 32 + mi * 16 + (lane >> 2);
#pragma unroll
            for (int ni = 0; ni < 2; ni++) {
                int col = kt * 64 + wn * 16 + ni * 8 + 2 * (lane & 3);
                Ssf[row * SPITCH + col]           = acc[mi][ni][0] * scale;
                Ssf[row * SPITCH + col + 1]       = acc[mi][ni][1] * scale;
                Ssf[(row + 8) * SPITCH + col]     = acc[mi][ni][2] * scale;
                Ssf[(row + 8) * SPITCH + col + 1] = acc[mi][ni][3] * scale;
            }
        }
    }
    __syncthreads();

    {
        int row  = tid >> 2;
        int part = tid & 3;
        float* srow = Ssf + row * SPITCH;
        float mx = -1e30f;
#pragma unroll 4
        for (int k2 = 0; k2 < 128; k2++)
            mx = fmaxf(mx, srow[part + k2 * 4]);
        mx = fmaxf(mx, __shfl_xor_sync(0xffffffffu, mx, 1));
        mx = fmaxf(mx, __shfl_xor_sync(0xffffffffu, mx, 2));
        float sum = 0.0f;
#pragma unroll 4
        for (int k2 = 0; k2 < 128; k2++) {
            float e = __expf(srow[part + k2 * 4] - mx);
            srow[part + k2 * 4] = e;
            sum += e;
        }
        sum += __shfl_xor_sync(0xffffffffu, sum, 1);
        sum += __shfl_xor_sync(0xffffffffu, sum, 2);
        float inv = 1.0f / sum;
#pragma unroll 4
        for (int k2 = 0; k2 < 128; k2++)
            srow[part + k2 * 4] *= inv;
    }

    float accO[2][2][4];
#pragma unroll
    for (int mi = 0; mi < 2; mi++)
#pragma unroll
        for (int ni = 0; ni < 2; ni++)
#pragma unroll
            for (int v = 0; v < 4; v++) accO[mi][ni][v] = 0.0f;

    const size_t vbase = (size_t)bh * SEQLEN * 64;
    for (int kt = 0; kt < 8; kt++) {
        __syncthreads();
#pragma unroll
        for (int j = 0; j < 2; j++) {
            int idx = tid + j * 256;
            int key = idx >> 3, dg = idx & 7;
            size_t g = vbase + (size_t)(kt * 64 + key) * 64 + dg * 8;
            uint4 vh = *(const uint4*)(VPH + g);
            const uint16_t* ph = (const uint16_t*)&vh;
#pragma unroll
            for (int jj = 0; jj < 8; jj++)
                *(uint16_t*)(sm2 + OFF_VH + (dg * 8 + jj) * VPITCH + key * 2) = ph[jj];
        }
        __syncthreads();

#pragma unroll
        for (int ks = 0; ks < 4; ks++) {
            uint32_t ph_[2][4], pl_[2][4];
#pragma unroll
            for (int mi = 0; mi < 2; mi++) {
                int r  = wm * 32 + mi * 16 + (lane >> 2);
                int kc = kt * 64 + ks * 16 + 2 * (lane & 3);
                f2_hilo_h(*(float2*)&Ssf[r * SPITCH + kc],           ph_[mi][0], pl_[mi][0]);
                f2_hilo_h(*(float2*)&Ssf[(r + 8) * SPITCH + kc],     ph_[mi][1], pl_[mi][1]);
                f2_hilo_h(*(float2*)&Ssf[r * SPITCH + kc + 8],       ph_[mi][2], pl_[mi][2]);
                f2_hilo_h(*(float2*)&Ssf[(r + 8) * SPITCH + kc + 8], ph_[mi][3], pl_[mi][3]);
            }
            uint32_t vh_[2][2];
#pragma unroll
            for (int ni = 0; ni < 2; ni++) {
                uint32_t a = sb + OFF_VH + (wn * 16 + ni * 8 + r8) * VPITCH + ks * 32 + khalfB;
                ldsm_x2(vh_[ni][0], vh_[ni][1], a);
            }
#pragma unroll
            for (int mi = 0; mi < 2; mi++)
#pragma unroll
                for (int ni = 0; ni < 2; ni++) {
                    mma16816(accO[mi][ni], ph_[mi], vh_[ni]);
                    mma16816(accO[mi][ni], pl_[mi], vh_[ni]);
                }
        }
    }

#pragma unroll
    for (int mi = 0; mi < 2; mi++) {
        int rloc = wm * 32 + mi * 16 + (lane >> 2);
        int tok  = b * SEQLEN + q0 + rloc;
#pragma unroll
        for (int ni = 0; ni < 2; ni++) {
            int col = wn * 16 + ni * 8 + 2 * (lane & 3);
            float v00 = accO[mi][ni][0], v01 = accO[mi][ni][1];
            float v10 = accO[mi][ni][2], v11 = accO[mi][ni][3];
            __half2 h0 = __floats2half2_rn(v00, v01);
            __half2 l0 = __floats2half2_rn(v00 - __low2float(h0),
                                           v01 - __high2float(h0));
            __half2 h1 = __floats2half2_rn(v10, v11);
            __half2 l1 = __floats2half2_rn(v10 - __low2float(h1),
                                           v11 - __high2float(h1));
            *(__half2*)(aoH + (size_t)tok * UPDIM + hh * 64 + col) = h0;
            *(__half2*)(aoL + (size_t)tok * UPDIM + hh * 64 + col) = l0;
            *(__half2*)(aoH + (size_t)(tok + 8) * UPDIM + hh * 64 + col) = h1;
            *(__half2*)(aoL + (size_t)(tok + 8) * UPDIM + hh * 64 + col) = l1;
        }
    }
}

// ---------------------------------------------------------------------------
extern "C" void kernel_launch(void* const* d_in, const int* in_sizes, int n_in,
                              void* d_out, int out_size)
{
    const float* h    = (const float*)d_in[0];
    const float* Wdkv = (const float*)d_in[1];
    const float* bdkv = (const float*)d_in[2];
    const float* Wuk  = (const float*)d_in[3];
    const float* buk  = (const float*)d_in[4];
    const float* Wuv  = (const float*)d_in[5];
    const float* buv  = (const float*)d_in[6];
    const float* Wdq  = (const float*)d_in[7];
    const float* bdq  = (const float*)d_in[8];
    const float* Wuq  = (const float*)d_in[9];
    const float* buq  = (const float*)d_in[10];
    const float* Wqr  = (const float*)d_in[11];
    const float* bqr  = (const float*)d_in[12];
    const float* Wkr  = (const float*)d_in[13];
    const float* bkr  = (const float*)d_in[14];
    const float* Wfc  = (const float*)d_in[15];
    const float* bfc  = (const float*)d_in[16];
    float* out = (float*)d_out;

    float *kc, *vc, *qc, *qr, *kr;
    cudaGetSymbolAddress((void**)&kc,  g_kc);
    cudaGetSymbolAddress((void**)&vc,  g_vc);
    cudaGetSymbolAddress((void**)&qc,  g_qc);
    cudaGetSymbolAddress((void**)&qr,  g_qr);
    cudaGetSymbolAddress((void**)&kr,  g_kr);

    __half *hH, *hL, *ckvH, *ckvL, *cqH, *cqL, *aoH, *aoL;
    __half *Wdkv16, *Wdq16, *Wkr16, *Wuk16, *Wuv16, *Wuq16, *Wqr16, *Wfc16;
    __half *QPH, *QPL, *KPH, *VPH;
    cudaGetSymbolAddress((void**)&hH,     g_hH);
    cudaGetSymbolAddress((void**)&hL,     g_hL);
    cudaGetSymbolAddress((void**)&ckvH,   g_ckvH);
    cudaGetSymbolAddress((void**)&ckvL,   g_ckvL);
    cudaGetSymbolAddress((void**)&cqH,    g_cqH);
    cudaGetSymbolAddress((void**)&cqL,    g_cqL);
    cudaGetSymbolAddress((void**)&aoH,    g_aoH);
    cudaGetSymbolAddress((void**)&aoL,    g_aoL);
    cudaGetSymbolAddress((void**)&Wdkv16, g_Wdkv16);
    cudaGetSymbolAddress((void**)&Wdq16,  g_Wdq16);
    cudaGetSymbolAddress((void**)&Wkr16,  g_Wkr16);
    cudaGetSymbolAddress((void**)&Wuk16,  g_Wuk16);
    cudaGetSymbolAddress((void**)&Wuv16,  g_Wuv16);
    cudaGetSymbolAddress((void**)&Wuq16,  g_Wuq16);
    cudaGetSymbolAddress((void**)&Wqr16,  g_Wqr16);
    cudaGetSymbolAddress((void**)&Wfc16,  g_Wfc16);
    cudaGetSymbolAddress((void**)&QPH,    g_QPH);
    cudaGetSymbolAddress((void**)&QPL,    g_QPL);
    cudaGetSymbolAddress((void**)&KPH,    g_KPH);
    cudaGetSymbolAddress((void**)&VPH,    g_VPH);

    cudaFuncSetAttribute(attn2_kernel,
                         cudaFuncAttributeMaxDynamicSharedMemorySize, ATTN2_SMEM);
    cudaFuncSetAttribute(tgemm_kernel,
                         cudaFuncAttributeMaxDynamicSharedMemorySize, GT_SMEM);

    // prep: split h, convert weights to fp16
    split_kernel<<<TOK * DMODEL / 2 / 256, 256>>>(h, hH, hL, TOK * DMODEL / 2);
    wconv_kernel<<<DOWND * DMODEL / 2 / 256, 256>>>(Wdkv, Wdkv16, DOWND * DMODEL / 2);
    wconv_kernel<<<DOWND * DMODEL / 2 / 256, 256>>>(Wdq,  Wdq16,  DOWND * DMODEL / 2);
    wconv_kernel<<<RDIM * DMODEL / 2 / 256, 256>>>(Wkr,  Wkr16,  RDIM * DMODEL / 2);
    wconv_kernel<<<UPDIM * DOWND / 2 / 256, 256>>>(Wuk,  Wuk16,  UPDIM * DOWND / 2);
    wconv_kernel<<<UPDIM * DOWND / 2 / 256, 256>>>(Wuv,  Wuv16,  UPDIM * DOWND / 2);
    wconv_kernel<<<UPDIM * DOWND / 2 / 256, 256>>>(Wuq,  Wuq16,  UPDIM * DOWND / 2);
    wconv_kernel<<<UPDIM * DOWND / 2 / 256, 256>>>(Wqr,  Wqr16,  UPDIM * DOWND / 2);
    wconv_kernel<<<DMODEL * UPDIM / 2 / 256, 256>>>(Wfc, Wfc16, DMODEL * UPDIM / 2);

    dim3 blk(256);
    // down projections (fp16 hi/lo outputs) + decoupled k rope projection
    tgemm_kernel<<<dim3(DOWND / 128, TOK / 128), blk, GT_SMEM>>>(
        hH, hL, Wdkv16, bdkv, nullptr, ckvH, ckvL, DOWND, DMODEL);
    tgemm_kernel<<<dim3(DOWND / 128, TOK / 128), blk, GT_SMEM>>>(
        hH, hL, Wdq16, bdq, nullptr, cqH, cqL, DOWND, DMODEL);
    tgemm_kernel<<<dim3(1, TOK / 128), blk, GT_SMEM>>>(
        hH, hL, Wkr16, bkr, kr, nullptr, nullptr, RDIM, DMODEL);

    // up projections (fp32 outputs for packs)
    tgemm_kernel<<<dim3(UPDIM / 128, TOK / 128), blk, GT_SMEM>>>(
        ckvH, ckvL, Wuk16, buk, kc, nullptr, nullptr, UPDIM, DOWND);
    tgemm_kernel<<<dim3(UPDIM / 128, TOK / 128), blk, GT_SMEM>>>(
        ckvH, ckvL, Wuv16, buv, vc, nullptr, nullptr, UPDIM, DOWND);
    tgemm_kernel<<<dim3(UPDIM / 128, TOK / 128), blk, GT_SMEM>>>(
        cqH, cqL, Wuq16, buq, qc, nullptr, nullptr, UPDIM, DOWND);
    tgemm_kernel<<<dim3(UPDIM / 128, TOK / 128), blk, GT_SMEM>>>(
        cqH, cqL, Wqr16, bqr, qr, nullptr, nullptr, UPDIM, DOWND);

    // pack (rope fused) + attention
    qpack_kernel<<<NBH * SEQLEN * 64 / 256, 256>>>(qc, qr, QPH, QPL);
    kpack_kernel<<<NBH * SEQLEN * 64 / 256, 256>>>(kc, kr, KPH);
    vpack_kernel<<<NBH * SEQLEN * 32 / 256, 256>>>(vc, VPH);
    attn2_kernel<<<dim3(SEQLEN / 64, NHEADS, BATCH), blk, ATTN2_SMEM>>>(
        QPH, QPL, KPH, VPH, aoH, aoL);

    // output projection (fp32 out)
    tgemm_kernel<<<dim3(DMODEL / 128, TOK / 128), blk, GT_SMEM>>>(
        aoH, aoL, Wfc16, bfc, out, nullptr, nullptr, DMODEL, UPDIM);
}

// round 11
// speedup vs baseline: 3.9979x; 1.1028x over previous
#include <cuda_runtime.h>
#include <cuda_fp16.h>
#include <math.h>
#include <cstdint>

// ===========================================================================
// MLA attention. All GEMMs + attention via mma.sync fp16 2-pass split
// (A = Ah+Al fp16 pair, B single fp16; fp32 accum). GEMMs fused along N:
//   down: N=1088 (Wdkv|Wdq|Wkr) -> fp16 hi/lo combined c-buffer
//   up:   N=2048 (Wuk|Wuv) -> kv fp32 ; N=2048 (Wuq|Wqr) -> qq fp32
// RoPE fused into packs. cp.async double buffer.
// ===========================================================================

#define TOK    8192
#define SEQLEN 512
#define DMODEL 2048
#define DOWND  512
#define UPDIM  1024
#define NHEADS 16
#define RDIM   64
#define BATCH  16
#define NBH    (BATCH * NHEADS)
#define NDOWN  1088          // 512 ckv | 512 cq | 64 kr

// ------------------------------ scratch ------------------------------------
__device__ __half g_hH [TOK * DMODEL];
__device__ __half g_hL [TOK * DMODEL];
__device__ __half g_cH [TOK * NDOWN];
__device__ __half g_cL [TOK * NDOWN];
__device__ float  g_kv [TOK * 2048];    // k_c | v_c
__device__ float  g_qq [TOK * 2048];    // q_c | q_r
__device__ __half g_aoH[TOK * UPDIM];
__device__ __half g_aoL[TOK * UPDIM];

__device__ __half g_Wdown16[NDOWN * DMODEL];
__device__ __half g_Wkv16  [2048 * DOWND];
__device__ __half g_Wqq16  [2048 * DOWND];
__device__ __half g_Wfc16  [DMODEL * UPDIM];
__device__ float  g_bdown[NDOWN];
__device__ float  g_bkv  [2048];
__device__ float  g_bqq  [2048];

__device__ __half g_QPH[NBH * SEQLEN * 128];
__device__ __half g_QPL[NBH * SEQLEN * 128];
__device__ __half g_KPH[NBH * SEQLEN * 128];
__device__ __half g_VPH[NBH * SEQLEN * 64];

// ------------------------------ helpers ------------------------------------
__device__ __forceinline__ uint32_t smem_u32(const void* p) {
    uint32_t a;
    asm("{ .reg .u64 t; cvta.to.shared.u64 t, %1; cvt.u32.u64 %0, t; }"
        : "=r"(a) : "l"(p));
    return a;
}
__device__ __forceinline__ void ldsm_x4(uint32_t& r0, uint32_t& r1,
                                        uint32_t& r2, uint32_t& r3,
                                        uint32_t addr) {
    asm volatile("ldmatrix.sync.aligned.m8n8.x4.shared.b16 {%0,%1,%2,%3}, [%4];"
                 : "=r"(r0), "=r"(r1), "=r"(r2), "=r"(r3) : "r"(addr));
}
__device__ __forceinline__ void ldsm_x2(uint32_t& r0, uint32_t& r1,
                                        uint32_t addr) {
    asm volatile("ldmatrix.sync.aligned.m8n8.x2.shared.b16 {%0,%1}, [%2];"
                 : "=r"(r0), "=r"(r1) : "r"(addr));
}
__device__ __forceinline__ void mma16816(float* c, const uint32_t* a,
                                         const uint32_t* b) {
    asm volatile(
        "mma.sync.aligned.m16n8k16.row.col.f32.f16.f16.f32 "
        "{%0,%1,%2,%3}, {%4,%5,%6,%7}, {%8,%9}, {%0,%1,%2,%3};"
        : "+f"(c[0]), "+f"(c[1]), "+f"(c[2]), "+f"(c[3])
        : "r"(a[0]), "r"(a[1]), "r"(a[2]), "r"(a[3]), "r"(b[0]), "r"(b[1]));
}
__device__ __forceinline__ void cp16(uint32_t dst, const void* src, int nbytes) {
    asm volatile("cp.async.cg.shared.global [%0], [%1], 16, %2;"
                 :: "r"(dst), "l"(src), "r"(nbytes));
}
__device__ __forceinline__ void cp_commit() {
    asm volatile("cp.async.commit_group;");
}
template <int N> __device__ __forceinline__ void cp_wait() {
    asm volatile("cp.async.wait_group %0;" :: "n"(N));
}
__device__ __forceinline__ void splt_h(float v, __half& h, __half& l) {
    h = __float2half_rn(v);
    l = __float2half_rn(v - __half2float(h));
}
__device__ __forceinline__ void f2_hilo_h(float2 f, uint32_t& h, uint32_t& l) {
    __half2 hb = __floats2half2_rn(f.x, f.y);
    float rx = f.x - __low2float(hb);
    float ry = f.y - __high2float(hb);
    __half2 lb = __floats2half2_rn(rx, ry);
    h = *(uint32_t*)&hb;
    l = *(uint32_t*)&lb;
}

// ------------------------------ prep kernels -------------------------------
__global__ void split_kernel(const float* __restrict__ x,
                             __half* __restrict__ hi,
                             __half* __restrict__ lo, int n2)
{
    int i = blockIdx.x * blockDim.x + threadIdx.x;
    if (i >= n2) return;
    float2 v = *(const float2*)(x + i * 2);
    __half2 hb = __floats2half2_rn(v.x, v.y);
    float rx = v.x - __low2float(hb);
    float ry = v.y - __high2float(hb);
    __half2 lb = __floats2half2_rn(rx, ry);
    *(__half2*)(hi + i * 2) = hb;
    *(__half2*)(lo + i * 2) = lb;
}

// all weight conversions in one kernel; segment boundaries in float2 units
#define WB0 524288u   // Wdkv 512x2048
#define WB1 1048576u  // Wdq
#define WB2 1114112u  // Wkr 64x2048
#define WB3 1376256u  // Wuk 1024x512
#define WB4 1638400u  // Wuv
#define WB5 1900544u  // Wuq
#define WB6 2162688u  // Wqr
#define WB7 3211264u  // Wfc 2048x1024

__global__ void wconv_all_kernel(const float* __restrict__ Wdkv,
                                 const float* __restrict__ Wdq,
                                 const float* __restrict__ Wkr,
                                 const float* __restrict__ Wuk,
                                 const float* __restrict__ Wuv,
                                 const float* __restrict__ Wuq,
                                 const float* __restrict__ Wqr,
                                 const float* __restrict__ Wfc,
                                 __half* __restrict__ Wdown16,
                                 __half* __restrict__ Wkv16,
                                 __half* __restrict__ Wqq16,
                                 __half* __restrict__ Wfc16)
{
    uint32_t i = blockIdx.x * 256u + threadIdx.x;
    if (i >= WB7) return;
    const float* src;
    __half* dst;
    uint32_t o;
    if (i < WB1) {
        if (i < WB0) { src = Wdkv; o = i;        dst = Wdown16; }
        else         { src = Wdq;  o = i - WB0;  dst = Wdown16 + 1048576u; }
    } else if (i < WB3) {
        if (i < WB2) { src = Wkr;  o = i - WB1;  dst = Wdown16 + 2097152u; }
        else         { src = Wuk;  o = i - WB2;  dst = Wkv16; }
    } else if (i < WB5) {
        if (i < WB4) { src = Wuv;  o = i - WB3;  dst = Wkv16 + 524288u; }
        else         { src = Wuq;  o = i - WB4;  dst = Wqq16; }
    } else {
        if (i < WB6) { src = Wqr;  o = i - WB5;  dst = Wqq16 + 524288u; }
        else         { src = Wfc;  o = i - WB6;  dst = Wfc16; }
    }
    float2 v = *(const float2*)(src + (size_t)o * 2);
    *(__half2*)(dst + (size_t)o * 2) = __floats2half2_rn(v.x, v.y);
}

__global__ void bias_concat_kernel(const float* __restrict__ bdkv,
                                   const float* __restrict__ bdq,
                                   const float* __restrict__ bkr,
                                   const float* __restrict__ buk,
                                   const float* __restrict__ buv,
                                   const float* __restrict__ buq,
                                   const float* __restrict__ bqr,
                                   float* __restrict__ bdown,
                                   float* __restrict__ bkv,
                                   float* __restrict__ bqq)
{
    int i = blockIdx.x * 256 + threadIdx.x;
    if (i < 512)       bdown[i] = bdkv[i];
    else if (i < 1024) bdown[i] = bdq[i - 512];
    else if (i < 1088) bdown[i] = bkr[i - 1024];
    else if (i < 2112) bkv[i - 1088] = buk[i - 1088];
    else if (i < 3136) bkv[i - 1088] = buv[i - 2112];
    else if (i < 4160) bqq[i - 3136] = buq[i - 3136];
    else if (i < 5184) bqq[i - 3136] = bqr[i - 4160];
}

// ------------------------------ tensor GEMM --------------------------------
// C(M,N) = (Ah+Al)(M x K, row pitch lda) @ Bh^T(N,K) + bias.
// CTA 128x128, K-chunk 32, 8 warps, warp tile 64x32, 2-stage cp.async.
#define ROWB 80
#define TILEB (128 * ROWB)
#define STAGEB (3 * TILEB)
#define GT_SMEM (2 * STAGEB)

__global__ __launch_bounds__(256)
void tgemm_kernel(const __half* __restrict__ Ah,
                  const __half* __restrict__ Al,
                  const __half* __restrict__ Bh,
                  const float* __restrict__ bias,
                  float* __restrict__ C,
                  __half* __restrict__ CH,
                  __half* __restrict__ CL,
                  int N, int K, int lda)
{
    extern __shared__ __align__(16) char smem[];

    const int tid  = threadIdx.x;
    const int wid  = tid >> 5;
    const int lane = tid & 31;
    const int wm   = wid >> 2;
    const int wn   = wid & 3;
    const int m0   = blockIdx.y * 128;
    const int n0   = blockIdx.x * 128;
    const uint32_t sb = smem_u32(smem);

    const __half* srcs[3] = {Ah, Al, Bh};

    const int lrow0 = tid >> 2;
    const int lq0   = tid & 3;
    const int lrow1 = (tid + 256) >> 2;
    const int lq1   = (tid + 256) & 3;

    float acc[4][4][4];
#pragma unroll
    for (int i = 0; i < 4; i++)
#pragma unroll
        for (int j = 0; j < 4; j++)
#pragma unroll
            for (int v = 0; v < 4; v++) acc[i][j][v] = 0.0f;

    const int r16   = lane & 15;
    const int khalfA = (lane >> 4) * 16;
    const int r8    = lane & 7;
    const int khalfB = ((lane >> 3) & 1) * 16;

    const int nchunks = K >> 5;

    {
#pragma unroll
        for (int t = 0; t < 3; t++) {
            const bool isB = (t == 2);
            const __half* src = srcs[t];
            const int ld = isB ? K : lda;
            {
                int grow = isB ? (n0 + lrow0) : (m0 + lrow0);
                int ok = (!isB || grow < N) ? 16 : 0;
                if (!ok) grow = n0;
                cp16(sb + t * TILEB + lrow0 * ROWB + lq0 * 16,
                     src + (size_t)grow * ld + lq0 * 8, ok);
            }
            {
                int grow = isB ? (n0 + lrow1) : (m0 + lrow1);
                int ok = (!isB || grow < N) ? 16 : 0;
                if (!ok) grow = n0;
                cp16(sb + t * TILEB + lrow1 * ROWB + lq1 * 16,
                     src + (size_t)grow * ld + lq1 * 8, ok);
            }
        }
        cp_commit();
    }

    for (int ci = 0; ci < nchunks; ci++) {
        const uint32_t cur = sb + (uint32_t)(ci & 1) * STAGEB;

        if (ci + 1 < nchunks) {
            const int k0 = (ci + 1) << 5;
            const uint32_t nxt = sb + (uint32_t)((ci + 1) & 1) * STAGEB;
#pragma unroll
            for (int t = 0; t < 3; t++) {
                const bool isB = (t == 2);
                const __half* src = srcs[t];
                const int ld = isB ? K : lda;
                {
                    int grow = isB ? (n0 + lrow0) : (m0 + lrow0);
                    int ok = (!isB || grow < N) ? 16 : 0;
                    if (!ok) grow = n0;
                    cp16(nxt + t * TILEB + lrow0 * ROWB + lq0 * 16,
                         src + (size_t)grow * ld + k0 + lq0 * 8, ok);
                }
                {
                    int grow = isB ? (n0 + lrow1) : (m0 + lrow1);
                    int ok = (!isB || grow < N) ? 16 : 0;
                    if (!ok) grow = n0;
                    cp16(nxt + t * TILEB + lrow1 * ROWB + lq1 * 16,
                         src + (size_t)grow * ld + k0 + lq1 * 8, ok);
                }
            }
            cp_commit();
            cp_wait<1>();
        } else {
            cp_wait<0>();
        }
        __syncthreads();

#pragma unroll
        for (int ks = 0; ks < 2; ks++) {
            const int kb = ks * 32;
            uint32_t ah[4][4], al[4][4], bh[4][2];
#pragma unroll
            for (int mi = 0; mi < 4; mi++)
                ldsm_x4(ah[mi][0], ah[mi][1], ah[mi][2], ah[mi][3],
                        cur + 0 * TILEB + (wm * 64 + mi * 16 + r16) * ROWB + kb + khalfA);
#pragma unroll
            for (int ni = 0; ni < 4; ni++)
                ldsm_x2(bh[ni][0], bh[ni][1],
                        cur + 2 * TILEB + (wn * 32 + ni * 8 + r8) * ROWB + kb + khalfB);
#pragma unroll
            for (int mi = 0; mi < 4; mi++)
#pragma unroll
                for (int ni = 0; ni < 4; ni++)
                    mma16816(acc[mi][ni], ah[mi], bh[ni]);

#pragma unroll
            for (int mi = 0; mi < 4; mi++)
                ldsm_x4(al[mi][0], al[mi][1], al[mi][2], al[mi][3],
                        cur + 1 * TILEB + (wm * 64 + mi * 16 + r16) * ROWB + kb + khalfA);
#pragma unroll
            for (int mi = 0; mi < 4; mi++)
#pragma unroll
                for (int ni = 0; ni < 4; ni++)
                    mma16816(acc[mi][ni], al[mi], bh[ni]);
        }
        __syncthreads();
    }

#pragma unroll
    for (int mi = 0; mi < 4; mi++) {
        int row0 = m0 + wm * 64 + mi * 16 + (lane >> 2);
#pragma unroll
        for (int ni = 0; ni < 4; ni++) {
            int col = n0 + wn * 32 + ni * 8 + 2 * (lane & 3);
            if (col < N) {
                float2 b2 = *(const float2*)(bias + col);
                float v00 = acc[mi][ni][0] + b2.x, v01 = acc[mi][ni][1] + b2.y;
                float v10 = acc[mi][ni][2] + b2.x, v11 = acc[mi][ni][3] + b2.y;
                if (C) {
                    *(float2*)(C + (size_t)row0 * N + col) = make_float2(v00, v01);
                    *(float2*)(C + (size_t)(row0 + 8) * N + col) = make_float2(v10, v11);
                }
                if (CH) {
                    __half2 h0 = __floats2half2_rn(v00, v01);
                    __half2 l0 = __floats2half2_rn(v00 - __low2float(h0),
                                                   v01 - __high2float(h0));
                    __half2 h1 = __floats2half2_rn(v10, v11);
                    __half2 l1 = __floats2half2_rn(v10 - __low2float(h1),
                                                   v11 - __high2float(h1));
                    *(__half2*)(CH + (size_t)row0 * N + col) = h0;
                    *(__half2*)(CL + (size_t)row0 * N + col) = l0;
                    *(__half2*)(CH + (size_t)(row0 + 8) * N + col) = h1;
                    *(__half2*)(CL + (size_t)(row0 + 8) * N + col) = l1;
                }
            }
        }
    }
}

// ------------------------------ pack kernels (rope fused) ------------------
// qq layout: [tok][2048] = q_c(1024) | q_r(1024)
__global__ void qpack_kernel(const float* __restrict__ qq,
                             __half* __restrict__ PH,
                             __half* __restrict__ PL)
{
    int idx = blockIdx.x * 256 + threadIdx.x;
    int d2 = idx & 63;
    int s  = (idx >> 6) & (SEQLEN - 1);
    int bh = idx >> 15;
    int h = bh & (NHEADS - 1), b = bh >> 4;
    int tok = b * SEQLEN + s;
    float f0, f1;
    int dd;
    if (d2 < 32) {
        dd = d2 * 2;
        float2 v = *(const float2*)(qq + (size_t)tok * 2048 + h * 64 + dd);
        f0 = v.x; f1 = v.y;
    } else {
        int pair = d2 - 32;
        int rp = pair * 2;
        float2 v = *(const float2*)(qq + (size_t)tok * 2048 + 1024 + h * 64 + rp);
        float theta = powf(10000.0f, -(float)pair * (1.0f / 32.0f));
        float sn, cs;
        sincosf((float)s * theta, &sn, &cs);
        f0 = v.x * sn - v.y * cs;
        f1 = v.y * sn + v.x * cs;
        dd = 64 + rp;
    }
    size_t base = ((size_t)bh * SEQLEN + s) * 128 + dd;
    splt_h(f0, PH[base], PL[base]);
    splt_h(f1, PH[base + 1], PL[base + 1]);
}

// kv layout: [tok][2048] = k_c(1024) | v_c(1024); kr from cH/cL cols 1024-1087
__global__ void kpack_kernel(const float* __restrict__ kv,
                             const __half* __restrict__ cH,
                             const __half* __restrict__ cL,
                             __half* __restrict__ PH)
{
    int idx = blockIdx.x * 256 + threadIdx.x;
    int d2 = idx & 63;
    int s  = (idx >> 6) & (SEQLEN - 1);
    int bh = idx >> 15;
    int h = bh & (NHEADS - 1), b = bh >> 4;
    int tok = b * SEQLEN + s;
    float f0, f1;
    int dd;
    if (d2 < 32) {
        dd = d2 * 2;
        float2 v = *(const float2*)(kv + (size_t)tok * 2048 + h * 64 + dd);
        f0 = v.x; f1 = v.y;
    } else {
        int pair = d2 - 32;
        int rp = pair * 2;
        __half2 vh = *(const __half2*)(cH + (size_t)tok * NDOWN + 1024 + rp);
        __half2 vl = *(const __half2*)(cL + (size_t)tok * NDOWN + 1024 + rp);
        float x0 = __low2float(vh) + __low2float(vl);
        float x1 = __high2float(vh) + __high2float(vl);
        float theta = powf(10000.0f, -(float)pair * (1.0f / 32.0f));
        float sn, cs;
        sincosf((float)s * theta, &sn, &cs);
        f0 = x0 * sn - x1 * cs;
        f1 = x1 * sn + x0 * cs;
        dd = 64 + rp;
    }
    size_t base = ((size_t)bh * SEQLEN + s) * 128 + dd;
    *(__half2*)(PH + base) = __floats2half2_rn(f0, f1);
}

__global__ void vpack_kernel(const float* __restrict__ kv,
                             __half* __restrict__ PH)
{
    int idx = blockIdx.x * 256 + threadIdx.x;
    int d2 = idx & 31;
    int s  = (idx >> 5) & (SEQLEN - 1);
    int bh = idx >> 14;
    int h = bh & (NHEADS - 1), b = bh >> 4;
    int tok = b * SEQLEN + s;
    int dd = d2 * 2;
    float2 v = *(const float2*)(kv + (size_t)tok * 2048 + 1024 + h * 64 + dd);
    size_t base = ((size_t)bh * SEQLEN + s) * 64 + dd;
    *(__half2*)(PH + base) = __floats2half2_rn(v.x, v.y);
}

// ------------------------------ attention ----------------------------------
#define QPITCH 272
#define VPITCH 144
#define SPITCH 516
#define OFF_QH 0
#define OFF_QL 17408
#define OFF_KH 34816
#define OFF_VH 34816
#define OFF_S  52224
#define ATTN2_SMEM (OFF_S + 64 * SPITCH * 4)

__global__ __launch_bounds__(256)
void attn2_kernel(const __half* __restrict__ QPH,
                  const __half* __restrict__ QPL,
                  const __half* __restrict__ KPH,
                  const __half* __restrict__ VPH,
                  __half* __restrict__ aoH,
                  __half* __restrict__ aoL)
{
    extern __shared__ char sm2[];
    const uint32_t sb = smem_u32(sm2);
    float* Ssf = (float*)(sm2 + OFF_S);

    const int tid  = threadIdx.x;
    const int wid  = tid >> 5;
    const int lane = tid & 31;
    const int wm = wid >> 2;
    const int wn = wid & 3;
    const int q0 = blockIdx.x * 64;
    const int hh = blockIdx.y;
    const int b  = blockIdx.z;
    const int bh = b * NHEADS + hh;
    const size_t pbase = (size_t)bh * SEQLEN * 128;
    const float scale = 0.07216878364870322f;

    const int r16 = lane & 15;
    const int khalfA = (lane >> 4) * 16;
    const int r8 = lane & 7;
    const int khalfB = ((lane >> 3) & 1) * 16;

#pragma unroll
    for (int j = 0; j < 4; j++) {
        int idx = tid + j * 256;
        int row = idx >> 4, c = idx & 15;
        size_t g = pbase + (size_t)(q0 + row) * 128 + c * 8;
        *(uint4*)(sm2 + OFF_QH + row * QPITCH + c * 16) = *(const uint4*)(QPH + g);
        *(uint4*)(sm2 + OFF_QL + row * QPITCH + c * 16) = *(const uint4*)(QPL + g);
    }

    for (int kt = 0; kt < 8; kt++) {
        __syncthreads();
#pragma unroll
        for (int j = 0; j < 4; j++) {
            int idx = tid + j * 256;
            int row = idx >> 4, c = idx & 15;
            size_t g = pbase + (size_t)(kt * 64 + row) * 128 + c * 8;
            *(uint4*)(sm2 + OFF_KH + row * QPITCH + c * 16) = *(const uint4*)(KPH + g);
        }
        __syncthreads();

        float acc[2][2][4];
#pragma unroll
        for (int mi = 0; mi < 2; mi++)
#pragma unroll
            for (int ni = 0; ni < 2; ni++)
#pragma unroll
                for (int v = 0; v < 4; v++) acc[mi][ni][v] = 0.0f;

#pragma unroll
        for (int ks = 0; ks < 8; ks++) {
            const int kb = ks * 32;
            uint32_t ah[2][4], al[2][4], bhf[2][2];
#pragma unroll
            for (int mi = 0; mi < 2; mi++)
                ldsm_x4(ah[mi][0], ah[mi][1], ah[mi][2], ah[mi][3],
                        sb + OFF_QH + (wm * 32 + mi * 16 + r16) * QPITCH + kb + khalfA);
#pragma unroll
            for (int ni = 0; ni < 2; ni++)
                ldsm_x2(bhf[ni][0], bhf[ni][1],
                        sb + OFF_KH + (wn * 16 + ni * 8 + r8) * QPITCH + kb + khalfB);
#pragma unroll
            for (int mi = 0; mi < 2; mi++)
#pragma unroll
                for (int ni = 0; ni < 2; ni++)
                    mma16816(acc[mi][ni], ah[mi], bhf[ni]);
#pragma unroll
            for (int mi = 0; mi < 2; mi++)
                ldsm_x4(al[mi][0], al[mi][1], al[mi][2], al[mi][3],
                        sb + OFF_QL + (wm * 32 + mi * 16 + r16) * QPITCH + kb + khalfA);
#pragma unroll
            for (int mi = 0; mi < 2; mi++)
#pragma unroll
                for (int ni = 0; ni < 2; ni++)
                    mma16816(acc[mi][ni], al[mi], bhf[ni]);
        }

#pragma unroll
        for (int mi = 0; mi < 2; mi++) {
            int row = wm * 32 + mi * 16 + (lane >> 2);
#pragma unroll
            for (int ni = 0; ni < 2; ni++) {
                int col = kt * 64 + wn * 16 + ni * 8 + 2 * (lane & 3);
                Ssf[row * SPITCH + col]           = acc[mi][ni][0] * scale;
                Ssf[row * SPITCH + col + 1]       = acc[mi][ni][1] * scale;
                Ssf[(row + 8) * SPITCH + col]     = acc[mi][ni][2] * scale;
                Ssf[(row + 8) * SPITCH + col + 1] = acc[mi][ni][3] * scale;
            }
        }
    }
    __syncthreads();

    {
        int row  = tid >> 2;
        int part = tid & 3;
        float* srow = Ssf + row * SPITCH;
        float mx = -1e30f;
#pragma unroll 4
        for (int k2 = 0; k2 < 128; k2++)
            mx = fmaxf(mx, srow[part + k2 * 4]);
        mx = fmaxf(mx, __shfl_xor_sync(0xffffffffu, mx, 1));
        mx = fmaxf(mx, __shfl_xor_sync(0xffffffffu, mx, 2));
        float sum = 0.0f;
#pragma unroll 4
        for (int k2 = 0; k2 < 128; k2++) {
            float e = __expf(srow[part + k2 * 4] - mx);
            srow[part + k2 * 4] = e;
            sum += e;
        }
        sum += __shfl_xor_sync(0xffffffffu, sum, 1);
        sum += __shfl_xor_sync(0xffffffffu, sum, 2);
        float inv = 1.0f / sum;
#pragma unroll 4
        for (int k2 = 0; k2 < 128; k2++)
            srow[part + k2 * 4] *= inv;
    }

    float accO[2][2][4];
#pragma unroll
    for (int mi = 0; mi < 2; mi++)
#pragma unroll
        for (int ni = 0; ni < 2; ni++)
#pragma unroll
            for (int v = 0; v < 4; v++) accO[mi][ni][v] = 0.0f;

    const size_t vbase = (size_t)bh * SEQLEN * 64;
    for (int kt = 0; kt < 8; kt++) {
        __syncthreads();
#pragma unroll
        for (int j = 0; j < 2; j++) {
            int idx = tid + j * 256;
            int key = idx >> 3, dg = idx & 7;
            size_t g = vbase + (size_t)(kt * 64 + key) * 64 + dg * 8;
            uint4 vh = *(const uint4*)(VPH + g);
            const uint16_t* ph = (const uint16_t*)&vh;
#pragma unroll
            for (int jj = 0; jj < 8; jj++)
                *(uint16_t*)(sm2 + OFF_VH + (dg * 8 + jj) * VPITCH + key * 2) = ph[jj];
        }
        __syncthreads();

#pragma unroll
        for (int ks = 0; ks < 4; ks++) {
            uint32_t ph_[2][4], pl_[2][4];
#pragma unroll
            for (int mi = 0; mi < 2; mi++) {
                int r  = wm * 32 + mi * 16 + (lane >> 2);
                int kc = kt * 64 + ks * 16 + 2 * (lane & 3);
                f2_hilo_h(*(float2*)&Ssf[r * SPITCH + kc],           ph_[mi][0], pl_[mi][0]);
                f2_hilo_h(*(float2*)&Ssf[(r + 8) * SPITCH + kc],     ph_[mi][1], pl_[mi][1]);
                f2_hilo_h(*(float2*)&Ssf[r * SPITCH + kc + 8],       ph_[mi][2], pl_[mi][2]);
                f2_hilo_h(*(float2*)&Ssf[(r + 8) * SPITCH + kc + 8], ph_[mi][3], pl_[mi][3]);
            }
            uint32_t vh_[2][2];
#pragma unroll
            for (int ni = 0; ni < 2; ni++) {
                uint32_t a = sb + OFF_VH + (wn * 16 + ni * 8 + r8) * VPITCH + ks * 32 + khalfB;
                ldsm_x2(vh_[ni][0], vh_[ni][1], a);
            }
#pragma unroll
            for (int mi = 0; mi < 2; mi++)
#pragma unroll
                for (int ni = 0; ni < 2; ni++) {
                    mma16816(accO[mi][ni], ph_[mi], vh_[ni]);
                    mma16816(accO[mi][ni], pl_[mi], vh_[ni]);
                }
        }
    }

#pragma unroll
    for (int mi = 0; mi < 2; mi++) {
        int rloc = wm * 32 + mi * 16 + (lane >> 2);
        int tok  = b * SEQLEN + q0 + rloc;
#pragma unroll
        for (int ni = 0; ni < 2; ni++) {
            int col = wn * 16 + ni * 8 + 2 * (lane & 3);
            float v00 = accO[mi][ni][0], v01 = accO[mi][ni][1];
            float v10 = accO[mi][ni][2], v11 = accO[mi][ni][3];
            __half2 h0 = __floats2half2_rn(v00, v01);
            __half2 l0 = __floats2half2_rn(v00 - __low2float(h0),
                                           v01 - __high2float(h0));
            __half2 h1 = __floats2half2_rn(v10, v11);
            __half2 l1 = __floats2half2_rn(v10 - __low2float(h1),
                                           v11 - __high2float(h1));
            *(__half2*)(aoH + (size_t)tok * UPDIM + hh * 64 + col) = h0;
            *(__half2*)(aoL + (size_t)tok * UPDIM + hh * 64 + col) = l0;
            *(__half2*)(aoH + (size_t)(tok + 8) * UPDIM + hh * 64 + col) = h1;
            *(__half2*)(aoL + (size_t)(tok + 8) * UPDIM + hh * 64 + col) = l1;
        }
    }
}

// ---------------------------------------------------------------------------
extern "C" void kernel_launch(void* const* d_in, const int* in_sizes, int n_in,
                              void* d_out, int out_size)
{
    const float* h    = (const float*)d_in[0];
    const float* Wdkv = (const float*)d_in[1];
    const float* bdkv = (const float*)d_in[2];
    const float* Wuk  = (const float*)d_in[3];
    const float* buk  = (const float*)d_in[4];
    const float* Wuv  = (const float*)d_in[5];
    const float* buv  = (const float*)d_in[6];
    const float* Wdq  = (const float*)d_in[7];
    const float* bdq  = (const float*)d_in[8];
    const float* Wuq  = (const float*)d_in[9];
    const float* buq  = (const float*)d_in[10];
    const float* Wqr  = (const float*)d_in[11];
    const float* bqr  = (const float*)d_in[12];
    const float* Wkr  = (const float*)d_in[13];
    const float* bkr  = (const float*)d_in[14];
    const float* Wfc  = (const float*)d_in[15];
    const float* bfc  = (const float*)d_in[16];
    float* out = (float*)d_out;

    __half *hH, *hL, *cH, *cL, *aoH, *aoL;
    float *kv, *qq, *bdown, *bkv, *bqq;
    __half *Wdown16, *Wkv16, *Wqq16, *Wfc16;
    __half *QPH, *QPL, *KPH, *VPH;
    cudaGetSymbolAddress((void**)&hH,      g_hH);
    cudaGetSymbolAddress((void**)&hL,      g_hL);
    cudaGetSymbolAddress((void**)&cH,      g_cH);
    cudaGetSymbolAddress((void**)&cL,      g_cL);
    cudaGetSymbolAddress((void**)&kv,      g_kv);
    cudaGetSymbolAddress((void**)&qq,      g_qq);
    cudaGetSymbolAddress((void**)&aoH,     g_aoH);
    cudaGetSymbolAddress((void**)&aoL,     g_aoL);
    cudaGetSymbolAddress((void**)&Wdown16, g_Wdown16);
    cudaGetSymbolAddress((void**)&Wkv16,   g_Wkv16);
    cudaGetSymbolAddress((void**)&Wqq16,   g_Wqq16);
    cudaGetSymbolAddress((void**)&Wfc16,   g_Wfc16);
    cudaGetSymbolAddress((void**)&bdown,   g_bdown);
    cudaGetSymbolAddress((void**)&bkv,     g_bkv);
    cudaGetSymbolAddress((void**)&bqq,     g_bqq);
    cudaGetSymbolAddress((void**)&QPH,     g_QPH);
    cudaGetSymbolAddress((void**)&QPL,     g_QPL);
    cudaGetSymbolAddress((void**)&KPH,     g_KPH);
    cudaGetSymbolAddress((void**)&VPH,     g_VPH);

    cudaFuncSetAttribute(attn2_kernel,
                         cudaFuncAttributeMaxDynamicSharedMemorySize, ATTN2_SMEM);
    cudaFuncSetAttribute(tgemm_kernel,
                         cudaFuncAttributeMaxDynamicSharedMemorySize, GT_SMEM);

    // prep
    split_kernel<<<TOK * DMODEL / 2 / 256, 256>>>(h, hH, hL, TOK * DMODEL / 2);
    wconv_all_kernel<<<(WB7 + 255) / 256, 256>>>(Wdkv, Wdq, Wkr, Wuk, Wuv, Wuq,
                                                 Wqr, Wfc, Wdown16, Wkv16,
                                                 Wqq16, Wfc16);
    bias_concat_kernel<<<21, 256>>>(bdkv, bdq, bkr, buk, buv, buq, bqr,
                                    bdown, bkv, bqq);

    dim3 blk(256);
    // fused down projection: N=1088 (ckv|cq|kr), hi/lo fp16 out
    tgemm_kernel<<<dim3(9, TOK / 128), blk, GT_SMEM>>>(
        hH, hL, Wdown16, bdown, nullptr, cH, cL, NDOWN, DMODEL, DMODEL);

    // fused up projections: N=2048 each, fp32 out
    tgemm_kernel<<<dim3(16, TOK / 128), blk, GT_SMEM>>>(
        cH, cL, Wkv16, bkv, kv, nullptr, nullptr, 2048, DOWND, NDOWN);
    tgemm_kernel<<<dim3(16, TOK / 128), blk, GT_SMEM>>>(
        cH + 512, cL + 512, Wqq16, bqq, qq, nullptr, nullptr, 2048, DOWND, NDOWN);

    // pack (rope fused) + attention
    qpack_kernel<<<NBH * SEQLEN * 64 / 256, 256>>>(qq, QPH, QPL);
    kpack_kernel<<<NBH * SEQLEN * 64 / 256, 256>>>(kv, cH, cL, KPH);
    vpack_kernel<<<NBH * SEQLEN * 32 / 256, 256>>>(kv, VPH);
    attn2_kernel<<<dim3(SEQLEN / 64, NHEADS, BATCH), blk, ATTN2_SMEM>>>(
        QPH, QPL, KPH, VPH, aoH, aoL);

    // output projection (fp32 out)
    tgemm_kernel<<<dim3(16, TOK / 128), blk, GT_SMEM>>>(
        aoH, aoL, Wfc16, bfc, out, nullptr, nullptr, DMODEL, UPDIM, UPDIM);
}

// round 15
// speedup vs baseline: 4.1115x; 1.0284x over previous
#include <cuda_runtime.h>
#include <cuda_fp16.h>
#include <math.h>
#include <cstdint>

// ===========================================================================
// MLA attention. All GEMMs + attention via mma.sync fp16 2-pass split
// (A = Ah+Al fp16 pair, B single fp16; fp32 accum). GEMMs fused along N.
// 3-stage cp.async pipeline. Attention pack layouts written directly by
// GEMM epilogues (rope fused); only k_r head-broadcast is a separate kernel.
// ===========================================================================

#define TOK    8192
#define SEQLEN 512
#define DMODEL 2048
#define DOWND  512
#define UPDIM  1024
#define NHEADS 16
#define RDIM   64
#define BATCH  16
#define NBH    (BATCH * NHEADS)
#define NDOWN  1088          // 512 ckv | 512 cq | 64 kr

// ------------------------------ scratch ------------------------------------
__device__ __half g_hH [TOK * DMODEL];
__device__ __half g_hL [TOK * DMODEL];
__device__ __half g_cH [TOK * NDOWN];
__device__ __half g_cL [TOK * NDOWN];
__device__ __half g_aoH[TOK * UPDIM];
__device__ __half g_aoL[TOK * UPDIM];

__device__ __half g_Wdown16[NDOWN * DMODEL];
__device__ __half g_Wkv16  [2048 * DOWND];
__device__ __half g_Wqq16  [2048 * DOWND];
__device__ __half g_Wfc16  [DMODEL * UPDIM];
__device__ float  g_bdown[NDOWN];
__device__ float  g_bkv  [2048];
__device__ float  g_bqq  [2048];

__device__ __half g_QPH[NBH * SEQLEN * 128];
__device__ __half g_QPL[NBH * SEQLEN * 128];
__device__ __half g_KPH[NBH * SEQLEN * 128];
__device__ __half g_VPH[NBH * SEQLEN * 64];

// ------------------------------ helpers ------------------------------------
__device__ __forceinline__ uint32_t smem_u32(const void* p) {
    uint32_t a;
    asm("{ .reg .u64 t; cvta.to.shared.u64 t, %1; cvt.u32.u64 %0, t; }"
        : "=r"(a) : "l"(p));
    return a;
}
__device__ __forceinline__ void ldsm_x4(uint32_t& r0, uint32_t& r1,
                                        uint32_t& r2, uint32_t& r3,
                                        uint32_t addr) {
    asm volatile("ldmatrix.sync.aligned.m8n8.x4.shared.b16 {%0,%1,%2,%3}, [%4];"
                 : "=r"(r0), "=r"(r1), "=r"(r2), "=r"(r3) : "r"(addr));
}
__device__ __forceinline__ void ldsm_x2(uint32_t& r0, uint32_t& r1,
                                        uint32_t addr) {
    asm volatile("ldmatrix.sync.aligned.m8n8.x2.shared.b16 {%0,%1}, [%2];"
                 : "=r"(r0), "=r"(r1) : "r"(addr));
}
__device__ __forceinline__ void mma16816(float* c, const uint32_t* a,
                                         const uint32_t* b) {
    asm volatile(
        "mma.sync.aligned.m16n8k16.row.col.f32.f16.f16.f32 "
        "{%0,%1,%2,%3}, {%4,%5,%6,%7}, {%8,%9}, {%0,%1,%2,%3};"
        : "+f"(c[0]), "+f"(c[1]), "+f"(c[2]), "+f"(c[3])
        : "r"(a[0]), "r"(a[1]), "r"(a[2]), "r"(a[3]), "r"(b[0]), "r"(b[1]));
}
__device__ __forceinline__ void cp16(uint32_t dst, const void* src, int nbytes) {
    asm volatile("cp.async.cg.shared.global [%0], [%1], 16, %2;"
                 :: "r"(dst), "l"(src), "r"(nbytes));
}
__device__ __forceinline__ void cp_commit() {
    asm volatile("cp.async.commit_group;");
}
template <int N> __device__ __forceinline__ void cp_wait() {
    asm volatile("cp.async.wait_group %0;" :: "n"(N));
}
__device__ __forceinline__ void splt_h(float v, __half& h, __half& l) {
    h = __float2half_rn(v);
    l = __float2half_rn(v - __half2float(h));
}
__device__ __forceinline__ void f2_hilo_h(float2 f, uint32_t& h, uint32_t& l) {
    __half2 hb = __floats2half2_rn(f.x, f.y);
    float rx = f.x - __low2float(hb);
    float ry = f.y - __high2float(hb);
    __half2 lb = __floats2half2_rn(rx, ry);
    h = *(uint32_t*)&hb;
    l = *(uint32_t*)&lb;
}

// ------------------------------ prep kernels -------------------------------
__global__ void split_kernel(const float* __restrict__ x,
                             __half* __restrict__ hi,
                             __half* __restrict__ lo, int n2)
{
    int i = blockIdx.x * blockDim.x + threadIdx.x;
    if (i >= n2) return;
    float2 v = *(const float2*)(x + i * 2);
    __half2 hb = __floats2half2_rn(v.x, v.y);
    float rx = v.x - __low2float(hb);
    float ry = v.y - __high2float(hb);
    __half2 lb = __floats2half2_rn(rx, ry);
    *(__half2*)(hi + i * 2) = hb;
    *(__half2*)(lo + i * 2) = lb;
}

#define WB0 524288u
#define WB1 1048576u
#define WB2 1114112u
#define WB3 1376256u
#define WB4 1638400u
#define WB5 1900544u
#define WB6 2162688u
#define WB7 3211264u

__global__ void wconv_all_kernel(const float* __restrict__ Wdkv,
                                 const float* __restrict__ Wdq,
                                 const float* __restrict__ Wkr,
                                 const float* __restrict__ Wuk,
                                 const float* __restrict__ Wuv,
                                 const float* __restrict__ Wuq,
                                 const float* __restrict__ Wqr,
                                 const float* __restrict__ Wfc,
                                 __half* __restrict__ Wdown16,
                                 __half* __restrict__ Wkv16,
                                 __half* __restrict__ Wqq16,
                                 __half* __restrict__ Wfc16)
{
    uint32_t i = blockIdx.x * 256u + threadIdx.x;
    if (i >= WB7) return;
    const float* src;
    __half* dst;
    uint32_t o;
    if (i < WB1) {
        if (i < WB0) { src = Wdkv; o = i;        dst = Wdown16; }
        else         { src = Wdq;  o = i - WB0;  dst = Wdown16 + 1048576u; }
    } else if (i < WB3) {
        if (i < WB2) { src = Wkr;  o = i - WB1;  dst = Wdown16 + 2097152u; }
        else         { src = Wuk;  o = i - WB2;  dst = Wkv16; }
    } else if (i < WB5) {
        if (i < WB4) { src = Wuv;  o = i - WB3;  dst = Wkv16 + 524288u; }
        else         { src = Wuq;  o = i - WB4;  dst = Wqq16; }
    } else {
        if (i < WB6) { src = Wqr;  o = i - WB5;  dst = Wqq16 + 524288u; }
        else         { src = Wfc;  o = i - WB6;  dst = Wfc16; }
    }
    float2 v = *(const float2*)(src + (size_t)o * 2);
    *(__half2*)(dst + (size_t)o * 2) = __floats2half2_rn(v.x, v.y);
}

__global__ void bias_concat_kernel(const float* __restrict__ bdkv,
                                   const float* __restrict__ bdq,
                                   const float* __restrict__ bkr,
                                   const float* __restrict__ buk,
                                   const float* __restrict__ buv,
                                   const float* __restrict__ buq,
                                   const float* __restrict__ bqr,
                                   float* __restrict__ bdown,
                                   float* __restrict__ bkv,
                                   float* __restrict__ bqq)
{
    int i = blockIdx.x * 256 + threadIdx.x;
    if (i < 512)       bdown[i] = bdkv[i];
    else if (i < 1024) bdown[i] = bdq[i - 512];
    else if (i < 1088) bdown[i] = bkr[i - 1024];
    else if (i < 2112) bkv[i - 1088] = buk[i - 1088];
    else if (i < 3136) bkv[i - 1088] = buv[i - 2112];
    else if (i < 4160) bqq[i - 3136] = buq[i - 3136];
    else if (i < 5184) bqq[i - 3136] = bqr[i - 4160];
}

// k_r shared rope, broadcast to all heads: KPH[bh][s][64..127]
__global__ void krope_kernel(const __half* __restrict__ cH,
                             const __half* __restrict__ cL,
                             __half* __restrict__ KPH)
{
    int idx = blockIdx.x * 256 + threadIdx.x;   // TOK*32
    int pair = idx & 31;
    int tok  = idx >> 5;
    int s = tok & (SEQLEN - 1), b = tok >> 9;
    int rp = pair * 2;
    __half2 vh = *(const __half2*)(cH + (size_t)tok * NDOWN + 1024 + rp);
    __half2 vl = *(const __half2*)(cL + (size_t)tok * NDOWN + 1024 + rp);
    float x0 = __low2float(vh) + __low2float(vl);
    float x1 = __high2float(vh) + __high2float(vl);
    float theta = powf(10000.0f, -(float)pair * (1.0f / 32.0f));
    float sn, cs;
    sincosf((float)s * theta, &sn, &cs);
    __half2 val = __floats2half2_rn(x0 * sn - x1 * cs, x1 * sn + x0 * cs);
#pragma unroll
    for (int h = 0; h < NHEADS; h++)
        *(__half2*)(KPH + (((size_t)(b * NHEADS + h) * SEQLEN + s) * 128) + 64 + rp) = val;
}

// ------------------------------ tensor GEMM --------------------------------
// C(M,N) = (Ah+Al)(M x K, pitch lda) @ Bh^T(N,K) + bias.
// CTA 128x128, K-chunk 32, 8 warps, warp tile 64x32, 3-stage cp.async.
// mode 0: fp32 C.  mode 1: fp16 hi/lo CH/CL row-major.
// mode 2: kv pack  (CH=KPH content dims, CL_as_V=VPH).
// mode 3: qq pack  (CH=QPH, CL=QPL, rope on cols>=1024).
#define ROWB 80
#define TILEB (128 * ROWB)
#define STAGEB (3 * TILEB)
#define GT_SMEM (3 * STAGEB)

__global__ __launch_bounds__(256)
void tgemm_kernel(const __half* __restrict__ Ah,
                  const __half* __restrict__ Al,
                  const __half* __restrict__ Bh,
                  const float* __restrict__ bias,
                  float* __restrict__ C,
                  __half* __restrict__ CH,
                  __half* __restrict__ CL,
                  int N, int K, int lda, int mode)
{
    extern __shared__ __align__(16) char smem[];

    const int tid  = threadIdx.x;
    const int wid  = tid >> 5;
    const int lane = tid & 31;
    const int wm   = wid >> 2;
    const int wn   = wid & 3;
    const int m0   = blockIdx.y * 128;
    const int n0   = blockIdx.x * 128;
    const uint32_t sb = smem_u32(smem);

    const __half* srcs[3] = {Ah, Al, Bh};

    const int lrow0 = tid >> 2;
    const int lq0   = tid & 3;
    const int lrow1 = (tid + 256) >> 2;
    const int lq1   = (tid + 256) & 3;

    float acc[4][4][4];
#pragma unroll
    for (int i = 0; i < 4; i++)
#pragma unroll
        for (int j = 0; j < 4; j++)
#pragma unroll
            for (int v = 0; v < 4; v++) acc[i][j][v] = 0.0f;

    const int r16   = lane & 15;
    const int khalfA = (lane >> 4) * 16;
    const int r8    = lane & 7;
    const int khalfB = ((lane >> 3) & 1) * 16;

    const int nchunks = K >> 5;

    auto issue = [&](int c) {
        const uint32_t stg = sb + (uint32_t)(c % 3) * STAGEB;
        const int k0 = c << 5;
#pragma unroll
        for (int t = 0; t < 3; t++) {
            const bool isB = (t == 2);
            const __half* src = srcs[t];
            const int ld = isB ? K : lda;
            {
                int grow = isB ? (n0 + lrow0) : (m0 + lrow0);
                int ok = (!isB || grow < N) ? 16 : 0;
                if (!ok) grow = n0;
                cp16(stg + t * TILEB + lrow0 * ROWB + lq0 * 16,
                     src + (size_t)grow * ld + k0 + lq0 * 8, ok);
            }
            {
                int grow = isB ? (n0 + lrow1) : (m0 + lrow1);
                int ok = (!isB || grow < N) ? 16 : 0;
                if (!ok) grow = n0;
                cp16(stg + t * TILEB + lrow1 * ROWB + lq1 * 16,
                     src + (size_t)grow * ld + k0 + lq1 * 8, ok);
            }
        }
        cp_commit();
    };

    issue(0);
    if (nchunks > 1) issue(1);

    for (int ci = 0; ci < nchunks; ci++) {
        if (ci + 1 < nchunks) cp_wait<1>(); else cp_wait<0>();
        __syncthreads();
        if (ci + 2 < nchunks) issue(ci + 2);

        const uint32_t cur = sb + (uint32_t)(ci % 3) * STAGEB;
#pragma unroll
        for (int ks = 0; ks < 2; ks++) {
            const int kb = ks * 32;
            uint32_t ah[4][4], al[4][4], bh[4][2];
#pragma unroll
            for (int mi = 0; mi < 4; mi++)
                ldsm_x4(ah[mi][0], ah[mi][1], ah[mi][2], ah[mi][3],
                        cur + 0 * TILEB + (wm * 64 + mi * 16 + r16) * ROWB + kb + khalfA);
#pragma unroll
            for (int ni = 0; ni < 4; ni++)
                ldsm_x2(bh[ni][0], bh[ni][1],
                        cur + 2 * TILEB + (wn * 32 + ni * 8 + r8) * ROWB + kb + khalfB);
#pragma unroll
            for (int mi = 0; mi < 4; mi++)
#pragma unroll
                for (int ni = 0; ni < 4; ni++)
                    mma16816(acc[mi][ni], ah[mi], bh[ni]);

#pragma unroll
            for (int mi = 0; mi < 4; mi++)
                ldsm_x4(al[mi][0], al[mi][1], al[mi][2], al[mi][3],
                        cur + 1 * TILEB + (wm * 64 + mi * 16 + r16) * ROWB + kb + khalfA);
#pragma unroll
            for (int mi = 0; mi < 4; mi++)
#pragma unroll
                for (int ni = 0; ni < 4; ni++)
                    mma16816(acc[mi][ni], al[mi], bh[ni]);
        }
    }

    // ------------------------------ epilogue -------------------------------
#pragma unroll
    for (int mi = 0; mi < 4; mi++) {
        int row0 = m0 + wm * 64 + mi * 16 + (lane >> 2);
#pragma unroll
        for (int ni = 0; ni < 4; ni++) {
            int col = n0 + wn * 32 + ni * 8 + 2 * (lane & 3);
            if (col >= N) continue;
            float2 b2 = *(const float2*)(bias + col);
            float v00 = acc[mi][ni][0] + b2.x, v01 = acc[mi][ni][1] + b2.y;
            float v10 = acc[mi][ni][2] + b2.x, v11 = acc[mi][ni][3] + b2.y;

            if (mode == 0) {
                *(float2*)(C + (size_t)row0 * N + col) = make_float2(v00, v01);
                *(float2*)(C + (size_t)(row0 + 8) * N + col) = make_float2(v10, v11);
            } else if (mode == 1) {
                __half2 h0 = __floats2half2_rn(v00, v01);
                __half2 l0 = __floats2half2_rn(v00 - __low2float(h0),
                                               v01 - __high2float(h0));
                __half2 h1 = __floats2half2_rn(v10, v11);
                __half2 l1 = __floats2half2_rn(v10 - __low2float(h1),
                                               v11 - __high2float(h1));
                *(__half2*)(CH + (size_t)row0 * N + col) = h0;
                *(__half2*)(CL + (size_t)row0 * N + col) = l0;
                *(__half2*)(CH + (size_t)(row0 + 8) * N + col) = h1;
                *(__half2*)(CL + (size_t)(row0 + 8) * N + col) = l1;
            } else if (mode == 2) {
                // kv pack: cols<1024 -> KPH content, cols>=1024 -> VPH
#pragma unroll
                for (int rr = 0; rr < 2; rr++) {
                    int tok = row0 + rr * 8;
                    int b = tok >> 9, s = tok & (SEQLEN - 1);
                    float f0 = rr ? v10 : v00, f1 = rr ? v11 : v01;
                    __half2 hv = __floats2half2_rn(f0, f1);
                    if (col < 1024) {
                        int hh = col >> 6, d = col & 63;
                        *(__half2*)(CH + ((size_t)(b * NHEADS + hh) * SEQLEN + s) * 128 + d) = hv;
                    } else {
                        int hh = (col - 1024) >> 6, d = (col - 1024) & 63;
                        *(__half2*)(CL + ((size_t)(b * NHEADS + hh) * SEQLEN + s) * 64 + d) = hv;
                    }
                }
            } else {
                // qq pack: cols<1024 -> q_c (hi/lo), cols>=1024 -> q_r rope (hi/lo)
#pragma unroll
                for (int rr = 0; rr < 2; rr++) {
                    int tok = row0 + rr * 8;
                    int b = tok >> 9, s = tok & (SEQLEN - 1);
                    float f0 = rr ? v10 : v00, f1 = rr ? v11 : v01;
                    int hh, dd;
                    if (col < 1024) {
                        hh = col >> 6;
                        dd = col & 63;
                    } else {
                        hh = (col - 1024) >> 6;
                        int rp = (col - 1024) & 63;
                        int pair = rp >> 1;
                        float theta = powf(10000.0f, -(float)pair * (1.0f / 32.0f));
                        float sn, cs;
                        sincosf((float)s * theta, &sn, &cs);
                        float t0 = f0 * sn - f1 * cs;
                        float t1 = f1 * sn + f0 * cs;
                        f0 = t0; f1 = t1;
                        dd = 64 + rp;
                    }
                    uint32_t hi, lo;
                    f2_hilo_h(make_float2(f0, f1), hi, lo);
                    size_t base = ((size_t)(b * NHEADS + hh) * SEQLEN + s) * 128 + dd;
                    *(uint32_t*)(CH + base) = hi;
                    *(uint32_t*)(CL + base) = lo;
                }
            }
        }
    }
}

// ------------------------------ attention ----------------------------------
#define QPITCH 272
#define VPITCH 144
#define SPITCH 516
#define OFF_QH 0
#define OFF_QL 17408
#define OFF_KH 34816
#define OFF_VH 34816
#define OFF_S  52224
#define ATTN2_SMEM (OFF_S + 64 * SPITCH * 4)

__global__ __launch_bounds__(256)
void attn2_kernel(const __half* __restrict__ QPH,
                  const __half* __restrict__ QPL,
                  const __half* __restrict__ KPH,
                  const __half* __restrict__ VPH,
                  __half* __restrict__ aoH,
                  __half* __restrict__ aoL)
{
    extern __shared__ char sm2[];
    const uint32_t sb = smem_u32(sm2);
    float* Ssf = (float*)(sm2 + OFF_S);

    const int tid  = threadIdx.x;
    const int wid  = tid >> 5;
    const int lane = tid & 31;
    const int wm = wid >> 2;
    const int wn = wid & 3;
    const int q0 = blockIdx.x * 64;
    const int hh = blockIdx.y;
    const int b  = blockIdx.z;
    const int bh = b * NHEADS + hh;
    const size_t pbase = (size_t)bh * SEQLEN * 128;
    const float scale = 0.07216878364870322f;

    const int r16 = lane & 15;
    const int khalfA = (lane >> 4) * 16;
    const int r8 = lane & 7;
    const int khalfB = ((lane >> 3) & 1) * 16;

#pragma unroll
    for (int j = 0; j < 4; j++) {
        int idx = tid + j * 256;
        int row = idx >> 4, c = idx & 15;
        size_t g = pbase + (size_t)(q0 + row) * 128 + c * 8;
        *(uint4*)(sm2 + OFF_QH + row * QPITCH + c * 16) = *(const uint4*)(QPH + g);
        *(uint4*)(sm2 + OFF_QL + row * QPITCH + c * 16) = *(const uint4*)(QPL + g);
    }

    for (int kt = 0; kt < 8; kt++) {
        __syncthreads();
#pragma unroll
        for (int j = 0; j < 4; j++) {
            int idx = tid + j * 256;
            int row = idx >> 4, c = idx & 15;
            size_t g = pbase + (size_t)(kt * 64 + row) * 128 + c * 8;
            *(uint4*)(sm2 + OFF_KH + row * QPITCH + c * 16) = *(const uint4*)(KPH + g);
        }
        __syncthreads();

        float acc[2][2][4];
#pragma unroll
        for (int mi = 0; mi < 2; mi++)
#pragma unroll
            for (int ni = 0; ni < 2; ni++)
#pragma unroll
                for (int v = 0; v < 4; v++) acc[mi][ni][v] = 0.0f;

#pragma unroll
        for (int ks = 0; ks < 8; ks++) {
            const int kb = ks * 32;
            uint32_t ah[2][4], al[2][4], bhf[2][2];
#pragma unroll
            for (int mi = 0; mi < 2; mi++)
                ldsm_x4(ah[mi][0], ah[mi][1], ah[mi][2], ah[mi][3],
                        sb + OFF_QH + (wm * 32 + mi * 16 + r16) * QPITCH + kb + khalfA);
#pragma unroll
            for (int ni = 0; ni < 2; ni++)
                ldsm_x2(bhf[ni][0], bhf[ni][1],
                        sb + OFF_KH + (wn * 16 + ni * 8 + r8) * QPITCH + kb + khalfB);
#pragma unroll
            for (int mi = 0; mi < 2; mi++)
#pragma unroll
                for (int ni = 0; ni < 2; ni++)
                    mma16816(acc[mi][ni], ah[mi], bhf[ni]);
#pragma unroll
            for (int mi = 0; mi < 2; mi++)
                ldsm_x4(al[mi][0], al[mi][1], al[mi][2], al[mi][3],
                        sb + OFF_QL + (wm * 32 + mi * 16 + r16) * QPITCH + kb + khalfA);
#pragma unroll
            for (int mi = 0; mi < 2; mi++)
#pragma unroll
                for (int ni = 0; ni < 2; ni++)
                    mma16816(acc[mi][ni], al[mi], bhf[ni]);
        }

#pragma unroll
        for (int mi = 0; mi < 2; mi++) {
            int row = wm * 32 + mi * 16 + (lane >> 2);
#pragma unroll
            for (int ni = 0; ni < 2; ni++) {
                int col = kt * 64 + wn * 16 + ni * 8 + 2 * (lane & 3);
                Ssf[row * SPITCH + col]           = acc[mi][ni][0] * scale;
                Ssf[row * SPITCH + col + 1]       = acc[mi][ni][1] * scale;
                Ssf[(row + 8) * SPITCH + col]     = acc[mi][ni][2] * scale;
                Ssf[(row + 8) * SPITCH + col + 1] = acc[mi][ni][3] * scale;
            }
        }
    }
    __syncthreads();

    {
        int row  = tid >> 2;
        int part = tid & 3;
        float* srow = Ssf + row * SPITCH;
        float mx = -1e30f;
#pragma unroll 4
        for (int k2 = 0; k2 < 128; k2++)
            mx = fmaxf(mx, srow[part + k2 * 4]);
        mx = fmaxf(mx, __shfl_xor_sync(0xffffffffu, mx, 1));
        mx = fmaxf(mx, __shfl_xor_sync(0xffffffffu, mx, 2));
        float sum = 0.0f;
#pragma unroll 4
        for (int k2 = 0; k2 < 128; k2++) {
            float e = __expf(srow[part + k2 * 4] - mx);
            srow[part + k2 * 4] = e;
            sum += e;
        }
        sum += __shfl_xor_sync(0xffffffffu, sum, 1);
        sum += __shfl_xor_sync(0xffffffffu, sum, 2);
        float inv = 1.0f / sum;
#pragma unroll 4
        for (int k2 = 0; k2 < 128; k2++)
            srow[part + k2 * 4] *= inv;
    }

    float accO[2][2][4];
#pragma unroll
    for (int mi = 0; mi < 2; mi++)
#pragma unroll
        for (int ni = 0; ni < 2; ni++)
#pragma unroll
            for (int v = 0; v < 4; v++) accO[mi][ni][v] = 0.0f;

    const size_t vbase = (size_t)bh * SEQLEN * 64;
    for (int kt = 0; kt < 8; kt++) {
        __syncthreads();
#pragma unroll
        for (int j = 0; j < 2; j++) {
            int idx = tid + j * 256;
            int key = idx >> 3, dg = idx & 7;
            size_t g = vbase + (size_t)(kt * 64 + key) * 64 + dg * 8;
            uint4 vh = *(const uint4*)(VPH + g);
            const uint16_t* ph = (const uint16_t*)&vh;
#pragma unroll
            for (int jj = 0; jj < 8; jj++)
                *(uint16_t*)(sm2 + OFF_VH + (dg * 8 + jj) * VPITCH + key * 2) = ph[jj];
        }
        __syncthreads();

#pragma unroll
        for (int ks = 0; ks < 4; ks++) {
            uint32_t ph_[2][4], pl_[2][4];
#pragma unroll
            for (int mi = 0; mi < 2; mi++) {
                int r  = wm * 32 + mi * 16 + (lane >> 2);
                int kc = kt * 64 + ks * 16 + 2 * (lane & 3);
                f2_hilo_h(*(float2*)&Ssf[r * SPITCH + kc],           ph_[mi][0], pl_[mi][0]);
                f2_hilo_h(*(float2*)&Ssf[(r + 8) * SPITCH + kc],     ph_[mi][1], pl_[mi][1]);
                f2_hilo_h(*(float2*)&Ssf[r * SPITCH + kc + 8],       ph_[mi][2], pl_[mi][2]);
                f2_hilo_h(*(float2*)&Ssf[(r + 8) * SPITCH + kc + 8], ph_[mi][3], pl_[mi][3]);
            }
            uint32_t vh_[2][2];
#pragma unroll
            for (int ni = 0; ni < 2; ni++) {
                uint32_t a = sb + OFF_VH + (wn * 16 + ni * 8 + r8) * VPITCH + ks * 32 + khalfB;
                ldsm_x2(vh_[ni][0], vh_[ni][1], a);
            }
#pragma unroll
            for (int mi = 0; mi < 2; mi++)
#pragma unroll
                for (int ni = 0; ni < 2; ni++) {
                    mma16816(accO[mi][ni], ph_[mi], vh_[ni]);
                    mma16816(accO[mi][ni], pl_[mi], vh_[ni]);
                }
        }
    }

#pragma unroll
    for (int mi = 0; mi < 2; mi++) {
        int rloc = wm * 32 + mi * 16 + (lane >> 2);
        int tok  = b * SEQLEN + q0 + rloc;
#pragma unroll
        for (int ni = 0; ni < 2; ni++) {
            int col = wn * 16 + ni * 8 + 2 * (lane & 3);
            float v00 = accO[mi][ni][0], v01 = accO[mi][ni][1];
            float v10 = accO[mi][ni][2], v11 = accO[mi][ni][3];
            __half2 h0 = __floats2half2_rn(v00, v01);
            __half2 l0 = __floats2half2_rn(v00 - __low2float(h0),
                                           v01 - __high2float(h0));
            __half2 h1 = __floats2half2_rn(v10, v11);
            __half2 l1 = __floats2half2_rn(v10 - __low2float(h1),
                                           v11 - __high2float(h1));
            *(__half2*)(aoH + (size_t)tok * UPDIM + hh * 64 + col) = h0;
            *(__half2*)(aoL + (size_t)tok * UPDIM + hh * 64 + col) = l0;
            *(__half2*)(aoH + (size_t)(tok + 8) * UPDIM + hh * 64 + col) = h1;
            *(__half2*)(aoL + (size_t)(tok + 8) * UPDIM + hh * 64 + col) = l1;
        }
    }
}

// ---------------------------------------------------------------------------
extern "C" void kernel_launch(void* const* d_in, const int* in_sizes, int n_in,
                              void* d_out, int out_size)
{
    const float* h    = (const float*)d_in[0];
    const float* Wdkv = (const float*)d_in[1];
    const float* bdkv = (const float*)d_in[2];
    const float* Wuk  = (const float*)d_in[3];
    const float* buk  = (const float*)d_in[4];
    const float* Wuv  = (const float*)d_in[5];
    const float* buv  = (const float*)d_in[6];
    const float* Wdq  = (const float*)d_in[7];
    const float* bdq  = (const float*)d_in[8];
    const float* Wuq  = (const float*)d_in[9];
    const float* buq  = (const float*)d_in[10];
    const float* Wqr  = (const float*)d_in[11];
    const float* bqr  = (const float*)d_in[12];
    const float* Wkr  = (const float*)d_in[13];
    const float* bkr  = (const float*)d_in[14];
    const float* Wfc  = (const float*)d_in[15];
    const float* bfc  = (const float*)d_in[16];
    float* out = (float*)d_out;

    __half *hH, *hL, *cH, *cL, *aoH, *aoL;
    float *bdown, *bkv, *bqq;
    __half *Wdown16, *Wkv16, *Wqq16, *Wfc16;
    __half *QPH, *QPL, *KPH, *VPH;
    cudaGetSymbolAddress((void**)&hH,      g_hH);
    cudaGetSymbolAddress((void**)&hL,      g_hL);
    cudaGetSymbolAddress((void**)&cH,      g_cH);
    cudaGetSymbolAddress((void**)&cL,      g_cL);
    cudaGetSymbolAddress((void**)&aoH,     g_aoH);
    cudaGetSymbolAddress((void**)&aoL,     g_aoL);
    cudaGetSymbolAddress((void**)&Wdown16, g_Wdown16);
    cudaGetSymbolAddress((void**)&Wkv16,   g_Wkv16);
    cudaGetSymbolAddress((void**)&Wqq16,   g_Wqq16);
    cudaGetSymbolAddress((void**)&Wfc16,   g_Wfc16);
    cudaGetSymbolAddress((void**)&bdown,   g_bdown);
    cudaGetSymbolAddress((void**)&bkv,     g_bkv);
    cudaGetSymbolAddress((void**)&bqq,     g_bqq);
    cudaGetSymbolAddress((void**)&QPH,     g_QPH);
    cudaGetSymbolAddress((void**)&QPL,     g_QPL);
    cudaGetSymbolAddress((void**)&KPH,     g_KPH);
    cudaGetSymbolAddress((void**)&VPH,     g_VPH);

    cudaFuncSetAttribute(attn2_kernel,
                         cudaFuncAttributeMaxDynamicSharedMemorySize, ATTN2_SMEM);
    cudaFuncSetAttribute(tgemm_kernel,
                         cudaFuncAttributeMaxDynamicSharedMemorySize, GT_SMEM);

    // prep
    split_kernel<<<TOK * DMODEL / 2 / 256, 256>>>(h, hH, hL, TOK * DMODEL / 2);
    wconv_all_kernel<<<(WB7 + 255) / 256, 256>>>(Wdkv, Wdq, Wkr, Wuk, Wuv, Wuq,
                                                 Wqr, Wfc, Wdown16, Wkv16,
                                                 Wqq16, Wfc16);
    bias_concat_kernel<<<21, 256>>>(bdkv, bdq, bkr, buk, buv, buq, bqr,
                                    bdown, bkv, bqq);

    dim3 blk(256);
    // fused down projection: N=1088 (ckv|cq|kr), hi/lo fp16 out
    tgemm_kernel<<<dim3(9, TOK / 128), blk, GT_SMEM>>>(
        hH, hL, Wdown16, bdown, nullptr, cH, cL, NDOWN, DMODEL, DMODEL, 1);

    // k_r rope broadcast
    krope_kernel<<<TOK * 32 / 256, 256>>>(cH, cL, KPH);

    // fused up projections writing packed attention operands directly
    tgemm_kernel<<<dim3(16, TOK / 128), blk, GT_SMEM>>>(
        cH, cL, Wkv16, bkv, nullptr, KPH, VPH, 2048, DOWND, NDOWN, 2);
    tgemm_kernel<<<dim3(16, TOK / 128), blk, GT_SMEM>>>(
        cH + 512, cL + 512, Wqq16, bqq, nullptr, QPH, QPL, 2048, DOWND, NDOWN, 3);

    // attention
    attn2_kernel<<<dim3(SEQLEN / 64, NHEADS, BATCH), blk, ATTN2_SMEM>>>(
        QPH, QPL, KPH, VPH, aoH, aoL);

    // output projection (fp32 out)
    tgemm_kernel<<<dim3(16, TOK / 128), blk, GT_SMEM>>>(
        aoH, aoL, Wfc16, bfc, out, nullptr, nullptr, DMODEL, UPDIM, UPDIM, 0);
}

// round 16
// speedup vs baseline: 4.7214x; 1.1483x over previous
#include <cuda_runtime.h>
#include <cuda_fp16.h>
#include <math.h>
#include <cstdint>

// ===========================================================================
// MLA attention. All GEMMs + attention via mma.sync fp16 2-pass split
// (A = Ah+Al fp16 pair, B single fp16; fp32 accum). GEMMs fused along N.
// 3-stage cp.async pipeline. Pack layouts written by GEMM epilogues.
// Attention: chunked online softmax (4 x 128 keys), 87KB smem -> 2 CTAs/SM.
// ===========================================================================

#define TOK    8192
#define SEQLEN 512
#define DMODEL 2048
#define DOWND  512
#define UPDIM  1024
#define NHEADS 16
#define RDIM   64
#define BATCH  16
#define NBH    (BATCH * NHEADS)
#define NDOWN  1088

// ------------------------------ scratch ------------------------------------
__device__ __half g_hH [TOK * DMODEL];
__device__ __half g_hL [TOK * DMODEL];
__device__ __half g_cH [TOK * NDOWN];
__device__ __half g_cL [TOK * NDOWN];
__device__ __half g_aoH[TOK * UPDIM];
__device__ __half g_aoL[TOK * UPDIM];

__device__ __half g_Wdown16[NDOWN * DMODEL];
__device__ __half g_Wkv16  [2048 * DOWND];
__device__ __half g_Wqq16  [2048 * DOWND];
__device__ __half g_Wfc16  [DMODEL * UPDIM];
__device__ float  g_bdown[NDOWN];
__device__ float  g_bkv  [2048];
__device__ float  g_bqq  [2048];

__device__ __half g_QPH[NBH * SEQLEN * 128];
__device__ __half g_QPL[NBH * SEQLEN * 128];
__device__ __half g_KPH[NBH * SEQLEN * 128];
__device__ __half g_VPH[NBH * SEQLEN * 64];

// ------------------------------ helpers ------------------------------------
__device__ __forceinline__ uint32_t smem_u32(const void* p) {
    uint32_t a;
    asm("{ .reg .u64 t; cvta.to.shared.u64 t, %1; cvt.u32.u64 %0, t; }"
        : "=r"(a) : "l"(p));
    return a;
}
__device__ __forceinline__ void ldsm_x4(uint32_t& r0, uint32_t& r1,
                                        uint32_t& r2, uint32_t& r3,
                                        uint32_t addr) {
    asm volatile("ldmatrix.sync.aligned.m8n8.x4.shared.b16 {%0,%1,%2,%3}, [%4];"
                 : "=r"(r0), "=r"(r1), "=r"(r2), "=r"(r3) : "r"(addr));
}
__device__ __forceinline__ void ldsm_x2(uint32_t& r0, uint32_t& r1,
                                        uint32_t addr) {
    asm volatile("ldmatrix.sync.aligned.m8n8.x2.shared.b16 {%0,%1}, [%2];"
                 : "=r"(r0), "=r"(r1) : "r"(addr));
}
__device__ __forceinline__ void mma16816(float* c, const uint32_t* a,
                                         const uint32_t* b) {
    asm volatile(
        "mma.sync.aligned.m16n8k16.row.col.f32.f16.f16.f32 "
        "{%0,%1,%2,%3}, {%4,%5,%6,%7}, {%8,%9}, {%0,%1,%2,%3};"
        : "+f"(c[0]), "+f"(c[1]), "+f"(c[2]), "+f"(c[3])
        : "r"(a[0]), "r"(a[1]), "r"(a[2]), "r"(a[3]), "r"(b[0]), "r"(b[1]));
}
__device__ __forceinline__ void cp16(uint32_t dst, const void* src, int nbytes) {
    asm volatile("cp.async.cg.shared.global [%0], [%1], 16, %2;"
                 :: "r"(dst), "l"(src), "r"(nbytes));
}
__device__ __forceinline__ void cp_commit() {
    asm volatile("cp.async.commit_group;");
}
template <int N> __device__ __forceinline__ void cp_wait() {
    asm volatile("cp.async.wait_group %0;" :: "n"(N));
}
__device__ __forceinline__ void f2_hilo_h(float2 f, uint32_t& h, uint32_t& l) {
    __half2 hb = __floats2half2_rn(f.x, f.y);
    float rx = f.x - __low2float(hb);
    float ry = f.y - __high2float(hb);
    __half2 lb = __floats2half2_rn(rx, ry);
    h = *(uint32_t*)&hb;
    l = *(uint32_t*)&lb;
}

// ------------------------------ prep kernels -------------------------------
__global__ void split_kernel(const float* __restrict__ x,
                             __half* __restrict__ hi,
                             __half* __restrict__ lo, int n2)
{
    int i = blockIdx.x * blockDim.x + threadIdx.x;
    if (i >= n2) return;
    float2 v = *(const float2*)(x + i * 2);
    __half2 hb = __floats2half2_rn(v.x, v.y);
    float rx = v.x - __low2float(hb);
    float ry = v.y - __high2float(hb);
    __half2 lb = __floats2half2_rn(rx, ry);
    *(__half2*)(hi + i * 2) = hb;
    *(__half2*)(lo + i * 2) = lb;
}

#define WB0 524288u
#define WB1 1048576u
#define WB2 1114112u
#define WB3 1376256u
#define WB4 1638400u
#define WB5 1900544u
#define WB6 2162688u
#define WB7 3211264u

__global__ void wconv_all_kernel(const float* __restrict__ Wdkv,
                                 const float* __restrict__ Wdq,
                                 const float* __restrict__ Wkr,
                                 const float* __restrict__ Wuk,
                                 const float* __restrict__ Wuv,
                                 const float* __restrict__ Wuq,
                                 const float* __restrict__ Wqr,
                                 const float* __restrict__ Wfc,
                                 __half* __restrict__ Wdown16,
                                 __half* __restrict__ Wkv16,
                                 __half* __restrict__ Wqq16,
                                 __half* __restrict__ Wfc16)
{
    uint32_t i = blockIdx.x * 256u + threadIdx.x;
    if (i >= WB7) return;
    const float* src;
    __half* dst;
    uint32_t o;
    if (i < WB1) {
        if (i < WB0) { src = Wdkv; o = i;        dst = Wdown16; }
        else         { src = Wdq;  o = i - WB0;  dst = Wdown16 + 1048576u; }
    } else if (i < WB3) {
        if (i < WB2) { src = Wkr;  o = i - WB1;  dst = Wdown16 + 2097152u; }
        else         { src = Wuk;  o = i - WB2;  dst = Wkv16; }
    } else if (i < WB5) {
        if (i < WB4) { src = Wuv;  o = i - WB3;  dst = Wkv16 + 524288u; }
        else         { src = Wuq;  o = i - WB4;  dst = Wqq16; }
    } else {
        if (i < WB6) { src = Wqr;  o = i - WB5;  dst = Wqq16 + 524288u; }
        else         { src = Wfc;  o = i - WB6;  dst = Wfc16; }
    }
    float2 v = *(const float2*)(src + (size_t)o * 2);
    *(__half2*)(dst + (size_t)o * 2) = __floats2half2_rn(v.x, v.y);
}

__global__ void bias_concat_kernel(const float* __restrict__ bdkv,
                                   const float* __restrict__ bdq,
                                   const float* __restrict__ bkr,
                                   const float* __restrict__ buk,
                                   const float* __restrict__ buv,
                                   const float* __restrict__ buq,
                                   const float* __restrict__ bqr,
                                   float* __restrict__ bdown,
                                   float* __restrict__ bkv,
                                   float* __restrict__ bqq)
{
    int i = blockIdx.x * 256 + threadIdx.x;
    if (i < 512)       bdown[i] = bdkv[i];
    else if (i < 1024) bdown[i] = bdq[i - 512];
    else if (i < 1088) bdown[i] = bkr[i - 1024];
    else if (i < 2112) bkv[i - 1088] = buk[i - 1088];
    else if (i < 3136) bkv[i - 1088] = buv[i - 2112];
    else if (i < 4160) bqq[i - 3136] = buq[i - 3136];
    else if (i < 5184) bqq[i - 3136] = bqr[i - 4160];
}

__global__ void krope_kernel(const __half* __restrict__ cH,
                             const __half* __restrict__ cL,
                             __half* __restrict__ KPH)
{
    int idx = blockIdx.x * 256 + threadIdx.x;
    int pair = idx & 31;
    int tok  = idx >> 5;
    int s = tok & (SEQLEN - 1), b = tok >> 9;
    int rp = pair * 2;
    __half2 vh = *(const __half2*)(cH + (size_t)tok * NDOWN + 1024 + rp);
    __half2 vl = *(const __half2*)(cL + (size_t)tok * NDOWN + 1024 + rp);
    float x0 = __low2float(vh) + __low2float(vl);
    float x1 = __high2float(vh) + __high2float(vl);
    float theta = powf(10000.0f, -(float)pair * (1.0f / 32.0f));
    float sn, cs;
    sincosf((float)s * theta, &sn, &cs);
    __half2 val = __floats2half2_rn(x0 * sn - x1 * cs, x1 * sn + x0 * cs);
#pragma unroll
    for (int h = 0; h < NHEADS; h++)
        *(__half2*)(KPH + (((size_t)(b * NHEADS + h) * SEQLEN + s) * 128) + 64 + rp) = val;
}

// ------------------------------ tensor GEMM --------------------------------
#define ROWB 80
#define TILEB (128 * ROWB)
#define STAGEB (3 * TILEB)
#define GT_SMEM (3 * STAGEB)

__global__ __launch_bounds__(256)
void tgemm_kernel(const __half* __restrict__ Ah,
                  const __half* __restrict__ Al,
                  const __half* __restrict__ Bh,
                  const float* __restrict__ bias,
                  float* __restrict__ C,
                  __half* __restrict__ CH,
                  __half* __restrict__ CL,
                  int N, int K, int lda, int mode)
{
    extern __shared__ __align__(16) char smem[];

    const int tid  = threadIdx.x;
    const int wid  = tid >> 5;
    const int lane = tid & 31;
    const int wm   = wid >> 2;
    const int wn   = wid & 3;
    const int m0   = blockIdx.y * 128;
    const int n0   = blockIdx.x * 128;
    const uint32_t sb = smem_u32(smem);

    const __half* srcs[3] = {Ah, Al, Bh};

    const int lrow0 = tid >> 2;
    const int lq0   = tid & 3;
    const int lrow1 = (tid + 256) >> 2;
    const int lq1   = (tid + 256) & 3;

    float acc[4][4][4];
#pragma unroll
    for (int i = 0; i < 4; i++)
#pragma unroll
        for (int j = 0; j < 4; j++)
#pragma unroll
            for (int v = 0; v < 4; v++) acc[i][j][v] = 0.0f;

    const int r16   = lane & 15;
    const int khalfA = (lane >> 4) * 16;
    const int r8    = lane & 7;
    const int khalfB = ((lane >> 3) & 1) * 16;

    const int nchunks = K >> 5;

    auto issue = [&](int c) {
        const uint32_t stg = sb + (uint32_t)(c % 3) * STAGEB;
        const int k0 = c << 5;
#pragma unroll
        for (int t = 0; t < 3; t++) {
            const bool isB = (t == 2);
            const __half* src = srcs[t];
            const int ld = isB ? K : lda;
            {
                int grow = isB ? (n0 + lrow0) : (m0 + lrow0);
                int ok = (!isB || grow < N) ? 16 : 0;
                if (!ok) grow = n0;
                cp16(stg + t * TILEB + lrow0 * ROWB + lq0 * 16,
                     src + (size_t)grow * ld + k0 + lq0 * 8, ok);
            }
            {
                int grow = isB ? (n0 + lrow1) : (m0 + lrow1);
                int ok = (!isB || grow < N) ? 16 : 0;
                if (!ok) grow = n0;
                cp16(stg + t * TILEB + lrow1 * ROWB + lq1 * 16,
                     src + (size_t)grow * ld + k0 + lq1 * 8, ok);
            }
        }
        cp_commit();
    };

    issue(0);
    if (nchunks > 1) issue(1);

    for (int ci = 0; ci < nchunks; ci++) {
        if (ci + 1 < nchunks) cp_wait<1>(); else cp_wait<0>();
        __syncthreads();
        if (ci + 2 < nchunks) issue(ci + 2);

        const uint32_t cur = sb + (uint32_t)(ci % 3) * STAGEB;
#pragma unroll
        for (int ks = 0; ks < 2; ks++) {
            const int kb = ks * 32;
            uint32_t ah[4][4], al[4][4], bh[4][2];
#pragma unroll
            for (int mi = 0; mi < 4; mi++)
                ldsm_x4(ah[mi][0], ah[mi][1], ah[mi][2], ah[mi][3],
                        cur + 0 * TILEB + (wm * 64 + mi * 16 + r16) * ROWB + kb + khalfA);
#pragma unroll
            for (int ni = 0; ni < 4; ni++)
                ldsm_x2(bh[ni][0], bh[ni][1],
                        cur + 2 * TILEB + (wn * 32 + ni * 8 + r8) * ROWB + kb + khalfB);
#pragma unroll
            for (int mi = 0; mi < 4; mi++)
#pragma unroll
                for (int ni = 0; ni < 4; ni++)
                    mma16816(acc[mi][ni], ah[mi], bh[ni]);

#pragma unroll
            for (int mi = 0; mi < 4; mi++)
                ldsm_x4(al[mi][0], al[mi][1], al[mi][2], al[mi][3],
                        cur + 1 * TILEB + (wm * 64 + mi * 16 + r16) * ROWB + kb + khalfA);
#pragma unroll
            for (int mi = 0; mi < 4; mi++)
#pragma unroll
                for (int ni = 0; ni < 4; ni++)
                    mma16816(acc[mi][ni], al[mi], bh[ni]);
        }
    }

    // ------------------------------ epilogue -------------------------------
#pragma unroll
    for (int mi = 0; mi < 4; mi++) {
        int row0 = m0 + wm * 64 + mi * 16 + (lane >> 2);
#pragma unroll
        for (int ni = 0; ni < 4; ni++) {
            int col = n0 + wn * 32 + ni * 8 + 2 * (lane & 3);
            if (col >= N) continue;
            float2 b2 = *(const float2*)(bias + col);
            float v00 = acc[mi][ni][0] + b2.x, v01 = acc[mi][ni][1] + b2.y;
            float v10 = acc[mi][ni][2] + b2.x, v11 = acc[mi][ni][3] + b2.y;

            if (mode == 0) {
                *(float2*)(C + (size_t)row0 * N + col) = make_float2(v00, v01);
                *(float2*)(C + (size_t)(row0 + 8) * N + col) = make_float2(v10, v11);
            } else if (mode == 1) {
                __half2 h0 = __floats2half2_rn(v00, v01);
                __half2 l0 = __floats2half2_rn(v00 - __low2float(h0),
                                               v01 - __high2float(h0));
                __half2 h1 = __floats2half2_rn(v10, v11);
                __half2 l1 = __floats2half2_rn(v10 - __low2float(h1),
                                               v11 - __high2float(h1));
                *(__half2*)(CH + (size_t)row0 * N + col) = h0;
                *(__half2*)(CL + (size_t)row0 * N + col) = l0;
                *(__half2*)(CH + (size_t)(row0 + 8) * N + col) = h1;
                *(__half2*)(CL + (size_t)(row0 + 8) * N + col) = l1;
            } else if (mode == 2) {
#pragma unroll
                for (int rr = 0; rr < 2; rr++) {
                    int tok = row0 + rr * 8;
                    int b = tok >> 9, s = tok & (SEQLEN - 1);
                    float f0 = rr ? v10 : v00, f1 = rr ? v11 : v01;
                    __half2 hv = __floats2half2_rn(f0, f1);
                    if (col < 1024) {
                        int hh = col >> 6, d = col & 63;
                        *(__half2*)(CH + ((size_t)(b * NHEADS + hh) * SEQLEN + s) * 128 + d) = hv;
                    } else {
                        int hh = (col - 1024) >> 6, d = (col - 1024) & 63;
                        *(__half2*)(CL + ((size_t)(b * NHEADS + hh) * SEQLEN + s) * 64 + d) = hv;
                    }
                }
            } else {
#pragma unroll
                for (int rr = 0; rr < 2; rr++) {
                    int tok = row0 + rr * 8;
                    int b = tok >> 9, s = tok & (SEQLEN - 1);
                    float f0 = rr ? v10 : v00, f1 = rr ? v11 : v01;
                    int hh, dd;
                    if (col < 1024) {
                        hh = col >> 6;
                        dd = col & 63;
                    } else {
                        hh = (col - 1024) >> 6;
                        int rp = (col - 1024) & 63;
                        int pair = rp >> 1;
                        float theta = powf(10000.0f, -(float)pair * (1.0f / 32.0f));
                        float sn, cs;
                        sincosf((float)s * theta, &sn, &cs);
                        float t0 = f0 * sn - f1 * cs;
                        float t1 = f1 * sn + f0 * cs;
                        f0 = t0; f1 = t1;
                        dd = 64 + rp;
                    }
                    uint32_t hi, lo;
                    f2_hilo_h(make_float2(f0, f1), hi, lo);
                    size_t base = ((size_t)(b * NHEADS + hh) * SEQLEN + s) * 128 + dd;
                    *(uint32_t*)(CH + base) = hi;
                    *(uint32_t*)(CL + base) = lo;
                }
            }
        }
    }
}

// ------------------------------ attention (chunked online softmax) ---------
// CTA: 64 q x 512 keys, processed in 4 chunks of 128 keys.
#define QPITCH 272
#define VPITCH 144
#define SP2    132
#define OFF_QH 0
#define OFF_QL 17408
#define OFF_KV 34816
#define OFF_S  52224
#define OFF_M  86016
#define OFF_L  (OFF_M + 256)
#define OFF_CR (OFF_M + 512)
#define ATTN2_SMEM (OFF_M + 768)

__global__ __launch_bounds__(256)
void attn2_kernel(const __half* __restrict__ QPH,
                  const __half* __restrict__ QPL,
                  const __half* __restrict__ KPH,
                  const __half* __restrict__ VPH,
                  __half* __restrict__ aoH,
                  __half* __restrict__ aoL)
{
    extern __shared__ char sm2[];
    const uint32_t sb = smem_u32(sm2);
    float* Ssf = (float*)(sm2 + OFF_S);
    float* Sm  = (float*)(sm2 + OFF_M);
    float* Sl  = (float*)(sm2 + OFF_L);
    float* Scr = (float*)(sm2 + OFF_CR);

    const int tid  = threadIdx.x;
    const int wid  = tid >> 5;
    const int lane = tid & 31;
    const int wm = wid >> 2;
    const int wn = wid & 3;
    const int q0 = blockIdx.x * 64;
    const int hh = blockIdx.y;
    const int b  = blockIdx.z;
    const int bh = b * NHEADS + hh;
    const size_t pbase = (size_t)bh * SEQLEN * 128;
    const size_t vbase = (size_t)bh * SEQLEN * 64;
    const float scale = 0.07216878364870322f;   // 1/sqrt(192)

    const int r16 = lane & 15;
    const int khalfA = (lane >> 4) * 16;
    const int r8 = lane & 7;
    const int khalfB = ((lane >> 3) & 1) * 16;

    // load Q (64 x 128) hi+lo
#pragma unroll
    for (int j = 0; j < 4; j++) {
        int idx = tid + j * 256;
        int row = idx >> 4, c = idx & 15;
        size_t g = pbase + (size_t)(q0 + row) * 128 + c * 8;
        *(uint4*)(sm2 + OFF_QH + row * QPITCH + c * 16) = *(const uint4*)(QPH + g);
        *(uint4*)(sm2 + OFF_QL + row * QPITCH + c * 16) = *(const uint4*)(QPL + g);
    }
    if (tid < 64) { Sm[tid] = -1e30f; Sl[tid] = 0.0f; }

    float accO[2][2][4];
#pragma unroll
    for (int mi = 0; mi < 2; mi++)
#pragma unroll
        for (int ni = 0; ni < 2; ni++)
#pragma unroll
            for (int v = 0; v < 4; v++) accO[mi][ni][v] = 0.0f;

    for (int ck = 0; ck < 4; ck++) {
        // ---- QK for 2 key tiles of 64 ----
#pragma unroll
        for (int v = 0; v < 2; v++) {
            __syncthreads();
            const int ktile = ck * 2 + v;
#pragma unroll
            for (int j = 0; j < 4; j++) {
                int idx = tid + j * 256;
                int row = idx >> 4, c = idx & 15;
                size_t g = pbase + (size_t)(ktile * 64 + row) * 128 + c * 8;
                *(uint4*)(sm2 + OFF_KV + row * QPITCH + c * 16) = *(const uint4*)(KPH + g);
            }
            __syncthreads();

            float acc[2][2][4];
#pragma unroll
            for (int mi = 0; mi < 2; mi++)
#pragma unroll
                for (int ni = 0; ni < 2; ni++)
#pragma unroll
                    for (int vv = 0; vv < 4; vv++) acc[mi][ni][vv] = 0.0f;

#pragma unroll
            for (int ks = 0; ks < 8; ks++) {
                const int kb = ks * 32;
                uint32_t ah[2][4], al[2][4], bhf[2][2];
#pragma unroll
                for (int mi = 0; mi < 2; mi++)
                    ldsm_x4(ah[mi][0], ah[mi][1], ah[mi][2], ah[mi][3],
                            sb + OFF_QH + (wm * 32 + mi * 16 + r16) * QPITCH + kb + khalfA);
#pragma unroll
                for (int ni = 0; ni < 2; ni++)
                    ldsm_x2(bhf[ni][0], bhf[ni][1],
                            sb + OFF_KV + (wn * 16 + ni * 8 + r8) * QPITCH + kb + khalfB);
#pragma unroll
                for (int mi = 0; mi < 2; mi++)
#pragma unroll
                    for (int ni = 0; ni < 2; ni++)
                        mma16816(acc[mi][ni], ah[mi], bhf[ni]);
#pragma unroll
                for (int mi = 0; mi < 2; mi++)
                    ldsm_x4(al[mi][0], al[mi][1], al[mi][2], al[mi][3],
                            sb + OFF_QL + (wm * 32 + mi * 16 + r16) * QPITCH + kb + khalfA);
#pragma unroll
                for (int mi = 0; mi < 2; mi++)
#pragma unroll
                    for (int ni = 0; ni < 2; ni++)
                        mma16816(acc[mi][ni], al[mi], bhf[ni]);
            }

#pragma unroll
            for (int mi = 0; mi < 2; mi++) {
                int row = wm * 32 + mi * 16 + (lane >> 2);
#pragma unroll
                for (int ni = 0; ni < 2; ni++) {
                    int col = v * 64 + wn * 16 + ni * 8 + 2 * (lane & 3);
                    Ssf[row * SP2 + col]           = acc[mi][ni][0] * scale;
                    Ssf[row * SP2 + col + 1]       = acc[mi][ni][1] * scale;
                    Ssf[(row + 8) * SP2 + col]     = acc[mi][ni][2] * scale;
                    Ssf[(row + 8) * SP2 + col + 1] = acc[mi][ni][3] * scale;
                }
            }
        }
        __syncthreads();

        // ---- online softmax update over this 128-key chunk ----
        {
            int row  = tid >> 2;
            int part = tid & 3;
            float* srow = Ssf + row * SP2;
            float mx = -1e30f;
#pragma unroll 4
            for (int k2 = 0; k2 < 32; k2++)
                mx = fmaxf(mx, srow[part + k2 * 4]);
            mx = fmaxf(mx, __shfl_xor_sync(0xffffffffu, mx, 1));
            mx = fmaxf(mx, __shfl_xor_sync(0xffffffffu, mx, 2));
            float mo = Sm[row];
            float mn = fmaxf(mo, mx);
            float corr = __expf(mo - mn);
            float sum = 0.0f;
#pragma unroll 4
            for (int k2 = 0; k2 < 32; k2++) {
                float e = __expf(srow[part + k2 * 4] - mn);
                srow[part + k2 * 4] = e;
                sum += e;
            }
            sum += __shfl_xor_sync(0xffffffffu, sum, 1);
            sum += __shfl_xor_sync(0xffffffffu, sum, 2);
            if (part == 0) {
                Sm[row] = mn;
                Sl[row] = Sl[row] * corr + sum;
                Scr[row] = corr;
            }
        }
        __syncthreads();

        // ---- rescale O accumulators ----
#pragma unroll
        for (int mi = 0; mi < 2; mi++) {
            int r0 = wm * 32 + mi * 16 + (lane >> 2);
            float c0 = Scr[r0], c1 = Scr[r0 + 8];
#pragma unroll
            for (int ni = 0; ni < 2; ni++) {
                accO[mi][ni][0] *= c0;
                accO[mi][ni][1] *= c0;
                accO[mi][ni][2] *= c1;
                accO[mi][ni][3] *= c1;
            }
        }

        // ---- PV for the 2 key tiles of this chunk ----
#pragma unroll
        for (int v = 0; v < 2; v++) {
            if (v) __syncthreads();
            const int ktile = ck * 2 + v;
#pragma unroll
            for (int j = 0; j < 2; j++) {
                int idx = tid + j * 256;
                int key = idx >> 3, dg = idx & 7;
                size_t g = vbase + (size_t)(ktile * 64 + key) * 64 + dg * 8;
                uint4 vh = *(const uint4*)(VPH + g);
                const uint16_t* ph = (const uint16_t*)&vh;
#pragma unroll
                for (int jj = 0; jj < 8; jj++)
                    *(uint16_t*)(sm2 + OFF_KV + (dg * 8 + jj) * VPITCH + key * 2) = ph[jj];
            }
            __syncthreads();

#pragma unroll
            for (int ks = 0; ks < 4; ks++) {
                uint32_t ph_[2][4], pl_[2][4];
#pragma unroll
                for (int mi = 0; mi < 2; mi++) {
                    int r  = wm * 32 + mi * 16 + (lane >> 2);
                    int kc = v * 64 + ks * 16 + 2 * (lane & 3);
                    f2_hilo_h(*(float2*)&Ssf[r * SP2 + kc],           ph_[mi][0], pl_[mi][0]);
                    f2_hilo_h(*(float2*)&Ssf[(r + 8) * SP2 + kc],     ph_[mi][1], pl_[mi][1]);
                    f2_hilo_h(*(float2*)&Ssf[r * SP2 + kc + 8],       ph_[mi][2], pl_[mi][2]);
                    f2_hilo_h(*(float2*)&Ssf[(r + 8) * SP2 + kc + 8], ph_[mi][3], pl_[mi][3]);
                }
                uint32_t vh_[2][2];
#pragma unroll
                for (int ni = 0; ni < 2; ni++) {
                    uint32_t a = sb + OFF_KV + (wn * 16 + ni * 8 + r8) * VPITCH + ks * 32 + khalfB;
                    ldsm_x2(vh_[ni][0], vh_[ni][1], a);
                }
#pragma unroll
                for (int mi = 0; mi < 2; mi++)
#pragma unroll
                    for (int ni = 0; ni < 2; ni++) {
                        mma16816(accO[mi][ni], ph_[mi], vh_[ni]);
                        mma16816(accO[mi][ni], pl_[mi], vh_[ni]);
                    }
            }
        }
    }

    // ---- epilogue: normalize by l, hi/lo split, store ----
#pragma unroll
    for (int mi = 0; mi < 2; mi++) {
        int rloc = wm * 32 + mi * 16 + (lane >> 2);
        int tok  = b * SEQLEN + q0 + rloc;
        float inv0 = 1.0f / Sl[rloc];
        float inv1 = 1.0f / Sl[rloc + 8];
#pragma unroll
        for (int ni = 0; ni < 2; ni++) {
            int col = wn * 16 + ni * 8 + 2 * (lane & 3);
            float v00 = accO[mi][ni][0] * inv0, v01 = accO[mi][ni][1] * inv0;
            float v10 = accO[mi][ni][2] * inv1, v11 = accO[mi][ni][3] * inv1;
            __half2 h0 = __floats2half2_rn(v00, v01);
            __half2 l0 = __floats2half2_rn(v00 - __low2float(h0),
                                           v01 - __high2float(h0));
            __half2 h1 = __floats2half2_rn(v10, v11);
            __half2 l1 = __floats2half2_rn(v10 - __low2float(h1),
                                           v11 - __high2float(h1));
            *(__half2*)(aoH + (size_t)tok * UPDIM + hh * 64 + col) = h0;
            *(__half2*)(aoL + (size_t)tok * UPDIM + hh * 64 + col) = l0;
            *(__half2*)(aoH + (size_t)(tok + 8) * UPDIM + hh * 64 + col) = h1;
            *(__half2*)(aoL + (size_t)(tok + 8) * UPDIM + hh * 64 + col) = l1;
        }
    }
}

// ---------------------------------------------------------------------------
extern "C" void kernel_launch(void* const* d_in, const int* in_sizes, int n_in,
                              void* d_out, int out_size)
{
    const float* h    = (const float*)d_in[0];
    const float* Wdkv = (const float*)d_in[1];
    const float* bdkv = (const float*)d_in[2];
    const float* Wuk  = (const float*)d_in[3];
    const float* buk  = (const float*)d_in[4];
    const float* Wuv  = (const float*)d_in[5];
    const float* buv  = (const float*)d_in[6];
    const float* Wdq  = (const float*)d_in[7];
    const float* bdq  = (const float*)d_in[8];
    const float* Wuq  = (const float*)d_in[9];
    const float* buq  = (const float*)d_in[10];
    const float* Wqr  = (const float*)d_in[11];
    const float* bqr  = (const float*)d_in[12];
    const float* Wkr  = (const float*)d_in[13];
    const float* bkr  = (const float*)d_in[14];
    const float* Wfc  = (const float*)d_in[15];
    const float* bfc  = (const float*)d_in[16];
    float* out = (float*)d_out;

    __half *hH, *hL, *cH, *cL, *aoH, *aoL;
    float *bdown, *bkv, *bqq;
    __half *Wdown16, *Wkv16, *Wqq16, *Wfc16;
    __half *QPH, *QPL, *KPH, *VPH;
    cudaGetSymbolAddress((void**)&hH,      g_hH);
    cudaGetSymbolAddress((void**)&hL,      g_hL);
    cudaGetSymbolAddress((void**)&cH,      g_cH);
    cudaGetSymbolAddress((void**)&cL,      g_cL);
    cudaGetSymbolAddress((void**)&aoH,     g_aoH);
    cudaGetSymbolAddress((void**)&aoL,     g_aoL);
    cudaGetSymbolAddress((void**)&Wdown16, g_Wdown16);
    cudaGetSymbolAddress((void**)&Wkv16,   g_Wkv16);
    cudaGetSymbolAddress((void**)&Wqq16,   g_Wqq16);
    cudaGetSymbolAddress((void**)&Wfc16,   g_Wfc16);
    cudaGetSymbolAddress((void**)&bdown,   g_bdown);
    cudaGetSymbolAddress((void**)&bkv,     g_bkv);
    cudaGetSymbolAddress((void**)&bqq,     g_bqq);
    cudaGetSymbolAddress((void**)&QPH,     g_QPH);
    cudaGetSymbolAddress((void**)&QPL,     g_QPL);
    cudaGetSymbolAddress((void**)&KPH,     g_KPH);
    cudaGetSymbolAddress((void**)&VPH,     g_VPH);

    cudaFuncSetAttribute(attn2_kernel,
                         cudaFuncAttributeMaxDynamicSharedMemorySize, ATTN2_SMEM);
    cudaFuncSetAttribute(tgemm_kernel,
                         cudaFuncAttributeMaxDynamicSharedMemorySize, GT_SMEM);

    // prep
    split_kernel<<<TOK * DMODEL / 2 / 256, 256>>>(h, hH, hL, TOK * DMODEL / 2);
    wconv_all_kernel<<<(WB7 + 255) / 256, 256>>>(Wdkv, Wdq, Wkr, Wuk, Wuv, Wuq,
                                                 Wqr, Wfc, Wdown16, Wkv16,
                                                 Wqq16, Wfc16);
    bias_concat_kernel<<<21, 256>>>(bdkv, bdq, bkr, buk, buv, buq, bqr,
                                    bdown, bkv, bqq);

    dim3 blk(256);
    // fused down projection: N=1088 (ckv|cq|kr), hi/lo fp16 out
    tgemm_kernel<<<dim3(9, TOK / 128), blk, GT_SMEM>>>(
        hH, hL, Wdown16, bdown, nullptr, cH, cL, NDOWN, DMODEL, DMODEL, 1);

    // k_r rope broadcast
    krope_kernel<<<TOK * 32 / 256, 256>>>(cH, cL, KPH);

    // fused up projections writing packed attention operands directly
    tgemm_kernel<<<dim3(16, TOK / 128), blk, GT_SMEM>>>(
        cH, cL, Wkv16, bkv, nullptr, KPH, VPH, 2048, DOWND, NDOWN, 2);
    tgemm_kernel<<<dim3(16, TOK / 128), blk, GT_SMEM>>>(
        cH + 512, cL + 512, Wqq16, bqq, nullptr, QPH, QPL, 2048, DOWND, NDOWN, 3);

    // attention
    attn2_kernel<<<dim3(SEQLEN / 64, NHEADS, BATCH), blk, ATTN2_SMEM>>>(
        QPH, QPL, KPH, VPH, aoH, aoL);

    // output projection (fp32 out)
    tgemm_kernel<<<dim3(16, TOK / 128), blk, GT_SMEM>>>(
        aoH, aoL, Wfc16, bfc, out, nullptr, nullptr, DMODEL, UPDIM, UPDIM, 0);
}

// round 17
// speedup vs baseline: 6.8469x; 1.4502x over previous
#include <cuda_runtime.h>
#include <cuda_fp16.h>
#include <math.h>
#include <cstdint>

// ===========================================================================
// MLA attention. All GEMMs + attention via single-pass fp16 mma.sync
// (fp32 accumulate). GEMMs fused along N; pack layouts (rope fused) written
// by GEMM epilogues. 3-stage cp.async pipeline. Chunked online-softmax attn.
// ===========================================================================

#define TOK    8192
#define SEQLEN 512
#define DMODEL 2048
#define DOWND  512
#define UPDIM  1024
#define NHEADS 16
#define RDIM   64
#define BATCH  16
#define NBH    (BATCH * NHEADS)
#define NDOWN  1088

// ------------------------------ scratch ------------------------------------
__device__ __half g_h16 [TOK * DMODEL];
__device__ __half g_c16 [TOK * NDOWN];
__device__ __half g_ao16[TOK * UPDIM];

__device__ __half g_Wdown16[NDOWN * DMODEL];
__device__ __half g_Wkv16  [2048 * DOWND];
__device__ __half g_Wqq16  [2048 * DOWND];
__device__ __half g_Wfc16  [DMODEL * UPDIM];
__device__ float  g_bdown[NDOWN];
__device__ float  g_bkv  [2048];
__device__ float  g_bqq  [2048];

__device__ __half g_QPH[NBH * SEQLEN * 128];
__device__ __half g_KPH[NBH * SEQLEN * 128];
__device__ __half g_VPH[NBH * SEQLEN * 64];

// ------------------------------ helpers ------------------------------------
__device__ __forceinline__ uint32_t smem_u32(const void* p) {
    uint32_t a;
    asm("{ .reg .u64 t; cvta.to.shared.u64 t, %1; cvt.u32.u64 %0, t; }"
        : "=r"(a) : "l"(p));
    return a;
}
__device__ __forceinline__ void ldsm_x4(uint32_t& r0, uint32_t& r1,
                                        uint32_t& r2, uint32_t& r3,
                                        uint32_t addr) {
    asm volatile("ldmatrix.sync.aligned.m8n8.x4.shared.b16 {%0,%1,%2,%3}, [%4];"
                 : "=r"(r0), "=r"(r1), "=r"(r2), "=r"(r3) : "r"(addr));
}
__device__ __forceinline__ void ldsm_x2(uint32_t& r0, uint32_t& r1,
                                        uint32_t addr) {
    asm volatile("ldmatrix.sync.aligned.m8n8.x2.shared.b16 {%0,%1}, [%2];"
                 : "=r"(r0), "=r"(r1) : "r"(addr));
}
__device__ __forceinline__ void mma16816(float* c, const uint32_t* a,
                                         const uint32_t* b) {
    asm volatile(
        "mma.sync.aligned.m16n8k16.row.col.f32.f16.f16.f32 "
        "{%0,%1,%2,%3}, {%4,%5,%6,%7}, {%8,%9}, {%0,%1,%2,%3};"
        : "+f"(c[0]), "+f"(c[1]), "+f"(c[2]), "+f"(c[3])
        : "r"(a[0]), "r"(a[1]), "r"(a[2]), "r"(a[3]), "r"(b[0]), "r"(b[1]));
}
__device__ __forceinline__ void cp16(uint32_t dst, const void* src, int nbytes) {
    asm volatile("cp.async.cg.shared.global [%0], [%1], 16, %2;"
                 :: "r"(dst), "l"(src), "r"(nbytes));
}
__device__ __forceinline__ void cp_commit() {
    asm volatile("cp.async.commit_group;");
}
template <int N> __device__ __forceinline__ void cp_wait() {
    asm volatile("cp.async.wait_group %0;" :: "n"(N));
}

// ------------------------------ prep kernels -------------------------------
__global__ void conv_kernel(const float* __restrict__ x,
                            __half* __restrict__ o, int n2)
{
    int i = blockIdx.x * blockDim.x + threadIdx.x;
    if (i >= n2) return;
    float2 v = *(const float2*)(x + i * 2);
    *(__half2*)(o + i * 2) = __floats2half2_rn(v.x, v.y);
}

#define WB0 524288u
#define WB1 1048576u
#define WB2 1114112u
#define WB3 1376256u
#define WB4 1638400u
#define WB5 1900544u
#define WB6 2162688u
#define WB7 3211264u

__global__ void wconv_all_kernel(const float* __restrict__ Wdkv,
                                 const float* __restrict__ Wdq,
                                 const float* __restrict__ Wkr,
                                 const float* __restrict__ Wuk,
                                 const float* __restrict__ Wuv,
                                 const float* __restrict__ Wuq,
                                 const float* __restrict__ Wqr,
                                 const float* __restrict__ Wfc,
                                 __half* __restrict__ Wdown16,
                                 __half* __restrict__ Wkv16,
                                 __half* __restrict__ Wqq16,
                                 __half* __restrict__ Wfc16)
{
    uint32_t i = blockIdx.x * 256u + threadIdx.x;
    if (i >= WB7) return;
    const float* src;
    __half* dst;
    uint32_t o;
    if (i < WB1) {
        if (i < WB0) { src = Wdkv; o = i;        dst = Wdown16; }
        else         { src = Wdq;  o = i - WB0;  dst = Wdown16 + 1048576u; }
    } else if (i < WB3) {
        if (i < WB2) { src = Wkr;  o = i - WB1;  dst = Wdown16 + 2097152u; }
        else         { src = Wuk;  o = i - WB2;  dst = Wkv16; }
    } else if (i < WB5) {
        if (i < WB4) { src = Wuv;  o = i - WB3;  dst = Wkv16 + 524288u; }
        else         { src = Wuq;  o = i - WB4;  dst = Wqq16; }
    } else {
        if (i < WB6) { src = Wqr;  o = i - WB5;  dst = Wqq16 + 524288u; }
        else         { src = Wfc;  o = i - WB6;  dst = Wfc16; }
    }
    float2 v = *(const float2*)(src + (size_t)o * 2);
    *(__half2*)(dst + (size_t)o * 2) = __floats2half2_rn(v.x, v.y);
}

__global__ void bias_concat_kernel(const float* __restrict__ bdkv,
                                   const float* __restrict__ bdq,
                                   const float* __restrict__ bkr,
                                   const float* __restrict__ buk,
                                   const float* __restrict__ buv,
                                   const float* __restrict__ buq,
                                   const float* __restrict__ bqr,
                                   float* __restrict__ bdown,
                                   float* __restrict__ bkv,
                                   float* __restrict__ bqq)
{
    int i = blockIdx.x * 256 + threadIdx.x;
    if (i < 512)       bdown[i] = bdkv[i];
    else if (i < 1024) bdown[i] = bdq[i - 512];
    else if (i < 1088) bdown[i] = bkr[i - 1024];
    else if (i < 2112) bkv[i - 1088] = buk[i - 1088];
    else if (i < 3136) bkv[i - 1088] = buv[i - 2112];
    else if (i < 4160) bqq[i - 3136] = buq[i - 3136];
    else if (i < 5184) bqq[i - 3136] = bqr[i - 4160];
}

__global__ void krope_kernel(const __half* __restrict__ c16,
                             __half* __restrict__ KPH)
{
    int idx = blockIdx.x * 256 + threadIdx.x;
    int pair = idx & 31;
    int tok  = idx >> 5;
    int s = tok & (SEQLEN - 1), b = tok >> 9;
    int rp = pair * 2;
    __half2 vh = *(const __half2*)(c16 + (size_t)tok * NDOWN + 1024 + rp);
    float x0 = __low2float(vh);
    float x1 = __high2float(vh);
    float theta = powf(10000.0f, -(float)pair * (1.0f / 32.0f));
    float sn, cs;
    sincosf((float)s * theta, &sn, &cs);
    __half2 val = __floats2half2_rn(x0 * sn - x1 * cs, x1 * sn + x0 * cs);
#pragma unroll
    for (int h = 0; h < NHEADS; h++)
        *(__half2*)(KPH + (((size_t)(b * NHEADS + h) * SEQLEN + s) * 128) + 64 + rp) = val;
}

// ------------------------------ tensor GEMM --------------------------------
// C(M,N) = A(M x K fp16, pitch lda) @ Bh^T(N,K) + bias. Single MMA pass.
// CTA 128x128, K-chunk 32, 8 warps, warp tile 64x32, 3-stage cp.async.
// mode 0: fp32 C.  mode 1: fp16 CH row-major.
// mode 2: kv pack (CH=KPH content, CL=VPH).  mode 3: qq pack (CH=QPH, rope).
#define ROWB 80
#define TILEB (128 * ROWB)
#define STAGEB (2 * TILEB)
#define GT_SMEM (3 * STAGEB)

__global__ __launch_bounds__(256)
void tgemm_kernel(const __half* __restrict__ Ah,
                  const __half* __restrict__ Bh,
                  const float* __restrict__ bias,
                  float* __restrict__ C,
                  __half* __restrict__ CH,
                  __half* __restrict__ CL,
                  int N, int K, int lda, int mode)
{
    extern __shared__ __align__(16) char smem[];

    const int tid  = threadIdx.x;
    const int wid  = tid >> 5;
    const int lane = tid & 31;
    const int wm   = wid >> 2;
    const int wn   = wid & 3;
    const int m0   = blockIdx.y * 128;
    const int n0   = blockIdx.x * 128;
    const uint32_t sb = smem_u32(smem);

    const __half* srcs[2] = {Ah, Bh};

    const int lrow0 = tid >> 2;
    const int lq0   = tid & 3;
    const int lrow1 = (tid + 256) >> 2;
    const int lq1   = (tid + 256) & 3;

    float acc[4][4][4];
#pragma unroll
    for (int i = 0; i < 4; i++)
#pragma unroll
        for (int j = 0; j < 4; j++)
#pragma unroll
            for (int v = 0; v < 4; v++) acc[i][j][v] = 0.0f;

    const int r16   = lane & 15;
    const int khalfA = (lane >> 4) * 16;
    const int r8    = lane & 7;
    const int khalfB = ((lane >> 3) & 1) * 16;

    const int nchunks = K >> 5;

    auto issue = [&](int c) {
        const uint32_t stg = sb + (uint32_t)(c % 3) * STAGEB;
        const int k0 = c << 5;
#pragma unroll
        for (int t = 0; t < 2; t++) {
            const bool isB = (t == 1);
            const __half* src = srcs[t];
            const int ld = isB ? K : lda;
            {
                int grow = isB ? (n0 + lrow0) : (m0 + lrow0);
                int ok = (!isB || grow < N) ? 16 : 0;
                if (!ok) grow = n0;
                cp16(stg + t * TILEB + lrow0 * ROWB + lq0 * 16,
                     src + (size_t)grow * ld + k0 + lq0 * 8, ok);
            }
            {
                int grow = isB ? (n0 + lrow1) : (m0 + lrow1);
                int ok = (!isB || grow < N) ? 16 : 0;
                if (!ok) grow = n0;
                cp16(stg + t * TILEB + lrow1 * ROWB + lq1 * 16,
                     src + (size_t)grow * ld + k0 + lq1 * 8, ok);
            }
        }
        cp_commit();
    };

    issue(0);
    if (nchunks > 1) issue(1);

    for (int ci = 0; ci < nchunks; ci++) {
        if (ci + 1 < nchunks) cp_wait<1>(); else cp_wait<0>();
        __syncthreads();
        if (ci + 2 < nchunks) issue(ci + 2);

        const uint32_t cur = sb + (uint32_t)(ci % 3) * STAGEB;
#pragma unroll
        for (int ks = 0; ks < 2; ks++) {
            const int kb = ks * 32;
            uint32_t ah[4][4], bh[4][2];
#pragma unroll
            for (int mi = 0; mi < 4; mi++)
                ldsm_x4(ah[mi][0], ah[mi][1], ah[mi][2], ah[mi][3],
                        cur + 0 * TILEB + (wm * 64 + mi * 16 + r16) * ROWB + kb + khalfA);
#pragma unroll
            for (int ni = 0; ni < 4; ni++)
                ldsm_x2(bh[ni][0], bh[ni][1],
                        cur + 1 * TILEB + (wn * 32 + ni * 8 + r8) * ROWB + kb + khalfB);
#pragma unroll
            for (int mi = 0; mi < 4; mi++)
#pragma unroll
                for (int ni = 0; ni < 4; ni++)
                    mma16816(acc[mi][ni], ah[mi], bh[ni]);
        }
    }

    // ------------------------------ epilogue -------------------------------
#pragma unroll
    for (int mi = 0; mi < 4; mi++) {
        int row0 = m0 + wm * 64 + mi * 16 + (lane >> 2);
#pragma unroll
        for (int ni = 0; ni < 4; ni++) {
            int col = n0 + wn * 32 + ni * 8 + 2 * (lane & 3);
            if (col >= N) continue;
            float2 b2 = *(const float2*)(bias + col);
            float v00 = acc[mi][ni][0] + b2.x, v01 = acc[mi][ni][1] + b2.y;
            float v10 = acc[mi][ni][2] + b2.x, v11 = acc[mi][ni][3] + b2.y;

            if (mode == 0) {
                *(float2*)(C + (size_t)row0 * N + col) = make_float2(v00, v01);
                *(float2*)(C + (size_t)(row0 + 8) * N + col) = make_float2(v10, v11);
            } else if (mode == 1) {
                *(__half2*)(CH + (size_t)row0 * N + col) = __floats2half2_rn(v00, v01);
                *(__half2*)(CH + (size_t)(row0 + 8) * N + col) = __floats2half2_rn(v10, v11);
            } else if (mode == 2) {
#pragma unroll
                for (int rr = 0; rr < 2; rr++) {
                    int tok = row0 + rr * 8;
                    int b = tok >> 9, s = tok & (SEQLEN - 1);
                    float f0 = rr ? v10 : v00, f1 = rr ? v11 : v01;
                    __half2 hv = __floats2half2_rn(f0, f1);
                    if (col < 1024) {
                        int hh = col >> 6, d = col & 63;
                        *(__half2*)(CH + ((size_t)(b * NHEADS + hh) * SEQLEN + s) * 128 + d) = hv;
                    } else {
                        int hh = (col - 1024) >> 6, d = (col - 1024) & 63;
                        *(__half2*)(CL + ((size_t)(b * NHEADS + hh) * SEQLEN + s) * 64 + d) = hv;
                    }
                }
            } else {
#pragma unroll
                for (int rr = 0; rr < 2; rr++) {
                    int tok = row0 + rr * 8;
                    int b = tok >> 9, s = tok & (SEQLEN - 1);
                    float f0 = rr ? v10 : v00, f1 = rr ? v11 : v01;
                    int hh, dd;
                    if (col < 1024) {
                        hh = col >> 6;
                        dd = col & 63;
                    } else {
                        hh = (col - 1024) >> 6;
                        int rp = (col - 1024) & 63;
                        int pair = rp >> 1;
                        float theta = powf(10000.0f, -(float)pair * (1.0f / 32.0f));
                        float sn, cs;
                        sincosf((float)s * theta, &sn, &cs);
                        float t0 = f0 * sn - f1 * cs;
                        float t1 = f1 * sn + f0 * cs;
                        f0 = t0; f1 = t1;
                        dd = 64 + rp;
                    }
                    size_t base = ((size_t)(b * NHEADS + hh) * SEQLEN + s) * 128 + dd;
                    *(__half2*)(CH + base) = __floats2half2_rn(f0, f1);
                }
            }
        }
    }
}

// ------------------------------ attention (chunked online softmax) ---------
#define QPITCH 272
#define VPITCH 144
#define SP2    132
#define OFF_Q  0
#define OFF_KV 17408
#define OFF_S  34816
#define OFF_M  68608
#define OFF_L  (OFF_M + 256)
#define OFF_CR (OFF_M + 512)
#define ATTN2_SMEM (OFF_M + 768)

__global__ __launch_bounds__(256)
void attn2_kernel(const __half* __restrict__ QPH,
                  const __half* __restrict__ KPH,
                  const __half* __restrict__ VPH,
                  __half* __restrict__ ao16)
{
    extern __shared__ char sm2[];
    const uint32_t sb = smem_u32(sm2);
    float* Ssf = (float*)(sm2 + OFF_S);
    float* Sm  = (float*)(sm2 + OFF_M);
    float* Sl  = (float*)(sm2 + OFF_L);
    float* Scr = (float*)(sm2 + OFF_CR);

    const int tid  = threadIdx.x;
    const int wid  = tid >> 5;
    const int lane = tid & 31;
    const int wm = wid >> 2;
    const int wn = wid & 3;
    const int q0 = blockIdx.x * 64;
    const int hh = blockIdx.y;
    const int b  = blockIdx.z;
    const int bh = b * NHEADS + hh;
    const size_t pbase = (size_t)bh * SEQLEN * 128;
    const size_t vbase = (size_t)bh * SEQLEN * 64;
    const float scale = 0.07216878364870322f;   // 1/sqrt(192)

    const int r16 = lane & 15;
    const int khalfA = (lane >> 4) * 16;
    const int r8 = lane & 7;
    const int khalfB = ((lane >> 3) & 1) * 16;

    // load Q (64 x 128)
#pragma unroll
    for (int j = 0; j < 4; j++) {
        int idx = tid + j * 256;
        int row = idx >> 4, c = idx & 15;
        size_t g = pbase + (size_t)(q0 + row) * 128 + c * 8;
        *(uint4*)(sm2 + OFF_Q + row * QPITCH + c * 16) = *(const uint4*)(QPH + g);
    }
    if (tid < 64) { Sm[tid] = -1e30f; Sl[tid] = 0.0f; }

    float accO[2][2][4];
#pragma unroll
    for (int mi = 0; mi < 2; mi++)
#pragma unroll
        for (int ni = 0; ni < 2; ni++)
#pragma unroll
            for (int v = 0; v < 4; v++) accO[mi][ni][v] = 0.0f;

    for (int ck = 0; ck < 4; ck++) {
        // ---- QK for 2 key tiles of 64 ----
#pragma unroll
        for (int v = 0; v < 2; v++) {
            __syncthreads();
            const int ktile = ck * 2 + v;
#pragma unroll
            for (int j = 0; j < 4; j++) {
                int idx = tid + j * 256;
                int row = idx >> 4, c = idx & 15;
                size_t g = pbase + (size_t)(ktile * 64 + row) * 128 + c * 8;
                *(uint4*)(sm2 + OFF_KV + row * QPITCH + c * 16) = *(const uint4*)(KPH + g);
            }
            __syncthreads();

            float acc[2][2][4];
#pragma unroll
            for (int mi = 0; mi < 2; mi++)
#pragma unroll
                for (int ni = 0; ni < 2; ni++)
#pragma unroll
                    for (int vv = 0; vv < 4; vv++) acc[mi][ni][vv] = 0.0f;

#pragma unroll
            for (int ks = 0; ks < 8; ks++) {
                const int kb = ks * 32;
                uint32_t ah[2][4], bhf[2][2];
#pragma unroll
                for (int mi = 0; mi < 2; mi++)
                    ldsm_x4(ah[mi][0], ah[mi][1], ah[mi][2], ah[mi][3],
                            sb + OFF_Q + (wm * 32 + mi * 16 + r16) * QPITCH + kb + khalfA);
#pragma unroll
                for (int ni = 0; ni < 2; ni++)
                    ldsm_x2(bhf[ni][0], bhf[ni][1],
                            sb + OFF_KV + (wn * 16 + ni * 8 + r8) * QPITCH + kb + khalfB);
#pragma unroll
                for (int mi = 0; mi < 2; mi++)
#pragma unroll
                    for (int ni = 0; ni < 2; ni++)
                        mma16816(acc[mi][ni], ah[mi], bhf[ni]);
            }

#pragma unroll
            for (int mi = 0; mi < 2; mi++) {
                int row = wm * 32 + mi * 16 + (lane >> 2);
#pragma unroll
                for (int ni = 0; ni < 2; ni++) {
                    int col = v * 64 + wn * 16 + ni * 8 + 2 * (lane & 3);
                    Ssf[row * SP2 + col]           = acc[mi][ni][0] * scale;
                    Ssf[row * SP2 + col + 1]       = acc[mi][ni][1] * scale;
                    Ssf[(row + 8) * SP2 + col]     = acc[mi][ni][2] * scale;
                    Ssf[(row + 8) * SP2 + col + 1] = acc[mi][ni][3] * scale;
                }
            }
        }
        __syncthreads();

        // ---- online softmax update over this 128-key chunk ----
        {
            int row  = tid >> 2;
            int part = tid & 3;
            float* srow = Ssf + row * SP2;
            float mx = -1e30f;
#pragma unroll 4
            for (int k2 = 0; k2 < 32; k2++)
                mx = fmaxf(mx, srow[part + k2 * 4]);
            mx = fmaxf(mx, __shfl_xor_sync(0xffffffffu, mx, 1));
            mx = fmaxf(mx, __shfl_xor_sync(0xffffffffu, mx, 2));
            float mo = Sm[row];
            float mn = fmaxf(mo, mx);
            float corr = __expf(mo - mn);
            float sum = 0.0f;
#pragma unroll 4
            for (int k2 = 0; k2 < 32; k2++) {
                float e = __expf(srow[part + k2 * 4] - mn);
                srow[part + k2 * 4] = e;
                sum += e;
            }
            sum += __shfl_xor_sync(0xffffffffu, sum, 1);
            sum += __shfl_xor_sync(0xffffffffu, sum, 2);
            if (part == 0) {
                Sm[row] = mn;
                Sl[row] = Sl[row] * corr + sum;
                Scr[row] = corr;
            }
        }
        __syncthreads();

        // ---- rescale O accumulators ----
#pragma unroll
        for (int mi = 0; mi < 2; mi++) {
            int r0 = wm * 32 + mi * 16 + (lane >> 2);
            float c0 = Scr[r0], c1 = Scr[r0 + 8];
#pragma unroll
            for (int ni = 0; ni < 2; ni++) {
                accO[mi][ni][0] *= c0;
                accO[mi][ni][1] *= c0;
                accO[mi][ni][2] *= c1;
                accO[mi][ni][3] *= c1;
            }
        }

        // ---- PV for the 2 key tiles of this chunk ----
#pragma unroll
        for (int v = 0; v < 2; v++) {
            if (v) __syncthreads();
            const int ktile = ck * 2 + v;
#pragma unroll
            for (int j = 0; j < 2; j++) {
                int idx = tid + j * 256;
                int key = idx >> 3, dg = idx & 7;
                size_t g = vbase + (size_t)(ktile * 64 + key) * 64 + dg * 8;
                uint4 vh = *(const uint4*)(VPH + g);
                const uint16_t* ph = (const uint16_t*)&vh;
#pragma unroll
                for (int jj = 0; jj < 8; jj++)
                    *(uint16_t*)(sm2 + OFF_KV + (dg * 8 + jj) * VPITCH + key * 2) = ph[jj];
            }
            __syncthreads();

#pragma unroll
            for (int ks = 0; ks < 4; ks++) {
                uint32_t ph_[2][4];
#pragma unroll
                for (int mi = 0; mi < 2; mi++) {
                    int r  = wm * 32 + mi * 16 + (lane >> 2);
                    int kc = v * 64 + ks * 16 + 2 * (lane & 3);
                    float2 p0 = *(float2*)&Ssf[r * SP2 + kc];
                    float2 p1 = *(float2*)&Ssf[(r + 8) * SP2 + kc];
                    float2 p2 = *(float2*)&Ssf[r * SP2 + kc + 8];
                    float2 p3 = *(float2*)&Ssf[(r + 8) * SP2 + kc + 8];
                    __half2 q0_ = __floats2half2_rn(p0.x, p0.y);
                    __half2 q1_ = __floats2half2_rn(p1.x, p1.y);
                    __half2 q2_ = __floats2half2_rn(p2.x, p2.y);
                    __half2 q3_ = __floats2half2_rn(p3.x, p3.y);
                    ph_[mi][0] = *(uint32_t*)&q0_;
                    ph_[mi][1] = *(uint32_t*)&q1_;
                    ph_[mi][2] = *(uint32_t*)&q2_;
                    ph_[mi][3] = *(uint32_t*)&q3_;
                }
                uint32_t vh_[2][2];
#pragma unroll
                for (int ni = 0; ni < 2; ni++) {
                    uint32_t a = sb + OFF_KV + (wn * 16 + ni * 8 + r8) * VPITCH + ks * 32 + khalfB;
                    ldsm_x2(vh_[ni][0], vh_[ni][1], a);
                }
#pragma unroll
                for (int mi = 0; mi < 2; mi++)
#pragma unroll
                    for (int ni = 0; ni < 2; ni++)
                        mma16816(accO[mi][ni], ph_[mi], vh_[ni]);
            }
        }
    }

    // ---- epilogue: normalize by l, store fp16 ----
#pragma unroll
    for (int mi = 0; mi < 2; mi++) {
        int rloc = wm * 32 + mi * 16 + (lane >> 2);
        int tok  = b * SEQLEN + q0 + rloc;
        float inv0 = 1.0f / Sl[rloc];
        float inv1 = 1.0f / Sl[rloc + 8];
#pragma unroll
        for (int ni = 0; ni < 2; ni++) {
            int col = wn * 16 + ni * 8 + 2 * (lane & 3);
            *(__half2*)(ao16 + (size_t)tok * UPDIM + hh * 64 + col) =
                __floats2half2_rn(accO[mi][ni][0] * inv0, accO[mi][ni][1] * inv0);
            *(__half2*)(ao16 + (size_t)(tok + 8) * UPDIM + hh * 64 + col) =
                __floats2half2_rn(accO[mi][ni][2] * inv1, accO[mi][ni][3] * inv1);
        }
    }
}

// ---------------------------------------------------------------------------
extern "C" void kernel_launch(void* const* d_in, const int* in_sizes, int n_in,
                              void* d_out, int out_size)
{
    const float* h    = (const float*)d_in[0];
    const float* Wdkv = (const float*)d_in[1];
    const float* bdkv = (const float*)d_in[2];
    const float* Wuk  = (const float*)d_in[3];
    const float* buk  = (const float*)d_in[4];
    const float* Wuv  = (const float*)d_in[5];
    const float* buv  = (const float*)d_in[6];
    const float* Wdq  = (const float*)d_in[7];
    const float* bdq  = (const float*)d_in[8];
    const float* Wuq  = (const float*)d_in[9];
    const float* buq  = (const float*)d_in[10];
    const float* Wqr  = (const float*)d_in[11];
    const float* bqr  = (const float*)d_in[12];
    const float* Wkr  = (const float*)d_in[13];
    const float* bkr  = (const float*)d_in[14];
    const float* Wfc  = (const float*)d_in[15];
    const float* bfc  = (const float*)d_in[16];
    float* out = (float*)d_out;

    __half *h16, *c16, *ao16;
    float *bdown, *bkv, *bqq;
    __half *Wdown16, *Wkv16, *Wqq16, *Wfc16;
    __half *QPH, *KPH, *VPH;
    cudaGetSymbolAddress((void**)&h16,     g_h16);
    cudaGetSymbolAddress((void**)&c16,     g_c16);
    cudaGetSymbolAddress((void**)&ao16,    g_ao16);
    cudaGetSymbolAddress((void**)&Wdown16, g_Wdown16);
    cudaGetSymbolAddress((void**)&Wkv16,   g_Wkv16);
    cudaGetSymbolAddress((void**)&Wqq16,   g_Wqq16);
    cudaGetSymbolAddress((void**)&Wfc16,   g_Wfc16);
    cudaGetSymbolAddress((void**)&bdown,   g_bdown);
    cudaGetSymbolAddress((void**)&bkv,     g_bkv);
    cudaGetSymbolAddress((void**)&bqq,     g_bqq);
    cudaGetSymbolAddress((void**)&QPH,     g_QPH);
    cudaGetSymbolAddress((void**)&KPH,     g_KPH);
    cudaGetSymbolAddress((void**)&VPH,     g_VPH);

    cudaFuncSetAttribute(attn2_kernel,
                         cudaFuncAttributeMaxDynamicSharedMemorySize, ATTN2_SMEM);
    cudaFuncSetAttribute(tgemm_kernel,
                         cudaFuncAttributeMaxDynamicSharedMemorySize, GT_SMEM);

    // prep
    conv_kernel<<<TOK * DMODEL / 2 / 256, 256>>>(h, h16, TOK * DMODEL / 2);
    wconv_all_kernel<<<(WB7 + 255) / 256, 256>>>(Wdkv, Wdq, Wkr, Wuk, Wuv, Wuq,
                                                 Wqr, Wfc, Wdown16, Wkv16,
                                                 Wqq16, Wfc16);
    bias_concat_kernel<<<21, 256>>>(bdkv, bdq, bkr, buk, buv, buq, bqr,
                                    bdown, bkv, bqq);

    dim3 blk(256);
    // fused down projection: N=1088 (ckv|cq|kr), fp16 out
    tgemm_kernel<<<dim3(9, TOK / 128), blk, GT_SMEM>>>(
        h16, Wdown16, bdown, nullptr, c16, nullptr, NDOWN, DMODEL, DMODEL, 1);

    // k_r rope broadcast
    krope_kernel<<<TOK * 32 / 256, 256>>>(c16, KPH);

    // fused up projections writing packed attention operands directly
    tgemm_kernel<<<dim3(16, TOK / 128), blk, GT_SMEM>>>(
        c16, Wkv16, bkv, nullptr, KPH, VPH, 2048, DOWND, NDOWN, 2);
    tgemm_kernel<<<dim3(16, TOK / 128), blk, GT_SMEM>>>(
        c16 + 512, Wqq16, bqq, nullptr, QPH, nullptr, 2048, DOWND, NDOWN, 3);

    // attention
    attn2_kernel<<<dim3(SEQLEN / 64, NHEADS, BATCH), blk, ATTN2_SMEM>>>(
        QPH, KPH, VPH, ao16);

    // output projection (fp32 out)
    tgemm_kernel<<<dim3(16, TOK / 128), blk, GT_SMEM>>>(
        ao16, Wfc16, bfc, out, nullptr, nullptr, DMODEL, UPDIM, UPDIM, 0);
}